// round 2
// baseline (speedup 1.0000x reference)
#include <cuda_runtime.h>
#include <math.h>

// Problem constants
#define BB 4
#define TT 2048
#define CC 1024
#define HH 8
#define DD 128
#define NTOK (BB*TT)          // 8192

// ---------------------------------------------------------------------------
// Scratch (single static device buffer; no allocations anywhere)
// ---------------------------------------------------------------------------
#define XN_OFF  0
#define Q_OFF   (XN_OFF + (size_t)NTOK*CC)
#define K_OFF   (Q_OFF  + (size_t)NTOK*CC)
#define V_OFF   (K_OFF  + (size_t)NTOK*CC)
#define AO_OFF  (V_OFF  + (size_t)NTOK*CC)
#define QP_OFF  (AO_OFF + (size_t)NTOK*CC)
#define KP_OFF  (QP_OFF + (size_t)BB*HH*TT)
#define SCRATCH_TOTAL (KP_OFF + (size_t)BB*HH*TT)

__device__ float g_scratch[SCRATCH_TOTAL];

// ---------------------------------------------------------------------------
// LayerNorm: one block (256 thr) per token, float4 everywhere
// ---------------------------------------------------------------------------
__global__ __launch_bounds__(256) void ln_kernel(
    const float* __restrict__ x, const float* __restrict__ gam,
    const float* __restrict__ bet, float* __restrict__ xn)
{
    int row = blockIdx.x;
    int t   = threadIdx.x;
    const float4* xr = (const float4*)(x + (size_t)row * CC);
    float4 v = xr[t];
    float s  = v.x + v.y + v.z + v.w;
    float ss = v.x*v.x + v.y*v.y + v.z*v.z + v.w*v.w;
    #pragma unroll
    for (int o = 16; o; o >>= 1) {
        s  += __shfl_xor_sync(0xffffffffu, s,  o);
        ss += __shfl_xor_sync(0xffffffffu, ss, o);
    }
    __shared__ float ws[8], wss[8];
    int wid = t >> 5;
    if ((t & 31) == 0) { ws[wid] = s; wss[wid] = ss; }
    __syncthreads();
    s = 0.f; ss = 0.f;
    #pragma unroll
    for (int i = 0; i < 8; i++) { s += ws[i]; ss += wss[i]; }
    float mu  = s * (1.f / CC);
    float var = ss * (1.f / CC) - mu * mu;
    float inv = rsqrtf(var + 1e-5f);
    float4 g4 = ((const float4*)gam)[t];
    float4 b4 = ((const float4*)bet)[t];
    float4 o;
    o.x = (v.x - mu) * inv * g4.x + b4.x;
    o.y = (v.y - mu) * inv * g4.y + b4.y;
    o.z = (v.z - mu) * inv * g4.z + b4.z;
    o.w = (v.w - mu) * inv * g4.w + b4.w;
    ((float4*)(xn + (size_t)row * CC))[t] = o;
}

// ---------------------------------------------------------------------------
// TN GEMM:  Cm,n = sum_k A[m,k] * W[n,k]    (A,W row-major, K contiguous)
// 64x64 tile, BK=16, 256 threads, 4x4 micro-tile, float4 smem.
// MODE 0: scatter to head-major [B,H,T,D] (for q/k/v)
// MODE 1: out[m,n] = X[m,n] + acc          (final projection + residual)
// ---------------------------------------------------------------------------
template<int MODE>
__global__ __launch_bounds__(256) void gemm_tn(
    const float* __restrict__ A, const float* __restrict__ W,
    const float* __restrict__ X, float* __restrict__ out)
{
    __shared__ float As[64][20];
    __shared__ float Ws[64][20];
    int m0 = blockIdx.y << 6, n0 = blockIdx.x << 6;
    int tid = threadIdx.x, ty = tid >> 4, tx = tid & 15;
    int lr = tid >> 2, lc = (tid & 3) << 2;
    float acc[4][4] = {};
    const float* Ap = A + (size_t)(m0 + lr) * CC + lc;
    const float* Wp = W + (size_t)(n0 + lr) * CC + lc;
    for (int k0 = 0; k0 < CC; k0 += 16) {
        *(float4*)&As[lr][lc] = *(const float4*)(Ap + k0);
        *(float4*)&Ws[lr][lc] = *(const float4*)(Wp + k0);
        __syncthreads();
        #pragma unroll
        for (int kk = 0; kk < 16; kk += 4) {
            float4 aa[4], ww[4];
            #pragma unroll
            for (int r = 0; r < 4; r++) aa[r] = *(float4*)&As[ty*4 + r][kk];
            #pragma unroll
            for (int c = 0; c < 4; c++) ww[c] = *(float4*)&Ws[tx + 16*c][kk];
            #pragma unroll
            for (int r = 0; r < 4; r++)
                #pragma unroll
                for (int c = 0; c < 4; c++)
                    acc[r][c] += aa[r].x*ww[c].x + aa[r].y*ww[c].y
                               + aa[r].z*ww[c].z + aa[r].w*ww[c].w;
        }
        __syncthreads();
    }
    #pragma unroll
    for (int r = 0; r < 4; r++) {
        int m = m0 + ty*4 + r;
        #pragma unroll
        for (int c = 0; c < 4; c++) {
            int n = n0 + tx + 16*c;
            if (MODE == 0) {
                int b = m >> 11, t = m & 2047, h = n >> 7, d = n & 127;
                out[(((size_t)(b*HH + h) * TT) + t) * DD + d] = acc[r][c];
            } else {
                out[(size_t)m * CC + n] = X[(size_t)m * CC + n] + acc[r][c];
            }
        }
    }
}

// ---------------------------------------------------------------------------
// RoPE on q,k (head-major layout) + geo projections qp,kp
// one block = one (b,h,t); threads 0..63 -> q pairs, 64..127 -> k pairs
// ---------------------------------------------------------------------------
__global__ __launch_bounds__(128) void rope_kernel(
    float* __restrict__ q, float* __restrict__ k,
    const float* __restrict__ dirs,
    float* __restrict__ qp, float* __restrict__ kp)
{
    int idx = blockIdx.x;                  // (b*H+h)*T + t
    int t = idx & (TT - 1);
    int h = (idx >> 11) & (HH - 1);
    int tid = threadIdx.x;
    int i = tid & 63;
    float* p = (tid < 64 ? q : k) + (size_t)idx * DD;
    float x1 = p[i], x2 = p[i + 64];
    // inv = 10000^(-i/64)
    float inv = expf(-9.210340371976184f * (float)i * (1.f / 64.f));
    float ang = (float)t * inv;
    float sn, cs;
    sincosf(ang, &sn, &cs);
    float y1 = x1 * cs - x2 * sn;
    float y2 = x2 * cs + x1 * sn;
    p[i] = y1;
    p[i + 64] = y2;
    __shared__ float red[6];
    if (i < 3) red[(tid >> 6) * 3 + i] = y1 * dirs[h * 3 + i];
    __syncthreads();
    if (tid == 0)  qp[idx] = red[0] + red[1] + red[2];
    if (tid == 64) kp[idx] = red[3] + red[4] + red[5];
}

// ---------------------------------------------------------------------------
// Dual flash attention (regular softmax + rank-1 geo softmax, shared V)
// block = 64 queries x D=128, 256 threads. Streams 64-key tiles.
// ---------------------------------------------------------------------------
#define QP_PAD 132      // padded row (floats) for Q/K/V tiles
#define PP_PAD 68       // padded row for P tiles
#define ATTN_SMEM ((3*64*QP_PAD + 2*64*PP_PAD + 128) * 4)

__global__ __launch_bounds__(256) void attn_kernel(
    const float* __restrict__ q, const float* __restrict__ k,
    const float* __restrict__ v, const float* __restrict__ qp,
    const float* __restrict__ kp, const float* __restrict__ head_scales,
    float* __restrict__ out)
{
    extern __shared__ float sm[];
    float* Qs  = sm;                        // [64][132]
    float* Ks  = Qs + 64*QP_PAD;            // [64][132]
    float* Vs  = Ks + 64*QP_PAD;            // [64][132]
    float* Ps  = Vs + 64*QP_PAD;            // [64][68]
    float* Pg  = Ps + 64*PP_PAD;            // [64][68]
    float* qps = Pg + 64*PP_PAD;            // [64]
    float* kps = qps + 64;                  // [64]

    int bh = blockIdx.y;
    int b = bh >> 3, h = bh & 7;
    int q0 = blockIdx.x << 6;
    size_t base = (size_t)bh * TT * DD;
    int tid = threadIdx.x, ty = tid >> 4, tx = tid & 15;

    for (int idx = tid; idx < 64*32; idx += 256) {
        int r = idx >> 5, d4 = (idx & 31) << 2;
        *(float4*)&Qs[r*QP_PAD + d4] =
            *(const float4*)&q[base + (size_t)(q0 + r)*DD + d4];
    }
    if (tid < 64) qps[tid] = qp[(size_t)bh*TT + q0 + tid];

    float m[4], l[4], mg[4], lg[4];
    float O[4][8] = {}, Og[4][8] = {};
    #pragma unroll
    for (int r = 0; r < 4; r++) { m[r] = -INFINITY; l[r] = 0.f; mg[r] = -INFINITY; lg[r] = 0.f; }
    float hs = head_scales[h];
    const float scale = 0.08838834764831845f;   // 1/sqrt(128)

    #pragma unroll 1
    for (int n0 = 0; n0 <= q0; n0 += 64) {
        __syncthreads();        // protects Vs/Ps of previous iteration & Q on first
        for (int idx = tid; idx < 64*32; idx += 256) {
            int r = idx >> 5, d4 = (idx & 31) << 2;
            *(float4*)&Ks[r*QP_PAD + d4] =
                *(const float4*)&k[base + (size_t)(n0 + r)*DD + d4];
            *(float4*)&Vs[r*QP_PAD + d4] =
                *(const float4*)&v[base + (size_t)(n0 + r)*DD + d4];
        }
        if (tid < 64) kps[tid] = kp[(size_t)bh*TT + n0 + tid];
        __syncthreads();

        // ---- S = Q @ K^T  (64x64), 4x4 per thread
        float s[4][4] = {};
        #pragma unroll 8
        for (int kk = 0; kk < DD; kk += 4) {
            float4 aa[4], bk[4];
            #pragma unroll
            for (int r = 0; r < 4; r++) aa[r] = *(float4*)&Qs[(ty*4 + r)*QP_PAD + kk];
            #pragma unroll
            for (int c = 0; c < 4; c++) bk[c] = *(float4*)&Ks[(tx + 16*c)*QP_PAD + kk];
            #pragma unroll
            for (int r = 0; r < 4; r++)
                #pragma unroll
                for (int c = 0; c < 4; c++)
                    s[r][c] += aa[r].x*bk[c].x + aa[r].y*bk[c].y
                             + aa[r].z*bk[c].z + aa[r].w*bk[c].w;
        }

        bool diag = (n0 == q0);
        // ---- online softmax (attn + geo) per row
        #pragma unroll
        for (int r = 0; r < 4; r++) {
            int row = ty*4 + r;
            // attn
            float sv[4], mloc = -INFINITY;
            #pragma unroll
            for (int c = 0; c < 4; c++) {
                int col = tx + 16*c;
                float x_ = s[r][c] * scale;
                if (diag && col > row) x_ = -INFINITY;
                sv[c] = x_;
                mloc = fmaxf(mloc, x_);
            }
            #pragma unroll
            for (int o = 8; o; o >>= 1)
                mloc = fmaxf(mloc, __shfl_xor_sync(0xffffffffu, mloc, o, 16));
            float mn = fmaxf(m[r], mloc);
            float alpha = expf(m[r] - mn);
            float rsum = 0.f;
            #pragma unroll
            for (int c = 0; c < 4; c++) {
                float p_ = expf(sv[c] - mn);
                Ps[row*PP_PAD + tx + 16*c] = p_;
                rsum += p_;
            }
            #pragma unroll
            for (int o = 8; o; o >>= 1)
                rsum += __shfl_xor_sync(0xffffffffu, rsum, o, 16);
            l[r] = l[r]*alpha + rsum;
            m[r] = mn;
            #pragma unroll
            for (int c = 0; c < 8; c++) O[r][c] *= alpha;

            // geo (rank-1 scores)
            float qpr = qps[row];
            float gv[4], gloc = -INFINITY;
            #pragma unroll
            for (int c = 0; c < 4; c++) {
                int col = tx + 16*c;
                float g_ = qpr * kps[col];
                if (diag && col > row) g_ = -INFINITY;
                gv[c] = g_;
                gloc = fmaxf(gloc, g_);
            }
            #pragma unroll
            for (int o = 8; o; o >>= 1)
                gloc = fmaxf(gloc, __shfl_xor_sync(0xffffffffu, gloc, o, 16));
            float gmn = fmaxf(mg[r], gloc);
            float galpha = expf(mg[r] - gmn);
            float gsum = 0.f;
            #pragma unroll
            for (int c = 0; c < 4; c++) {
                float p_ = expf(gv[c] - gmn);
                Pg[row*PP_PAD + tx + 16*c] = p_;
                gsum += p_;
            }
            #pragma unroll
            for (int o = 8; o; o >>= 1)
                gsum += __shfl_xor_sync(0xffffffffu, gsum, o, 16);
            lg[r] = lg[r]*galpha + gsum;
            mg[r] = gmn;
            #pragma unroll
            for (int c = 0; c < 8; c++) Og[r][c] *= galpha;
        }
        __syncthreads();

        // ---- O += P @ V ; Og += Pg @ V
        #pragma unroll 4
        for (int n = 0; n < 64; n++) {
            float vv[8];
            #pragma unroll
            for (int c = 0; c < 8; c++) vv[c] = Vs[n*QP_PAD + tx + 16*c];
            #pragma unroll
            for (int r = 0; r < 4; r++) {
                float pr  = Ps[(ty*4 + r)*PP_PAD + n];
                float pgr = Pg[(ty*4 + r)*PP_PAD + n];
                #pragma unroll
                for (int c = 0; c < 8; c++) {
                    O[r][c]  += pr  * vv[c];
                    Og[r][c] += pgr * vv[c];
                }
            }
        }
    }

    // ---- epilogue: normalize, blend, write (b,t,c) layout
    #pragma unroll
    for (int r = 0; r < 4; r++) {
        int row = q0 + ty*4 + r;
        float invl  = 1.f / l[r];
        float invlg = 1.f / lg[r];
        #pragma unroll
        for (int c = 0; c < 8; c++) {
            float o  = O[r][c]  * invl;
            float og = Og[r][c] * invlg;
            float val = o + hs * (og - o);
            out[(size_t)(b*TT + row)*CC + h*DD + tx + 16*c] = val;
        }
    }
}

// ---------------------------------------------------------------------------
// Launcher
// ---------------------------------------------------------------------------
extern "C" void kernel_launch(void* const* d_in, const int* in_sizes, int n_in,
                              void* d_out, int out_size)
{
    const float* x   = (const float*)d_in[0];
    const float* Wq  = (const float*)d_in[1];
    const float* Wk  = (const float*)d_in[2];
    const float* Wv  = (const float*)d_in[3];
    const float* Wo  = (const float*)d_in[4];
    const float* lng = (const float*)d_in[5];
    const float* lnb = (const float*)d_in[6];
    const float* hsc = (const float*)d_in[7];
    const float* hdr = (const float*)d_in[8];
    float* out = (float*)d_out;

    float* base = nullptr;
    cudaGetSymbolAddress((void**)&base, g_scratch);
    float* xn = base + XN_OFF;
    float* gq = base + Q_OFF;
    float* gk = base + K_OFF;
    float* gv = base + V_OFF;
    float* ao = base + AO_OFF;
    float* gqp = base + QP_OFF;
    float* gkp = base + KP_OFF;

    ln_kernel<<<NTOK, 256>>>(x, lng, lnb, xn);

    dim3 gg(CC / 64, NTOK / 64);
    gemm_tn<0><<<gg, 256>>>(xn, Wq, nullptr, gq);
    gemm_tn<0><<<gg, 256>>>(xn, Wk, nullptr, gk);
    gemm_tn<0><<<gg, 256>>>(xn, Wv, nullptr, gv);

    rope_kernel<<<BB*HH*TT, 128>>>(gq, gk, hdr, gqp, gkp);

    cudaFuncSetAttribute(attn_kernel,
                         cudaFuncAttributeMaxDynamicSharedMemorySize, ATTN_SMEM);
    attn_kernel<<<dim3(TT/64, BB*HH), 256, ATTN_SMEM>>>(gq, gk, gv, gqp, gkp, hsc, ao);

    gemm_tn<1><<<gg, 256>>>(ao, Wo, x, out);
}

// round 3
// speedup vs baseline: 1.2398x; 1.2398x over previous
#include <cuda_runtime.h>
#include <math.h>

// Problem constants
#define BB 4
#define TT 2048
#define CC 1024
#define HH 8
#define DD 128
#define NTOK (BB*TT)          // 8192

// ---------------------------------------------------------------------------
// Scratch (single static device buffer; no allocations anywhere)
// ---------------------------------------------------------------------------
#define XN_OFF  0
#define Q_OFF   (XN_OFF + (size_t)NTOK*CC)
#define K_OFF   (Q_OFF  + (size_t)NTOK*CC)
#define V_OFF   (K_OFF  + (size_t)NTOK*CC)
#define AO_OFF  (V_OFF  + (size_t)NTOK*CC)
#define QP_OFF  (AO_OFF + (size_t)NTOK*CC)
#define KP_OFF  (QP_OFF + (size_t)BB*HH*TT)
#define SCRATCH_TOTAL (KP_OFF + (size_t)BB*HH*TT)

__device__ float g_scratch[SCRATCH_TOTAL];

// ---------------------------------------------------------------------------
// LayerNorm: one block (256 thr) per token, float4 everywhere
// ---------------------------------------------------------------------------
__global__ __launch_bounds__(256) void ln_kernel(
    const float* __restrict__ x, const float* __restrict__ gam,
    const float* __restrict__ bet, float* __restrict__ xn)
{
    int row = blockIdx.x;
    int t   = threadIdx.x;
    const float4* xr = (const float4*)(x + (size_t)row * CC);
    float4 v = xr[t];
    float s  = v.x + v.y + v.z + v.w;
    float ss = v.x*v.x + v.y*v.y + v.z*v.z + v.w*v.w;
    #pragma unroll
    for (int o = 16; o; o >>= 1) {
        s  += __shfl_xor_sync(0xffffffffu, s,  o);
        ss += __shfl_xor_sync(0xffffffffu, ss, o);
    }
    __shared__ float ws[8], wss[8];
    int wid = t >> 5;
    if ((t & 31) == 0) { ws[wid] = s; wss[wid] = ss; }
    __syncthreads();
    s = 0.f; ss = 0.f;
    #pragma unroll
    for (int i = 0; i < 8; i++) { s += ws[i]; ss += wss[i]; }
    float mu  = s * (1.f / CC);
    float var = ss * (1.f / CC) - mu * mu;
    float inv = rsqrtf(var + 1e-5f);
    float4 g4 = ((const float4*)gam)[t];
    float4 b4 = ((const float4*)bet)[t];
    float4 o;
    o.x = (v.x - mu) * inv * g4.x + b4.x;
    o.y = (v.y - mu) * inv * g4.y + b4.y;
    o.z = (v.z - mu) * inv * g4.z + b4.z;
    o.w = (v.w - mu) * inv * g4.w + b4.w;
    ((float4*)(xn + (size_t)row * CC))[t] = o;
}

// ---------------------------------------------------------------------------
// tf32 helpers
// ---------------------------------------------------------------------------
__device__ __forceinline__ float tf32_rna(float f) {
    unsigned u;
    asm("cvt.rna.tf32.f32 %0, %1;" : "=r"(u) : "f"(f));
    return __uint_as_float(u);
}

__device__ __forceinline__ void mma_tf32(float* c, const unsigned* a,
                                         unsigned b0, unsigned b1) {
    asm volatile(
        "mma.sync.aligned.m16n8k8.row.col.f32.tf32.tf32.f32 "
        "{%0,%1,%2,%3},{%4,%5,%6,%7},{%8,%9},{%0,%1,%2,%3};"
        : "+f"(c[0]), "+f"(c[1]), "+f"(c[2]), "+f"(c[3])
        : "r"(a[0]), "r"(a[1]), "r"(a[2]), "r"(a[3]), "r"(b0), "r"(b1));
}

// ---------------------------------------------------------------------------
// 3xTF32 tensor-core GEMM:  C[m,n] = sum_k A[m,k] * W[n,k]
// 128x128x32 tile, 256 threads (8 warps, warp grid 4x2 -> warp tile 32x64).
// hi/lo tf32 split done once at tile load; inner loop is pure LDS + HMMA.
// MODE 0: scatter to head-major [B,H,T,D];  MODE 1: out = X + acc.
// ---------------------------------------------------------------------------
#define TPAD 36
#define GEMM_NIT (CC/32)
#define GEMM_SMEM (8 * 128 * TPAD * 4)   // Ah,Al,Bh,Bl x 2 buffers

template<int MODE>
__global__ __launch_bounds__(256, 1) void gemm_mma(
    const float* __restrict__ A, const float* __restrict__ W,
    const float* __restrict__ X, float* __restrict__ out)
{
    extern __shared__ float smg[];
    float* Ah = smg;                    // [2][128][TPAD]
    float* Al = Ah + 2*128*TPAD;
    float* Bh = Al + 2*128*TPAD;
    float* Bl = Bh + 2*128*TPAD;

    int tid  = threadIdx.x;
    int lane = tid & 31, warp = tid >> 5;
    int g = lane >> 2, tig = lane & 3;
    int wm = warp >> 1, wn = warp & 1;
    int m0 = blockIdx.y << 7, n0 = blockIdx.x << 7;

    int lrow = tid >> 1;                // 0..127
    int lcol = (tid & 1) << 4;          // 0 or 16

    const float* Ag = A + (size_t)(m0 + lrow) * CC + lcol;
    const float* Wg = W + (size_t)(n0 + lrow) * CC + lcol;

    float acc[16][4];
    #pragma unroll
    for (int i = 0; i < 16; i++)
        #pragma unroll
        for (int j = 0; j < 4; j++) acc[i][j] = 0.f;

    float4 va[4], vb[4];
    #pragma unroll
    for (int i = 0; i < 4; i++) {
        va[i] = *(const float4*)(Ag + i*4);
        vb[i] = *(const float4*)(Wg + i*4);
    }

    // split+store a prefetched tile into buffer `buf`
    auto store_tile = [&](int buf) {
        int base = buf*128*TPAD + lrow*TPAD + lcol;
        #pragma unroll
        for (int i = 0; i < 4; i++) {
            float4 v = va[i];
            float4 hv, lv;
            hv.x = tf32_rna(v.x); lv.x = tf32_rna(v.x - hv.x);
            hv.y = tf32_rna(v.y); lv.y = tf32_rna(v.y - hv.y);
            hv.z = tf32_rna(v.z); lv.z = tf32_rna(v.z - hv.z);
            hv.w = tf32_rna(v.w); lv.w = tf32_rna(v.w - hv.w);
            *(float4*)&Ah[base + i*4] = hv;
            *(float4*)&Al[base + i*4] = lv;
            v = vb[i];
            hv.x = tf32_rna(v.x); lv.x = tf32_rna(v.x - hv.x);
            hv.y = tf32_rna(v.y); lv.y = tf32_rna(v.y - hv.y);
            hv.z = tf32_rna(v.z); lv.z = tf32_rna(v.z - hv.z);
            hv.w = tf32_rna(v.w); lv.w = tf32_rna(v.w - hv.w);
            *(float4*)&Bh[base + i*4] = hv;
            *(float4*)&Bl[base + i*4] = lv;
        }
    };

    store_tile(0);
    __syncthreads();

    for (int it = 0; it < GEMM_NIT; it++) {
        int buf = it & 1;
        if (it + 1 < GEMM_NIT) {
            const float* Ap = Ag + (it+1)*32;
            const float* Wp = Wg + (it+1)*32;
            #pragma unroll
            for (int i = 0; i < 4; i++) {
                va[i] = *(const float4*)(Ap + i*4);
                vb[i] = *(const float4*)(Wp + i*4);
            }
        }

        #pragma unroll
        for (int kk = 0; kk < 32; kk += 8) {
            unsigned ah[2][4], al[2][4];
            #pragma unroll
            for (int mi = 0; mi < 2; mi++) {
                int row = wm*32 + mi*16 + g;
                int base = buf*128*TPAD + row*TPAD + kk;
                ah[mi][0] = __float_as_uint(Ah[base + tig]);
                ah[mi][1] = __float_as_uint(Ah[base + 8*TPAD + tig]);
                ah[mi][2] = __float_as_uint(Ah[base + tig + 4]);
                ah[mi][3] = __float_as_uint(Ah[base + 8*TPAD + tig + 4]);
                al[mi][0] = __float_as_uint(Al[base + tig]);
                al[mi][1] = __float_as_uint(Al[base + 8*TPAD + tig]);
                al[mi][2] = __float_as_uint(Al[base + tig + 4]);
                al[mi][3] = __float_as_uint(Al[base + 8*TPAD + tig + 4]);
            }
            #pragma unroll
            for (int ni = 0; ni < 8; ni++) {
                int col = wn*64 + ni*8 + g;
                int bbase = buf*128*TPAD + col*TPAD + kk;
                unsigned bh0 = __float_as_uint(Bh[bbase + tig]);
                unsigned bh1 = __float_as_uint(Bh[bbase + tig + 4]);
                unsigned bl0 = __float_as_uint(Bl[bbase + tig]);
                unsigned bl1 = __float_as_uint(Bl[bbase + tig + 4]);
                #pragma unroll
                for (int mi = 0; mi < 2; mi++) {
                    float* c = acc[mi*8 + ni];
                    mma_tf32(c, ah[mi], bh0, bh1);
                    mma_tf32(c, ah[mi], bl0, bl1);
                    mma_tf32(c, al[mi], bh0, bh1);
                }
            }
        }

        if (it + 1 < GEMM_NIT) store_tile(buf ^ 1);
        __syncthreads();
    }

    // epilogue
    #pragma unroll
    for (int mi = 0; mi < 2; mi++) {
        #pragma unroll
        for (int ni = 0; ni < 8; ni++) {
            const float* c = acc[mi*8 + ni];
            int r0 = m0 + wm*32 + mi*16 + g;
            int c0 = n0 + wn*64 + ni*8 + 2*tig;
            #pragma unroll
            for (int half = 0; half < 2; half++) {
                int r = r0 + half*8;
                float v0 = c[half*2], v1 = c[half*2 + 1];
                if (MODE == 0) {
                    int b = r >> 11, t = r & 2047, h = c0 >> 7, d = c0 & 127;
                    float2 p = make_float2(v0, v1);
                    *(float2*)&out[(((size_t)(b*HH + h) * TT) + t) * DD + d] = p;
                } else {
                    size_t o = (size_t)r * CC + c0;
                    float2 xv = *(const float2*)&X[o];
                    float2 p = make_float2(xv.x + v0, xv.y + v1);
                    *(float2*)&out[o] = p;
                }
            }
        }
    }
}

// ---------------------------------------------------------------------------
// RoPE on q,k (head-major layout) + geo projections qp,kp
// ---------------------------------------------------------------------------
__global__ __launch_bounds__(128) void rope_kernel(
    float* __restrict__ q, float* __restrict__ k,
    const float* __restrict__ dirs,
    float* __restrict__ qp, float* __restrict__ kp)
{
    int idx = blockIdx.x;                  // (b*H+h)*T + t
    int t = idx & (TT - 1);
    int h = (idx >> 11) & (HH - 1);
    int tid = threadIdx.x;
    int i = tid & 63;
    float* p = (tid < 64 ? q : k) + (size_t)idx * DD;
    float x1 = p[i], x2 = p[i + 64];
    float inv = expf(-9.210340371976184f * (float)i * (1.f / 64.f));
    float ang = (float)t * inv;
    float sn, cs;
    sincosf(ang, &sn, &cs);
    float y1 = x1 * cs - x2 * sn;
    float y2 = x2 * cs + x1 * sn;
    p[i] = y1;
    p[i + 64] = y2;
    __shared__ float red[6];
    if (i < 3) red[(tid >> 6) * 3 + i] = y1 * dirs[h * 3 + i];
    __syncthreads();
    if (tid == 0)  qp[idx] = red[0] + red[1] + red[2];
    if (tid == 64) kp[idx] = red[3] + red[4] + red[5];
}

// ---------------------------------------------------------------------------
// Dual flash attention (regular softmax + rank-1 geo softmax, shared V)
// ---------------------------------------------------------------------------
#define QP_PAD 132
#define PP_PAD 68
#define ATTN_SMEM ((3*64*QP_PAD + 2*64*PP_PAD + 128) * 4)

__global__ __launch_bounds__(256) void attn_kernel(
    const float* __restrict__ q, const float* __restrict__ k,
    const float* __restrict__ v, const float* __restrict__ qp,
    const float* __restrict__ kp, const float* __restrict__ head_scales,
    float* __restrict__ out)
{
    extern __shared__ float sm[];
    float* Qs  = sm;
    float* Ks  = Qs + 64*QP_PAD;
    float* Vs  = Ks + 64*QP_PAD;
    float* Ps  = Vs + 64*QP_PAD;
    float* Pg  = Ps + 64*PP_PAD;
    float* qps = Pg + 64*PP_PAD;
    float* kps = qps + 64;

    int bh = blockIdx.y;
    int b = bh >> 3, h = bh & 7;
    int q0 = blockIdx.x << 6;
    size_t base = (size_t)bh * TT * DD;
    int tid = threadIdx.x, ty = tid >> 4, tx = tid & 15;

    for (int idx = tid; idx < 64*32; idx += 256) {
        int r = idx >> 5, d4 = (idx & 31) << 2;
        *(float4*)&Qs[r*QP_PAD + d4] =
            *(const float4*)&q[base + (size_t)(q0 + r)*DD + d4];
    }
    if (tid < 64) qps[tid] = qp[(size_t)bh*TT + q0 + tid];

    float m[4], l[4], mg[4], lg[4];
    float O[4][8] = {}, Og[4][8] = {};
    #pragma unroll
    for (int r = 0; r < 4; r++) { m[r] = -INFINITY; l[r] = 0.f; mg[r] = -INFINITY; lg[r] = 0.f; }
    float hs = head_scales[h];
    const float scale = 0.08838834764831845f;

    #pragma unroll 1
    for (int n0 = 0; n0 <= q0; n0 += 64) {
        __syncthreads();
        for (int idx = tid; idx < 64*32; idx += 256) {
            int r = idx >> 5, d4 = (idx & 31) << 2;
            *(float4*)&Ks[r*QP_PAD + d4] =
                *(const float4*)&k[base + (size_t)(n0 + r)*DD + d4];
            *(float4*)&Vs[r*QP_PAD + d4] =
                *(const float4*)&v[base + (size_t)(n0 + r)*DD + d4];
        }
        if (tid < 64) kps[tid] = kp[(size_t)bh*TT + n0 + tid];
        __syncthreads();

        float s[4][4] = {};
        #pragma unroll 8
        for (int kk = 0; kk < DD; kk += 4) {
            float4 aa[4], bk[4];
            #pragma unroll
            for (int r = 0; r < 4; r++) aa[r] = *(float4*)&Qs[(ty*4 + r)*QP_PAD + kk];
            #pragma unroll
            for (int c = 0; c < 4; c++) bk[c] = *(float4*)&Ks[(tx + 16*c)*QP_PAD + kk];
            #pragma unroll
            for (int r = 0; r < 4; r++)
                #pragma unroll
                for (int c = 0; c < 4; c++)
                    s[r][c] += aa[r].x*bk[c].x + aa[r].y*bk[c].y
                             + aa[r].z*bk[c].z + aa[r].w*bk[c].w;
        }

        bool diag = (n0 == q0);
        #pragma unroll
        for (int r = 0; r < 4; r++) {
            int row = ty*4 + r;
            float sv[4], mloc = -INFINITY;
            #pragma unroll
            for (int c = 0; c < 4; c++) {
                int col = tx + 16*c;
                float x_ = s[r][c] * scale;
                if (diag && col > row) x_ = -INFINITY;
                sv[c] = x_;
                mloc = fmaxf(mloc, x_);
            }
            #pragma unroll
            for (int o = 8; o; o >>= 1)
                mloc = fmaxf(mloc, __shfl_xor_sync(0xffffffffu, mloc, o, 16));
            float mn = fmaxf(m[r], mloc);
            float alpha = __expf(m[r] - mn);
            float rsum = 0.f;
            #pragma unroll
            for (int c = 0; c < 4; c++) {
                float p_ = __expf(sv[c] - mn);
                Ps[row*PP_PAD + tx + 16*c] = p_;
                rsum += p_;
            }
            #pragma unroll
            for (int o = 8; o; o >>= 1)
                rsum += __shfl_xor_sync(0xffffffffu, rsum, o, 16);
            l[r] = l[r]*alpha + rsum;
            m[r] = mn;
            #pragma unroll
            for (int c = 0; c < 8; c++) O[r][c] *= alpha;

            float qpr = qps[row];
            float gv[4], gloc = -INFINITY;
            #pragma unroll
            for (int c = 0; c < 4; c++) {
                int col = tx + 16*c;
                float g_ = qpr * kps[col];
                if (diag && col > row) g_ = -INFINITY;
                gv[c] = g_;
                gloc = fmaxf(gloc, g_);
            }
            #pragma unroll
            for (int o = 8; o; o >>= 1)
                gloc = fmaxf(gloc, __shfl_xor_sync(0xffffffffu, gloc, o, 16));
            float gmn = fmaxf(mg[r], gloc);
            float galpha = __expf(mg[r] - gmn);
            float gsum = 0.f;
            #pragma unroll
            for (int c = 0; c < 4; c++) {
                float p_ = __expf(gv[c] - gmn);
                Pg[row*PP_PAD + tx + 16*c] = p_;
                gsum += p_;
            }
            #pragma unroll
            for (int o = 8; o; o >>= 1)
                gsum += __shfl_xor_sync(0xffffffffu, gsum, o, 16);
            lg[r] = lg[r]*galpha + gsum;
            mg[r] = gmn;
            #pragma unroll
            for (int c = 0; c < 8; c++) Og[r][c] *= galpha;
        }
        __syncthreads();

        #pragma unroll 4
        for (int n = 0; n < 64; n++) {
            float vv[8];
            #pragma unroll
            for (int c = 0; c < 8; c++) vv[c] = Vs[n*QP_PAD + tx + 16*c];
            #pragma unroll
            for (int r = 0; r < 4; r++) {
                float pr  = Ps[(ty*4 + r)*PP_PAD + n];
                float pgr = Pg[(ty*4 + r)*PP_PAD + n];
                #pragma unroll
                for (int c = 0; c < 8; c++) {
                    O[r][c]  += pr  * vv[c];
                    Og[r][c] += pgr * vv[c];
                }
            }
        }
    }

    #pragma unroll
    for (int r = 0; r < 4; r++) {
        int row = q0 + ty*4 + r;
        float invl  = 1.f / l[r];
        float invlg = 1.f / lg[r];
        #pragma unroll
        for (int c = 0; c < 8; c++) {
            float o  = O[r][c]  * invl;
            float og = Og[r][c] * invlg;
            float val = o + hs * (og - o);
            out[(size_t)(b*TT + row)*CC + h*DD + tx + 16*c] = val;
        }
    }
}

// ---------------------------------------------------------------------------
// Launcher
// ---------------------------------------------------------------------------
extern "C" void kernel_launch(void* const* d_in, const int* in_sizes, int n_in,
                              void* d_out, int out_size)
{
    const float* x   = (const float*)d_in[0];
    const float* Wq  = (const float*)d_in[1];
    const float* Wk  = (const float*)d_in[2];
    const float* Wv  = (const float*)d_in[3];
    const float* Wo  = (const float*)d_in[4];
    const float* lng = (const float*)d_in[5];
    const float* lnb = (const float*)d_in[6];
    const float* hsc = (const float*)d_in[7];
    const float* hdr = (const float*)d_in[8];
    float* out = (float*)d_out;

    float* base = nullptr;
    cudaGetSymbolAddress((void**)&base, g_scratch);
    float* xn = base + XN_OFF;
    float* gq = base + Q_OFF;
    float* gk = base + K_OFF;
    float* gv = base + V_OFF;
    float* ao = base + AO_OFF;
    float* gqp = base + QP_OFF;
    float* gkp = base + KP_OFF;

    cudaFuncSetAttribute(gemm_mma<0>,
                         cudaFuncAttributeMaxDynamicSharedMemorySize, GEMM_SMEM);
    cudaFuncSetAttribute(gemm_mma<1>,
                         cudaFuncAttributeMaxDynamicSharedMemorySize, GEMM_SMEM);
    cudaFuncSetAttribute(attn_kernel,
                         cudaFuncAttributeMaxDynamicSharedMemorySize, ATTN_SMEM);

    ln_kernel<<<NTOK, 256>>>(x, lng, lnb, xn);

    dim3 gg(CC / 128, NTOK / 128);
    gemm_mma<0><<<gg, 256, GEMM_SMEM>>>(xn, Wq, nullptr, gq);
    gemm_mma<0><<<gg, 256, GEMM_SMEM>>>(xn, Wk, nullptr, gk);
    gemm_mma<0><<<gg, 256, GEMM_SMEM>>>(xn, Wv, nullptr, gv);

    rope_kernel<<<BB*HH*TT, 128>>>(gq, gk, hdr, gqp, gkp);

    attn_kernel<<<dim3(TT/64, BB*HH), 256, ATTN_SMEM>>>(gq, gk, gv, gqp, gkp, hsc, ao);

    gemm_mma<1><<<gg, 256, GEMM_SMEM>>>(ao, Wo, x, out);
}

// round 4
// speedup vs baseline: 2.3417x; 1.8888x over previous
#include <cuda_runtime.h>
#include <cuda_bf16.h>
#include <math.h>

// Problem constants
#define BB 4
#define TT 2048
#define CC 1024
#define HH 8
#define DD 128
#define NTOK (BB*TT)          // 8192
#define BH   (BB*HH)          // 32

// ---------------------------------------------------------------------------
// Scratch (single static device buffer; no allocations anywhere)
// ---------------------------------------------------------------------------
#define SZ_F32 ((size_t)NTOK*CC*4)   // 33.5 MB
#define SZ_BF  ((size_t)NTOK*CC*2)   // 16.8 MB
#define SZ_P   ((size_t)BH*TT*4)

#define OFF_XN  ((size_t)0)
#define OFF_QF  (OFF_XN + SZ_F32)
#define OFF_KF  (OFF_QF + SZ_F32)
#define OFF_AO  (OFF_KF + SZ_F32)
#define OFF_QH  (OFF_AO + SZ_F32)
#define OFF_QL  (OFF_QH + SZ_BF)
#define OFF_KH  (OFF_QL + SZ_BF)
#define OFF_KL  (OFF_KH + SZ_BF)
#define OFF_VTH (OFF_KL + SZ_BF)
#define OFF_VTL (OFF_VTH + SZ_BF)
#define OFF_QP  (OFF_VTL + SZ_BF)
#define OFF_KP  (OFF_QP + SZ_P)
#define SCRATCH_BYTES (OFF_KP + SZ_P)

__device__ __align__(256) unsigned char g_scratch[SCRATCH_BYTES];

// ---------------------------------------------------------------------------
// helpers
// ---------------------------------------------------------------------------
__device__ __forceinline__ void mma_bf16(float* c, const unsigned* a,
                                         unsigned b0, unsigned b1) {
    asm volatile(
        "mma.sync.aligned.m16n8k16.row.col.f32.bf16.bf16.f32 "
        "{%0,%1,%2,%3},{%4,%5,%6,%7},{%8,%9},{%0,%1,%2,%3};"
        : "+f"(c[0]), "+f"(c[1]), "+f"(c[2]), "+f"(c[3])
        : "r"(a[0]), "r"(a[1]), "r"(a[2]), "r"(a[3]), "r"(b0), "r"(b1));
}

// split two floats into packed bf16 hi and lo words
__device__ __forceinline__ void split2(float a, float b, unsigned& hi, unsigned& lo) {
    __nv_bfloat162 h = __floats2bfloat162_rn(a, b);
    float la = a - __bfloat162float(h.x);
    float lb = b - __bfloat162float(h.y);
    __nv_bfloat162 l = __floats2bfloat162_rn(la, lb);
    hi = *(unsigned*)&h;
    lo = *(unsigned*)&l;
}

// ---------------------------------------------------------------------------
// LayerNorm
// ---------------------------------------------------------------------------
__global__ __launch_bounds__(256) void ln_kernel(
    const float* __restrict__ x, const float* __restrict__ gam,
    const float* __restrict__ bet, float* __restrict__ xn)
{
    int row = blockIdx.x;
    int t   = threadIdx.x;
    const float4* xr = (const float4*)(x + (size_t)row * CC);
    float4 v = xr[t];
    float s  = v.x + v.y + v.z + v.w;
    float ss = v.x*v.x + v.y*v.y + v.z*v.z + v.w*v.w;
    #pragma unroll
    for (int o = 16; o; o >>= 1) {
        s  += __shfl_xor_sync(0xffffffffu, s,  o);
        ss += __shfl_xor_sync(0xffffffffu, ss, o);
    }
    __shared__ float ws[8], wss[8];
    int wid = t >> 5;
    if ((t & 31) == 0) { ws[wid] = s; wss[wid] = ss; }
    __syncthreads();
    s = 0.f; ss = 0.f;
    #pragma unroll
    for (int i = 0; i < 8; i++) { s += ws[i]; ss += wss[i]; }
    float mu  = s * (1.f / CC);
    float var = ss * (1.f / CC) - mu * mu;
    float inv = rsqrtf(var + 1e-5f);
    float4 g4 = ((const float4*)gam)[t];
    float4 b4 = ((const float4*)bet)[t];
    float4 o;
    o.x = (v.x - mu) * inv * g4.x + b4.x;
    o.y = (v.y - mu) * inv * g4.y + b4.y;
    o.z = (v.z - mu) * inv * g4.z + b4.z;
    o.w = (v.w - mu) * inv * g4.w + b4.w;
    ((float4*)(xn + (size_t)row * CC))[t] = o;
}

// ---------------------------------------------------------------------------
// 3xBF16 tensor-core GEMM:  C[m,n] = sum_k A[m,k] * W[n,k]
// 128x128x32 tile, 256 threads (8 warps 4x2), m16n8k16 bf16, hi/lo split.
// MODE 0: out fp32 head-major [B,H,T,D]
// MODE 1: out = X + acc (fp32, row-major)
// MODE 2: transposed bf16 hi/lo planes [B,H,D,T]  (V path)
// ---------------------------------------------------------------------------
#define TPB 40
#define GEMM_NIT (CC/32)
#define GEMM_SMEM (4 * 2 * 128 * TPB * 2)   // 81920 B

template<int MODE>
__global__ __launch_bounds__(256, 1) void gemm_mma(
    const float* __restrict__ A, const float* __restrict__ W,
    const float* __restrict__ X, float* __restrict__ out,
    __nv_bfloat16* __restrict__ oh, __nv_bfloat16* __restrict__ ol)
{
    extern __shared__ __nv_bfloat16 smb[];
    __nv_bfloat16* Ah = smb;
    __nv_bfloat16* Al = Ah + 2*128*TPB;
    __nv_bfloat16* Bh = Al + 2*128*TPB;
    __nv_bfloat16* Bl = Bh + 2*128*TPB;

    int tid  = threadIdx.x;
    int lane = tid & 31, warp = tid >> 5;
    int g = lane >> 2, tig = lane & 3;
    int wm = warp >> 1, wn = warp & 1;
    int m0 = blockIdx.y << 7, n0 = blockIdx.x << 7;

    int lrow = tid >> 1;
    int lcol = (tid & 1) << 4;

    const float* Ag = A + (size_t)(m0 + lrow) * CC + lcol;
    const float* Wg = W + (size_t)(n0 + lrow) * CC + lcol;

    float acc[16][4];
    #pragma unroll
    for (int i = 0; i < 16; i++)
        #pragma unroll
        for (int j = 0; j < 4; j++) acc[i][j] = 0.f;

    float4 va[4], vb[4];
    #pragma unroll
    for (int i = 0; i < 4; i++) {
        va[i] = *(const float4*)(Ag + i*4);
        vb[i] = *(const float4*)(Wg + i*4);
    }

    auto store_tile = [&](int buf) {
        int base = (buf*128 + lrow)*TPB + lcol;
        #pragma unroll
        for (int i = 0; i < 4; i++) {
            float4 v = va[i];
            __nv_bfloat162 h0 = __floats2bfloat162_rn(v.x, v.y);
            __nv_bfloat162 h1 = __floats2bfloat162_rn(v.z, v.w);
            __nv_bfloat162 l0 = __floats2bfloat162_rn(v.x - __bfloat162float(h0.x),
                                                      v.y - __bfloat162float(h0.y));
            __nv_bfloat162 l1 = __floats2bfloat162_rn(v.z - __bfloat162float(h1.x),
                                                      v.w - __bfloat162float(h1.y));
            *(__nv_bfloat162*)&Ah[base + i*4]     = h0;
            *(__nv_bfloat162*)&Ah[base + i*4 + 2] = h1;
            *(__nv_bfloat162*)&Al[base + i*4]     = l0;
            *(__nv_bfloat162*)&Al[base + i*4 + 2] = l1;
            v = vb[i];
            h0 = __floats2bfloat162_rn(v.x, v.y);
            h1 = __floats2bfloat162_rn(v.z, v.w);
            l0 = __floats2bfloat162_rn(v.x - __bfloat162float(h0.x),
                                       v.y - __bfloat162float(h0.y));
            l1 = __floats2bfloat162_rn(v.z - __bfloat162float(h1.x),
                                       v.w - __bfloat162float(h1.y));
            *(__nv_bfloat162*)&Bh[base + i*4]     = h0;
            *(__nv_bfloat162*)&Bh[base + i*4 + 2] = h1;
            *(__nv_bfloat162*)&Bl[base + i*4]     = l0;
            *(__nv_bfloat162*)&Bl[base + i*4 + 2] = l1;
        }
    };

    store_tile(0);
    __syncthreads();

    for (int it = 0; it < GEMM_NIT; it++) {
        int buf = it & 1;
        if (it + 1 < GEMM_NIT) {
            const float* Ap = Ag + (it+1)*32;
            const float* Wp = Wg + (it+1)*32;
            #pragma unroll
            for (int i = 0; i < 4; i++) {
                va[i] = *(const float4*)(Ap + i*4);
                vb[i] = *(const float4*)(Wp + i*4);
            }
        }

        #pragma unroll
        for (int kk = 0; kk < 2; kk++) {
            int cw = kk*16 + 2*tig;
            unsigned ah[2][4], al[2][4];
            #pragma unroll
            for (int mi = 0; mi < 2; mi++) {
                int r0 = wm*32 + mi*16 + g;
                int b0 = (buf*128 + r0)*TPB + cw;
                int b1 = b0 + 8*TPB;
                ah[mi][0] = *(unsigned*)&Ah[b0];
                ah[mi][1] = *(unsigned*)&Ah[b1];
                ah[mi][2] = *(unsigned*)&Ah[b0 + 8];
                ah[mi][3] = *(unsigned*)&Ah[b1 + 8];
                al[mi][0] = *(unsigned*)&Al[b0];
                al[mi][1] = *(unsigned*)&Al[b1];
                al[mi][2] = *(unsigned*)&Al[b0 + 8];
                al[mi][3] = *(unsigned*)&Al[b1 + 8];
            }
            #pragma unroll
            for (int ni = 0; ni < 8; ni++) {
                int col = wn*64 + ni*8 + g;
                int bb = (buf*128 + col)*TPB + cw;
                unsigned bh0 = *(unsigned*)&Bh[bb];
                unsigned bh1 = *(unsigned*)&Bh[bb + 8];
                unsigned bl0 = *(unsigned*)&Bl[bb];
                unsigned bl1 = *(unsigned*)&Bl[bb + 8];
                #pragma unroll
                for (int mi = 0; mi < 2; mi++) {
                    float* c = acc[mi*8 + ni];
                    mma_bf16(c, ah[mi], bh0, bh1);
                    mma_bf16(c, ah[mi], bl0, bl1);
                    mma_bf16(c, al[mi], bh0, bh1);
                }
            }
        }

        if (it + 1 < GEMM_NIT) store_tile(buf ^ 1);
        __syncthreads();
    }

    // epilogue
    #pragma unroll
    for (int mi = 0; mi < 2; mi++) {
        #pragma unroll
        for (int ni = 0; ni < 8; ni++) {
            const float* c = acc[mi*8 + ni];
            int r0 = m0 + wm*32 + mi*16 + g;
            int c0 = n0 + wn*64 + ni*8 + 2*tig;
            #pragma unroll
            for (int half = 0; half < 2; half++) {
                int r = r0 + half*8;
                float v0 = c[half*2], v1 = c[half*2 + 1];
                if (MODE == 0) {
                    int b = r >> 11, t = r & 2047, h = c0 >> 7, d = c0 & 127;
                    *(float2*)&out[(((size_t)(b*HH + h) * TT) + t) * DD + d] =
                        make_float2(v0, v1);
                } else if (MODE == 1) {
                    size_t o = (size_t)r * CC + c0;
                    float2 xv = *(const float2*)&X[o];
                    *(float2*)&out[o] = make_float2(xv.x + v0, xv.y + v1);
                } else {
                    int b = r >> 11, t = r & 2047, h = c0 >> 7, d = c0 & 127;
                    size_t rb = ((size_t)((b*HH + h)*DD + d)) * TT + t;
                    __nv_bfloat16 h0 = __float2bfloat16(v0);
                    __nv_bfloat16 h1 = __float2bfloat16(v1);
                    oh[rb]      = h0;
                    ol[rb]      = __float2bfloat16(v0 - __bfloat162float(h0));
                    oh[rb + TT] = h1;
                    ol[rb + TT] = __float2bfloat16(v1 - __bfloat162float(h1));
                }
            }
        }
    }
}

// ---------------------------------------------------------------------------
// RoPE on q,k: read fp32 head-major, write bf16 hi/lo planes + qp/kp
// ---------------------------------------------------------------------------
__global__ __launch_bounds__(128) void rope_kernel(
    const float* __restrict__ qf, const float* __restrict__ kf,
    const float* __restrict__ dirs,
    __nv_bfloat16* __restrict__ qh, __nv_bfloat16* __restrict__ ql,
    __nv_bfloat16* __restrict__ kh, __nv_bfloat16* __restrict__ kl,
    float* __restrict__ qp, float* __restrict__ kp)
{
    int idx = blockIdx.x;                  // (b*H+h)*T + t
    int t = idx & (TT - 1);
    int h = (idx >> 11) & (HH - 1);
    int tid = threadIdx.x;
    int i = tid & 63;
    bool isq = tid < 64;
    const float* src = (isq ? qf : kf) + (size_t)idx * DD;
    __nv_bfloat16* dh = isq ? qh : kh;
    __nv_bfloat16* dl = isq ? ql : kl;
    float x1 = src[i], x2 = src[i + 64];
    float inv = expf(-9.210340371976184f * (float)i * (1.f / 64.f));
    float ang = (float)t * inv;
    float sn, cs;
    sincosf(ang, &sn, &cs);
    float y1 = x1 * cs - x2 * sn;
    float y2 = x2 * cs + x1 * sn;
    size_t o = (size_t)idx * DD;
    __nv_bfloat16 h1 = __float2bfloat16(y1);
    __nv_bfloat16 h2 = __float2bfloat16(y2);
    dh[o + i]      = h1;
    dl[o + i]      = __float2bfloat16(y1 - __bfloat162float(h1));
    dh[o + i + 64] = h2;
    dl[o + i + 64] = __float2bfloat16(y2 - __bfloat162float(h2));
    __shared__ float red[6];
    if (i < 3) red[(tid >> 6) * 3 + i] = y1 * dirs[h * 3 + i];
    __syncthreads();
    if (tid == 0)  qp[idx] = red[0] + red[1] + red[2];
    if (tid == 64) kp[idx] = red[3] + red[4] + red[5];
}

// ---------------------------------------------------------------------------
// Two-pass dual-softmax flash attention, 3xBF16 MMA.
// CTA = 128 threads (4 warps), Br=64 (warp owns 16 rows), Bc=64.
// Pass 1: S MMA -> row sums l (attn) and lg (geo; rank-1 scores).
// Pass 2: S MMA again -> combined weights w = (1-hs)e/l + hs*eg/lg -> one PV.
// No max subtraction (scores provably small) => exact softmax, no rescaling.
// ---------------------------------------------------------------------------
#define KSTR 136     // bf16 stride for Q/K tiles (row = 128 d + pad 8)
#define VSTR 72      // bf16 stride for V^T tiles (row = 64 kpos + pad 8)
#define ATTN_SMEM ((4*64*KSTR + 2*128*VSTR)*2 + 3*64*4)   // 107264 B
#define SCALE 0.08838834764831845f

__global__ __launch_bounds__(128, 1) void attn_mma(
    const __nv_bfloat16* __restrict__ qh, const __nv_bfloat16* __restrict__ ql,
    const __nv_bfloat16* __restrict__ kh, const __nv_bfloat16* __restrict__ kl,
    const __nv_bfloat16* __restrict__ vth, const __nv_bfloat16* __restrict__ vtl,
    const float* __restrict__ qp, const float* __restrict__ kp,
    const float* __restrict__ hsc, float* __restrict__ ao)
{
    extern __shared__ unsigned char sma[];
    __nv_bfloat16* Qh  = (__nv_bfloat16*)sma;
    __nv_bfloat16* Ql  = Qh + 64*KSTR;
    __nv_bfloat16* Kh  = Ql + 64*KSTR;
    __nv_bfloat16* Kl  = Kh + 64*KSTR;
    __nv_bfloat16* Vth = Kl + 64*KSTR;
    __nv_bfloat16* Vtl = Vth + 128*VSTR;
    float* kps = (float*)(Vtl + 128*VSTR);
    float* ls  = kps + 64;
    float* lgs = ls + 64;

    int bh = blockIdx.y;
    int b = bh >> 3, h = bh & 7;
    int q0 = (gridDim.x - 1 - blockIdx.x) << 6;   // big tiles first
    size_t tb = (size_t)bh * TT;
    int tid = threadIdx.x;
    int lane = tid & 31, warp = tid >> 5;
    int g = lane >> 2, tig = lane & 3;
    int r0loc = warp*16 + g, r1loc = r0loc + 8;

    // load Q tiles (hi/lo)
    {
        const __nv_bfloat16* qhg = qh + (tb + q0) * DD;
        const __nv_bfloat16* qlg = ql + (tb + q0) * DD;
        for (int idx = tid; idx < 1024; idx += 128) {
            int r = idx >> 4, c = (idx & 15) << 3;
            *(uint4*)&Qh[r*KSTR + c] = *(const uint4*)&qhg[r*DD + c];
            *(uint4*)&Ql[r*KSTR + c] = *(const uint4*)&qlg[r*DD + c];
        }
    }
    float hs  = hsc[h];
    float qp0 = qp[tb + q0 + r0loc];
    float qp1 = qp[tb + q0 + r1loc];
    int ntiles = (q0 >> 6) + 1;

    // S = Q K^T for current K tile -> s[8][4]
    auto computeS = [&](float s[8][4]) {
        #pragma unroll
        for (int i = 0; i < 8; i++)
            #pragma unroll
            for (int j = 0; j < 4; j++) s[i][j] = 0.f;
        #pragma unroll
        for (int kk = 0; kk < 8; kk++) {
            int cw = kk*16 + 2*tig;
            unsigned qa[4], qb[4];
            int a0 = r0loc*KSTR + cw, a1 = r1loc*KSTR + cw;
            qa[0] = *(unsigned*)&Qh[a0];      qa[1] = *(unsigned*)&Qh[a1];
            qa[2] = *(unsigned*)&Qh[a0 + 8];  qa[3] = *(unsigned*)&Qh[a1 + 8];
            qb[0] = *(unsigned*)&Ql[a0];      qb[1] = *(unsigned*)&Ql[a1];
            qb[2] = *(unsigned*)&Ql[a0 + 8];  qb[3] = *(unsigned*)&Ql[a1 + 8];
            #pragma unroll
            for (int ni = 0; ni < 8; ni++) {
                int kr = (ni*8 + g)*KSTR + cw;
                unsigned bh0 = *(unsigned*)&Kh[kr];
                unsigned bh1 = *(unsigned*)&Kh[kr + 8];
                unsigned bl0 = *(unsigned*)&Kl[kr];
                unsigned bl1 = *(unsigned*)&Kl[kr + 8];
                mma_bf16(s[ni], qa, bh0, bh1);
                mma_bf16(s[ni], qa, bl0, bl1);
                mma_bf16(s[ni], qb, bh0, bh1);
            }
        }
    };

    // ---------------- PASS 1: row sums ----------------
    float l0 = 0.f, l1 = 0.f, lg0 = 0.f, lg1 = 0.f;
    for (int it = 0; it < ntiles; it++) {
        int n0 = it << 6;
        __syncthreads();
        {
            const __nv_bfloat16* khg = kh + (tb + n0) * DD;
            const __nv_bfloat16* klg = kl + (tb + n0) * DD;
            for (int idx = tid; idx < 1024; idx += 128) {
                int r = idx >> 4, c = (idx & 15) << 3;
                *(uint4*)&Kh[r*KSTR + c] = *(const uint4*)&khg[r*DD + c];
                *(uint4*)&Kl[r*KSTR + c] = *(const uint4*)&klg[r*DD + c];
            }
            if (tid < 64) kps[tid] = kp[tb + n0 + tid];
        }
        __syncthreads();

        float s[8][4];
        computeS(s);
        bool diag = (n0 == q0);
        #pragma unroll
        for (int ni = 0; ni < 8; ni++) {
            #pragma unroll
            for (int j = 0; j < 4; j++) {
                int cl = ni*8 + 2*tig + (j & 1);
                int rl = (j < 2) ? r0loc : r1loc;
                bool ok = !diag || (cl <= rl);
                float e  = ok ? __expf(s[ni][j] * SCALE) : 0.f;
                float ge = ok ? __expf(((j < 2) ? qp0 : qp1) * kps[cl]) : 0.f;
                if (j < 2) { l0 += e; lg0 += ge; }
                else       { l1 += e; lg1 += ge; }
            }
        }
    }
    // reduce across the 4 lanes of each row group
    #pragma unroll
    for (int o = 1; o <= 2; o <<= 1) {
        l0  += __shfl_xor_sync(0xffffffffu, l0,  o);
        l1  += __shfl_xor_sync(0xffffffffu, l1,  o);
        lg0 += __shfl_xor_sync(0xffffffffu, lg0, o);
        lg1 += __shfl_xor_sync(0xffffffffu, lg1, o);
    }
    if (tig == 0) {
        ls[r0loc] = l0;  lgs[r0loc] = lg0;
        ls[r1loc] = l1;  lgs[r1loc] = lg1;
    }
    __syncthreads();
    float c1a = (1.f - hs) / ls[r0loc], c2a = hs / lgs[r0loc];
    float c1b = (1.f - hs) / ls[r1loc], c2b = hs / lgs[r1loc];

    // ---------------- PASS 2: weighted PV ----------------
    float O[16][4];
    #pragma unroll
    for (int i = 0; i < 16; i++)
        #pragma unroll
        for (int j = 0; j < 4; j++) O[i][j] = 0.f;

    for (int it = 0; it < ntiles; it++) {
        int n0 = it << 6;
        __syncthreads();
        {
            const __nv_bfloat16* khg = kh + (tb + n0) * DD;
            const __nv_bfloat16* klg = kl + (tb + n0) * DD;
            for (int idx = tid; idx < 1024; idx += 128) {
                int r = idx >> 4, c = (idx & 15) << 3;
                *(uint4*)&Kh[r*KSTR + c] = *(const uint4*)&khg[r*DD + c];
                *(uint4*)&Kl[r*KSTR + c] = *(const uint4*)&klg[r*DD + c];
            }
            const __nv_bfloat16* vhg = vth + (size_t)bh*DD*TT + n0;
            const __nv_bfloat16* vlg = vtl + (size_t)bh*DD*TT + n0;
            for (int idx = tid; idx < 1024; idx += 128) {
                int d = idx >> 3, c = (idx & 7) << 3;
                *(uint4*)&Vth[d*VSTR + c] = *(const uint4*)&vhg[(size_t)d*TT + c];
                *(uint4*)&Vtl[d*VSTR + c] = *(const uint4*)&vlg[(size_t)d*TT + c];
            }
            if (tid < 64) kps[tid] = kp[tb + n0 + tid];
        }
        __syncthreads();

        float s[8][4];
        computeS(s);
        bool diag = (n0 == q0);
        #pragma unroll
        for (int ni = 0; ni < 8; ni++) {
            #pragma unroll
            for (int j = 0; j < 4; j++) {
                int cl = ni*8 + 2*tig + (j & 1);
                int rl = (j < 2) ? r0loc : r1loc;
                bool ok = !diag || (cl <= rl);
                float e  = __expf(s[ni][j] * SCALE);
                float ge = __expf(((j < 2) ? qp0 : qp1) * kps[cl]);
                float wv = ((j < 2) ? c1a : c1b) * e + ((j < 2) ? c2a : c2b) * ge;
                s[ni][j] = ok ? wv : 0.f;
            }
        }
        // pack P fragments (pair adjacent n-atoms -> k16 chunks)
        unsigned ph[4][4], pl[4][4];
        #pragma unroll
        for (int kc = 0; kc < 4; kc++) {
            split2(s[2*kc][0],   s[2*kc][1],   ph[kc][0], pl[kc][0]);
            split2(s[2*kc][2],   s[2*kc][3],   ph[kc][1], pl[kc][1]);
            split2(s[2*kc+1][0], s[2*kc+1][1], ph[kc][2], pl[kc][2]);
            split2(s[2*kc+1][2], s[2*kc+1][3], ph[kc][3], pl[kc][3]);
        }
        // O += P @ V
        #pragma unroll
        for (int nd = 0; nd < 16; nd++) {
            #pragma unroll
            for (int kc = 0; kc < 4; kc++) {
                int vb = (nd*8 + g)*VSTR + kc*16 + 2*tig;
                unsigned vh0 = *(unsigned*)&Vth[vb];
                unsigned vh1 = *(unsigned*)&Vth[vb + 8];
                unsigned vl0 = *(unsigned*)&Vtl[vb];
                unsigned vl1 = *(unsigned*)&Vtl[vb + 8];
                mma_bf16(O[nd], ph[kc], vh0, vh1);
                mma_bf16(O[nd], ph[kc], vl0, vl1);
                mma_bf16(O[nd], pl[kc], vh0, vh1);
            }
        }
    }

    // epilogue: weights already include normalization + blend
    size_t orow0 = (size_t)(b*TT + q0 + r0loc) * CC + h*DD;
    size_t orow1 = (size_t)(b*TT + q0 + r1loc) * CC + h*DD;
    #pragma unroll
    for (int nd = 0; nd < 16; nd++) {
        int d0 = nd*8 + 2*tig;
        *(float2*)&ao[orow0 + d0] = make_float2(O[nd][0], O[nd][1]);
        *(float2*)&ao[orow1 + d0] = make_float2(O[nd][2], O[nd][3]);
    }
}

// ---------------------------------------------------------------------------
// Launcher
// ---------------------------------------------------------------------------
extern "C" void kernel_launch(void* const* d_in, const int* in_sizes, int n_in,
                              void* d_out, int out_size)
{
    const float* x   = (const float*)d_in[0];
    const float* Wq  = (const float*)d_in[1];
    const float* Wk  = (const float*)d_in[2];
    const float* Wv  = (const float*)d_in[3];
    const float* Wo  = (const float*)d_in[4];
    const float* lng = (const float*)d_in[5];
    const float* lnb = (const float*)d_in[6];
    const float* hsc = (const float*)d_in[7];
    const float* hdr = (const float*)d_in[8];
    float* out = (float*)d_out;

    unsigned char* base = nullptr;
    cudaGetSymbolAddress((void**)&base, g_scratch);
    float* xn = (float*)(base + OFF_XN);
    float* qf = (float*)(base + OFF_QF);
    float* kf = (float*)(base + OFF_KF);
    float* ao = (float*)(base + OFF_AO);
    __nv_bfloat16* qhp = (__nv_bfloat16*)(base + OFF_QH);
    __nv_bfloat16* qlp = (__nv_bfloat16*)(base + OFF_QL);
    __nv_bfloat16* khp = (__nv_bfloat16*)(base + OFF_KH);
    __nv_bfloat16* klp = (__nv_bfloat16*)(base + OFF_KL);
    __nv_bfloat16* vth = (__nv_bfloat16*)(base + OFF_VTH);
    __nv_bfloat16* vtl = (__nv_bfloat16*)(base + OFF_VTL);
    float* gqp = (float*)(base + OFF_QP);
    float* gkp = (float*)(base + OFF_KP);

    cudaFuncSetAttribute(gemm_mma<0>,
                         cudaFuncAttributeMaxDynamicSharedMemorySize, GEMM_SMEM);
    cudaFuncSetAttribute(gemm_mma<1>,
                         cudaFuncAttributeMaxDynamicSharedMemorySize, GEMM_SMEM);
    cudaFuncSetAttribute(gemm_mma<2>,
                         cudaFuncAttributeMaxDynamicSharedMemorySize, GEMM_SMEM);
    cudaFuncSetAttribute(attn_mma,
                         cudaFuncAttributeMaxDynamicSharedMemorySize, ATTN_SMEM);

    ln_kernel<<<NTOK, 256>>>(x, lng, lnb, xn);

    dim3 gg(CC / 128, NTOK / 128);
    gemm_mma<0><<<gg, 256, GEMM_SMEM>>>(xn, Wq, nullptr, qf, nullptr, nullptr);
    gemm_mma<0><<<gg, 256, GEMM_SMEM>>>(xn, Wk, nullptr, kf, nullptr, nullptr);
    gemm_mma<2><<<gg, 256, GEMM_SMEM>>>(xn, Wv, nullptr, nullptr, vth, vtl);

    rope_kernel<<<BH*TT, 128>>>(qf, kf, hdr, qhp, qlp, khp, klp, gqp, gkp);

    attn_mma<<<dim3(TT/64, BH), 128, ATTN_SMEM>>>(qhp, qlp, khp, klp, vth, vtl,
                                                  gqp, gkp, hsc, ao);

    gemm_mma<1><<<gg, 256, GEMM_SMEM>>>(ao, Wo, x, out, nullptr, nullptr);
}

// round 5
// speedup vs baseline: 2.5752x; 1.0997x over previous
#include <cuda_runtime.h>
#include <cuda_bf16.h>
#include <math.h>

// Problem constants
#define BB 4
#define TT 2048
#define CC 1024
#define HH 8
#define DD 128
#define NTOK (BB*TT)          // 8192
#define BH   (BB*HH)          // 32
#define WPL  ((size_t)CC*CC)  // weight plane elems

// ---------------------------------------------------------------------------
// Scratch
// ---------------------------------------------------------------------------
#define SZ_F32 ((size_t)NTOK*CC*4)
#define SZ_BF  ((size_t)NTOK*CC*2)
#define SZ_WPL ((size_t)4*CC*CC*2)
#define SZ_P   ((size_t)BH*TT*4)

#define OFF_XNH ((size_t)0)
#define OFF_XNL (OFF_XNH + SZ_BF)
#define OFF_WH  (OFF_XNL + SZ_BF)
#define OFF_WL  (OFF_WH + SZ_WPL)
#define OFF_QF  (OFF_WL + SZ_WPL)
#define OFF_KF  (OFF_QF + SZ_F32)
#define OFF_QH  (OFF_KF + SZ_F32)
#define OFF_QL  (OFF_QH + SZ_BF)
#define OFF_KH  (OFF_QL + SZ_BF)
#define OFF_KL  (OFF_KH + SZ_BF)
#define OFF_VTH (OFF_KL + SZ_BF)
#define OFF_VTL (OFF_VTH + SZ_BF)
#define OFF_AOH (OFF_VTL + SZ_BF)
#define OFF_AOL (OFF_AOH + SZ_BF)
#define OFF_QP  (OFF_AOL + SZ_BF)
#define OFF_KP  (OFF_QP + SZ_P)
#define SCRATCH_BYTES (OFF_KP + SZ_P)

__device__ __align__(256) unsigned char g_scratch[SCRATCH_BYTES];

// ---------------------------------------------------------------------------
// helpers
// ---------------------------------------------------------------------------
__device__ __forceinline__ void mma_bf16(float* c, const unsigned* a,
                                         unsigned b0, unsigned b1) {
    asm volatile(
        "mma.sync.aligned.m16n8k16.row.col.f32.bf16.bf16.f32 "
        "{%0,%1,%2,%3},{%4,%5,%6,%7},{%8,%9},{%0,%1,%2,%3};"
        : "+f"(c[0]), "+f"(c[1]), "+f"(c[2]), "+f"(c[3])
        : "r"(a[0]), "r"(a[1]), "r"(a[2]), "r"(a[3]), "r"(b0), "r"(b1));
}

__device__ __forceinline__ void ldsm_x4(unsigned r[4], unsigned addr) {
    asm volatile("ldmatrix.sync.aligned.m8n8.x4.shared.b16 {%0,%1,%2,%3}, [%4];"
        : "=r"(r[0]), "=r"(r[1]), "=r"(r[2]), "=r"(r[3]) : "r"(addr));
}

#define CP16(dst, src) \
    asm volatile("cp.async.cg.shared.global [%0], [%1], 16;" :: "r"(dst), "l"(src))
#define CP_COMMIT() asm volatile("cp.async.commit_group;")
#define CP_WAIT0()  asm volatile("cp.async.wait_group 0;")

__device__ __forceinline__ void split2(float a, float b, unsigned& hi, unsigned& lo) {
    __nv_bfloat162 h = __floats2bfloat162_rn(a, b);
    float la = a - __bfloat162float(h.x);
    float lb = b - __bfloat162float(h.y);
    __nv_bfloat162 l = __floats2bfloat162_rn(la, lb);
    hi = *(unsigned*)&h;
    lo = *(unsigned*)&l;
}

// ---------------------------------------------------------------------------
// LayerNorm -> bf16 hi/lo planes
// ---------------------------------------------------------------------------
__global__ __launch_bounds__(256) void ln_split(
    const float* __restrict__ x, const float* __restrict__ gam,
    const float* __restrict__ bet,
    __nv_bfloat16* __restrict__ xnh, __nv_bfloat16* __restrict__ xnl)
{
    int row = blockIdx.x;
    int t   = threadIdx.x;
    const float4* xr = (const float4*)(x + (size_t)row * CC);
    float4 v = xr[t];
    float s  = v.x + v.y + v.z + v.w;
    float ss = v.x*v.x + v.y*v.y + v.z*v.z + v.w*v.w;
    #pragma unroll
    for (int o = 16; o; o >>= 1) {
        s  += __shfl_xor_sync(0xffffffffu, s,  o);
        ss += __shfl_xor_sync(0xffffffffu, ss, o);
    }
    __shared__ float ws[8], wss[8];
    int wid = t >> 5;
    if ((t & 31) == 0) { ws[wid] = s; wss[wid] = ss; }
    __syncthreads();
    s = 0.f; ss = 0.f;
    #pragma unroll
    for (int i = 0; i < 8; i++) { s += ws[i]; ss += wss[i]; }
    float mu  = s * (1.f / CC);
    float var = ss * (1.f / CC) - mu * mu;
    float inv = rsqrtf(var + 1e-5f);
    float4 g4 = ((const float4*)gam)[t];
    float4 b4 = ((const float4*)bet)[t];
    float4 o;
    o.x = (v.x - mu) * inv * g4.x + b4.x;
    o.y = (v.y - mu) * inv * g4.y + b4.y;
    o.z = (v.z - mu) * inv * g4.z + b4.z;
    o.w = (v.w - mu) * inv * g4.w + b4.w;
    unsigned h0, l0, h1, l1;
    split2(o.x, o.y, h0, l0);
    split2(o.z, o.w, h1, l1);
    size_t off = (size_t)row * CC + t*4;
    *(uint2*)&xnh[off] = make_uint2(h0, h1);
    *(uint2*)&xnl[off] = make_uint2(l0, l1);
}

// ---------------------------------------------------------------------------
// Split 4 weight matrices into bf16 hi/lo planes: plane order Wq,Wk,Wv,Wo
// ---------------------------------------------------------------------------
__global__ __launch_bounds__(256) void wsplit(
    const float* __restrict__ w0, const float* __restrict__ w1,
    const float* __restrict__ w2, const float* __restrict__ w3,
    __nv_bfloat16* __restrict__ wh, __nv_bfloat16* __restrict__ wl)
{
    int mid = blockIdx.x >> 10;
    const float* src = (mid == 0) ? w0 : (mid == 1) ? w1 : (mid == 2) ? w2 : w3;
    size_t idx = ((size_t)(blockIdx.x & 1023))*1024 + threadIdx.x*4;
    float4 v = *(const float4*)(src + idx);
    unsigned h0, l0, h1, l1;
    split2(v.x, v.y, h0, l0);
    split2(v.z, v.w, h1, l1);
    size_t off = (size_t)mid*WPL + idx;
    *(uint2*)&wh[off] = make_uint2(h0, h1);
    *(uint2*)&wl[off] = make_uint2(l0, l1);
}

// ---------------------------------------------------------------------------
// 3xBF16 GEMM v2: pre-split bf16 operands, cp.async double buffer, ldmatrix.
// BM=128, BN=128, BK=32, 256 thr (8 warps, 4x2), 2 CTA/SM.
// MODE 0: Q&K fused (grid.x=16; sel=x>>3) -> fp32 head-major [B,H,T,D]
// MODE 1: out0 = X + acc (fp32 row-major)
// MODE 2: V -> transposed bf16 hi/lo planes [B,H,D,T]
// ---------------------------------------------------------------------------
#define GSTR 40
#define GEMM_SMEM (4*2*128*GSTR*2)   // 81920 B

template<int MODE>
__global__ __launch_bounds__(256, 2) void gemm2(
    const __nv_bfloat16* __restrict__ Ah, const __nv_bfloat16* __restrict__ Al,
    const __nv_bfloat16* __restrict__ Wh, const __nv_bfloat16* __restrict__ Wl,
    const float* __restrict__ X,
    float* __restrict__ out0, float* __restrict__ out1,
    __nv_bfloat16* __restrict__ oh, __nv_bfloat16* __restrict__ ol)
{
    extern __shared__ __nv_bfloat16 smb[];
    __nv_bfloat16* sAh = smb;
    __nv_bfloat16* sAl = sAh + 2*128*GSTR;
    __nv_bfloat16* sBh = sAl + 2*128*GSTR;
    __nv_bfloat16* sBl = sBh + 2*128*GSTR;
    unsigned uAh = (unsigned)__cvta_generic_to_shared(sAh);
    unsigned uAl = (unsigned)__cvta_generic_to_shared(sAl);
    unsigned uBh = (unsigned)__cvta_generic_to_shared(sBh);
    unsigned uBl = (unsigned)__cvta_generic_to_shared(sBl);

    int tid = threadIdx.x, lane = tid & 31, warp = tid >> 5;
    int g = lane >> 2, tig = lane & 3;
    int wm = warp >> 1, wn = warp & 1;
    int sel = (MODE == 0) ? (blockIdx.x >> 3) : 0;
    int n0 = (MODE == 0) ? ((blockIdx.x & 7) << 7) : (blockIdx.x << 7);
    int m0 = blockIdx.y << 7;
    const __nv_bfloat16* Wph = Wh + (size_t)sel*WPL;
    const __nv_bfloat16* Wpl = Wl + (size_t)sel*WPL;

    int lr = tid >> 2;            // 0..63
    int lc8 = (tid & 3) * 8;

    float acc[16][4];
    #pragma unroll
    for (int i = 0; i < 16; i++)
        #pragma unroll
        for (int j = 0; j < 4; j++) acc[i][j] = 0.f;

    auto load_stage = [&](int buf, int k0) {
        size_t a0 = (size_t)(m0 + lr) * CC + k0 + lc8;
        size_t b0 = (size_t)(n0 + lr) * CC + k0 + lc8;
        unsigned d0 = (unsigned)(((buf*128 + lr)*GSTR + lc8) * 2);
        unsigned d1 = (unsigned)(((buf*128 + lr + 64)*GSTR + lc8) * 2);
        CP16(uAh + d0, Ah + a0);  CP16(uAh + d1, Ah + a0 + (size_t)64*CC);
        CP16(uAl + d0, Al + a0);  CP16(uAl + d1, Al + a0 + (size_t)64*CC);
        CP16(uBh + d0, Wph + b0); CP16(uBh + d1, Wph + b0 + (size_t)64*CC);
        CP16(uBl + d0, Wpl + b0); CP16(uBl + d1, Wpl + b0 + (size_t)64*CC);
    };

    load_stage(0, 0);
    CP_COMMIT();
    CP_WAIT0();
    __syncthreads();

    int lra = ((lane >> 3) & 1) * 8 + (lane & 7);
    int lca = (lane >> 4) * 8;
    const int NIT = CC / 32;

    for (int it = 0; it < NIT; it++) {
        int buf = it & 1;
        if (it + 1 < NIT) { load_stage(buf ^ 1, (it + 1) * 32); CP_COMMIT(); }

        int sb = buf * 128;
        #pragma unroll
        for (int kk = 0; kk < 2; kk++) {
            int col = kk*16 + lca;
            unsigned ah[2][4], al2[2][4];
            #pragma unroll
            for (int mi = 0; mi < 2; mi++) {
                unsigned offA = (unsigned)(((sb + wm*32 + mi*16 + lra)*GSTR + col) * 2);
                ldsm_x4(ah[mi],  uAh + offA);
                ldsm_x4(al2[mi], uAl + offA);
            }
            #pragma unroll
            for (int ng = 0; ng < 4; ng++) {
                unsigned offB = (unsigned)(((sb + wn*64 + ng*16 + lra)*GSTR + col) * 2);
                unsigned b4h[4], b4l[4];
                ldsm_x4(b4h, uBh + offB);
                ldsm_x4(b4l, uBl + offB);
                #pragma unroll
                for (int hf = 0; hf < 2; hf++) {
                    int ni = ng*2 + hf;
                    unsigned bh0 = b4h[hf], bh1 = b4h[2 + hf];
                    unsigned bl0 = b4l[hf], bl1 = b4l[2 + hf];
                    #pragma unroll
                    for (int mi = 0; mi < 2; mi++) {
                        float* c = acc[mi*8 + ni];
                        mma_bf16(c, ah[mi],  bh0, bh1);
                        mma_bf16(c, ah[mi],  bl0, bl1);
                        mma_bf16(c, al2[mi], bh0, bh1);
                    }
                }
            }
        }
        __syncthreads();
        if (it + 1 < NIT) { CP_WAIT0(); __syncthreads(); }
    }

    // epilogue
    float* outp = (MODE == 0) ? (sel ? out1 : out0) : out0;
    #pragma unroll
    for (int mi = 0; mi < 2; mi++) {
        #pragma unroll
        for (int ni = 0; ni < 8; ni++) {
            const float* c = acc[mi*8 + ni];
            int r0 = m0 + wm*32 + mi*16 + g;
            int c0 = n0 + wn*64 + ni*8 + 2*tig;
            #pragma unroll
            for (int half = 0; half < 2; half++) {
                int r = r0 + half*8;
                float v0 = c[half*2], v1 = c[half*2 + 1];
                if (MODE == 0) {
                    int b = r >> 11, t = r & 2047, h = c0 >> 7, d = c0 & 127;
                    *(float2*)&outp[(((size_t)(b*HH + h) * TT) + t) * DD + d] =
                        make_float2(v0, v1);
                } else if (MODE == 1) {
                    size_t o = (size_t)r * CC + c0;
                    float2 xv = *(const float2*)&X[o];
                    *(float2*)&outp[o] = make_float2(xv.x + v0, xv.y + v1);
                } else {
                    int b = r >> 11, t = r & 2047, h = c0 >> 7, d = c0 & 127;
                    size_t rb = ((size_t)((b*HH + h)*DD + d)) * TT + t;
                    __nv_bfloat16 h0 = __float2bfloat16(v0);
                    __nv_bfloat16 h1 = __float2bfloat16(v1);
                    oh[rb]      = h0;
                    ol[rb]      = __float2bfloat16(v0 - __bfloat162float(h0));
                    oh[rb + TT] = h1;
                    ol[rb + TT] = __float2bfloat16(v1 - __bfloat162float(h1));
                }
            }
        }
    }
}

// ---------------------------------------------------------------------------
// RoPE on q,k: read fp32 head-major, write bf16 hi/lo planes + qp/kp
// ---------------------------------------------------------------------------
__global__ __launch_bounds__(128) void rope_kernel(
    const float* __restrict__ qf, const float* __restrict__ kf,
    const float* __restrict__ dirs,
    __nv_bfloat16* __restrict__ qh, __nv_bfloat16* __restrict__ ql,
    __nv_bfloat16* __restrict__ kh, __nv_bfloat16* __restrict__ kl,
    float* __restrict__ qp, float* __restrict__ kp)
{
    int idx = blockIdx.x;
    int t = idx & (TT - 1);
    int h = (idx >> 11) & (HH - 1);
    int tid = threadIdx.x;
    int i = tid & 63;
    bool isq = tid < 64;
    const float* src = (isq ? qf : kf) + (size_t)idx * DD;
    __nv_bfloat16* dh = isq ? qh : kh;
    __nv_bfloat16* dl = isq ? ql : kl;
    float x1 = src[i], x2 = src[i + 64];
    float inv = expf(-9.210340371976184f * (float)i * (1.f / 64.f));
    float ang = (float)t * inv;
    float sn, cs;
    sincosf(ang, &sn, &cs);
    float y1 = x1 * cs - x2 * sn;
    float y2 = x2 * cs + x1 * sn;
    size_t o = (size_t)idx * DD;
    __nv_bfloat16 h1 = __float2bfloat16(y1);
    __nv_bfloat16 h2 = __float2bfloat16(y2);
    dh[o + i]      = h1;
    dl[o + i]      = __float2bfloat16(y1 - __bfloat162float(h1));
    dh[o + i + 64] = h2;
    dl[o + i + 64] = __float2bfloat16(y2 - __bfloat162float(h2));
    __shared__ float red[6];
    if (i < 3) red[(tid >> 6) * 3 + i] = y1 * dirs[h * 3 + i];
    __syncthreads();
    if (tid == 0)  qp[idx] = red[0] + red[1] + red[2];
    if (tid == 64) kp[idx] = red[3] + red[4] + red[5];
}

// ---------------------------------------------------------------------------
// Two-pass dual-softmax flash attention, 3xBF16 MMA + ldmatrix.
// ---------------------------------------------------------------------------
#define KSTR 136
#define VSTR 72
#define ATTN_SMEM ((4*64*KSTR + 2*128*VSTR)*2 + 3*64*4)
#define SCALE 0.08838834764831845f

__global__ __launch_bounds__(128, 1) void attn_mma(
    const __nv_bfloat16* __restrict__ qh, const __nv_bfloat16* __restrict__ ql,
    const __nv_bfloat16* __restrict__ kh, const __nv_bfloat16* __restrict__ kl,
    const __nv_bfloat16* __restrict__ vth, const __nv_bfloat16* __restrict__ vtl,
    const float* __restrict__ qp, const float* __restrict__ kp,
    const float* __restrict__ hsc,
    __nv_bfloat16* __restrict__ aoh, __nv_bfloat16* __restrict__ aol)
{
    extern __shared__ unsigned char sma[];
    __nv_bfloat16* Qh  = (__nv_bfloat16*)sma;
    __nv_bfloat16* Ql  = Qh + 64*KSTR;
    __nv_bfloat16* Kh  = Ql + 64*KSTR;
    __nv_bfloat16* Kl  = Kh + 64*KSTR;
    __nv_bfloat16* Vth = Kl + 64*KSTR;
    __nv_bfloat16* Vtl = Vth + 128*VSTR;
    float* kps = (float*)(Vtl + 128*VSTR);
    float* ls  = kps + 64;
    float* lgs = ls + 64;

    unsigned uQh = (unsigned)__cvta_generic_to_shared(Qh);
    unsigned uQl = (unsigned)__cvta_generic_to_shared(Ql);
    unsigned uKh = (unsigned)__cvta_generic_to_shared(Kh);
    unsigned uKl = (unsigned)__cvta_generic_to_shared(Kl);
    unsigned uVh = (unsigned)__cvta_generic_to_shared(Vth);
    unsigned uVl = (unsigned)__cvta_generic_to_shared(Vtl);

    int bh = blockIdx.y;
    int b = bh >> 3, h = bh & 7;
    int q0 = (gridDim.x - 1 - blockIdx.x) << 6;
    size_t tb = (size_t)bh * TT;
    int tid = threadIdx.x;
    int lane = tid & 31, warp = tid >> 5;
    int g = lane >> 2, tig = lane & 3;
    int r0loc = warp*16 + g, r1loc = r0loc + 8;
    int lra = ((lane >> 3) & 1) * 8 + (lane & 7);
    int lca = (lane >> 4) * 8;

    {
        const __nv_bfloat16* qhg = qh + (tb + q0) * DD;
        const __nv_bfloat16* qlg = ql + (tb + q0) * DD;
        for (int idx = tid; idx < 1024; idx += 128) {
            int r = idx >> 4, c = (idx & 15) << 3;
            *(uint4*)&Qh[r*KSTR + c] = *(const uint4*)&qhg[r*DD + c];
            *(uint4*)&Ql[r*KSTR + c] = *(const uint4*)&qlg[r*DD + c];
        }
    }
    float hs  = hsc[h];
    float qp0 = qp[tb + q0 + r0loc];
    float qp1 = qp[tb + q0 + r1loc];
    int ntiles = (q0 >> 6) + 1;

    auto computeS = [&](float s[8][4]) {
        #pragma unroll
        for (int i = 0; i < 8; i++)
            #pragma unroll
            for (int j = 0; j < 4; j++) s[i][j] = 0.f;
        #pragma unroll
        for (int kk = 0; kk < 8; kk++) {
            int col = kk*16 + lca;
            unsigned qoff = (unsigned)(((warp*16 + lra)*KSTR + col) * 2);
            unsigned qa[4], qb[4];
            ldsm_x4(qa, uQh + qoff);
            ldsm_x4(qb, uQl + qoff);
            #pragma unroll
            for (int ng = 0; ng < 4; ng++) {
                unsigned koff = (unsigned)(((ng*16 + lra)*KSTR + col) * 2);
                unsigned kh4[4], kl4[4];
                ldsm_x4(kh4, uKh + koff);
                ldsm_x4(kl4, uKl + koff);
                #pragma unroll
                for (int hf = 0; hf < 2; hf++) {
                    int ni = ng*2 + hf;
                    mma_bf16(s[ni], qa, kh4[hf], kh4[2 + hf]);
                    mma_bf16(s[ni], qa, kl4[hf], kl4[2 + hf]);
                    mma_bf16(s[ni], qb, kh4[hf], kh4[2 + hf]);
                }
            }
        }
    };

    // ---------------- PASS 1: row sums ----------------
    float l0 = 0.f, l1 = 0.f, lg0 = 0.f, lg1 = 0.f;
    for (int it = 0; it < ntiles; it++) {
        int n0 = it << 6;
        __syncthreads();
        {
            const __nv_bfloat16* khg = kh + (tb + n0) * DD;
            const __nv_bfloat16* klg = kl + (tb + n0) * DD;
            for (int idx = tid; idx < 1024; idx += 128) {
                int r = idx >> 4, c = (idx & 15) << 3;
                *(uint4*)&Kh[r*KSTR + c] = *(const uint4*)&khg[r*DD + c];
                *(uint4*)&Kl[r*KSTR + c] = *(const uint4*)&klg[r*DD + c];
            }
            if (tid < 64) kps[tid] = kp[tb + n0 + tid];
        }
        __syncthreads();

        float s[8][4];
        computeS(s);
        bool diag = (n0 == q0);
        #pragma unroll
        for (int ni = 0; ni < 8; ni++) {
            #pragma unroll
            for (int j = 0; j < 4; j++) {
                int cl = ni*8 + 2*tig + (j & 1);
                int rl = (j < 2) ? r0loc : r1loc;
                bool ok = !diag || (cl <= rl);
                float e  = ok ? __expf(s[ni][j] * SCALE) : 0.f;
                float ge = ok ? __expf(((j < 2) ? qp0 : qp1) * kps[cl]) : 0.f;
                if (j < 2) { l0 += e; lg0 += ge; }
                else       { l1 += e; lg1 += ge; }
            }
        }
    }
    #pragma unroll
    for (int o = 1; o <= 2; o <<= 1) {
        l0  += __shfl_xor_sync(0xffffffffu, l0,  o);
        l1  += __shfl_xor_sync(0xffffffffu, l1,  o);
        lg0 += __shfl_xor_sync(0xffffffffu, lg0, o);
        lg1 += __shfl_xor_sync(0xffffffffu, lg1, o);
    }
    if (tig == 0) {
        ls[r0loc] = l0;  lgs[r0loc] = lg0;
        ls[r1loc] = l1;  lgs[r1loc] = lg1;
    }
    __syncthreads();
    float c1a = (1.f - hs) / ls[r0loc], c2a = hs / lgs[r0loc];
    float c1b = (1.f - hs) / ls[r1loc], c2b = hs / lgs[r1loc];

    // ---------------- PASS 2: weighted PV ----------------
    float O[16][4];
    #pragma unroll
    for (int i = 0; i < 16; i++)
        #pragma unroll
        for (int j = 0; j < 4; j++) O[i][j] = 0.f;

    for (int it = 0; it < ntiles; it++) {
        int n0 = it << 6;
        __syncthreads();
        {
            const __nv_bfloat16* khg = kh + (tb + n0) * DD;
            const __nv_bfloat16* klg = kl + (tb + n0) * DD;
            for (int idx = tid; idx < 1024; idx += 128) {
                int r = idx >> 4, c = (idx & 15) << 3;
                *(uint4*)&Kh[r*KSTR + c] = *(const uint4*)&khg[r*DD + c];
                *(uint4*)&Kl[r*KSTR + c] = *(const uint4*)&klg[r*DD + c];
            }
            const __nv_bfloat16* vhg = vth + (size_t)bh*DD*TT + n0;
            const __nv_bfloat16* vlg = vtl + (size_t)bh*DD*TT + n0;
            for (int idx = tid; idx < 1024; idx += 128) {
                int d = idx >> 3, c = (idx & 7) << 3;
                *(uint4*)&Vth[d*VSTR + c] = *(const uint4*)&vhg[(size_t)d*TT + c];
                *(uint4*)&Vtl[d*VSTR + c] = *(const uint4*)&vlg[(size_t)d*TT + c];
            }
            if (tid < 64) kps[tid] = kp[tb + n0 + tid];
        }
        __syncthreads();

        float s[8][4];
        computeS(s);
        bool diag = (n0 == q0);
        #pragma unroll
        for (int ni = 0; ni < 8; ni++) {
            #pragma unroll
            for (int j = 0; j < 4; j++) {
                int cl = ni*8 + 2*tig + (j & 1);
                int rl = (j < 2) ? r0loc : r1loc;
                bool ok = !diag || (cl <= rl);
                float e  = __expf(s[ni][j] * SCALE);
                float ge = __expf(((j < 2) ? qp0 : qp1) * kps[cl]);
                float wv = ((j < 2) ? c1a : c1b) * e + ((j < 2) ? c2a : c2b) * ge;
                s[ni][j] = ok ? wv : 0.f;
            }
        }
        unsigned ph[4][4], pl[4][4];
        #pragma unroll
        for (int kc = 0; kc < 4; kc++) {
            split2(s[2*kc][0],   s[2*kc][1],   ph[kc][0], pl[kc][0]);
            split2(s[2*kc][2],   s[2*kc][3],   ph[kc][1], pl[kc][1]);
            split2(s[2*kc+1][0], s[2*kc+1][1], ph[kc][2], pl[kc][2]);
            split2(s[2*kc+1][2], s[2*kc+1][3], ph[kc][3], pl[kc][3]);
        }
        #pragma unroll
        for (int ndg = 0; ndg < 8; ndg++) {
            #pragma unroll
            for (int kc = 0; kc < 4; kc++) {
                unsigned voff = (unsigned)(((ndg*16 + lra)*VSTR + kc*16 + lca) * 2);
                unsigned vh4[4], vl4[4];
                ldsm_x4(vh4, uVh + voff);
                ldsm_x4(vl4, uVl + voff);
                #pragma unroll
                for (int hf = 0; hf < 2; hf++) {
                    int nd = ndg*2 + hf;
                    mma_bf16(O[nd], ph[kc], vh4[hf], vh4[2 + hf]);
                    mma_bf16(O[nd], ph[kc], vl4[hf], vl4[2 + hf]);
                    mma_bf16(O[nd], pl[kc], vh4[hf], vh4[2 + hf]);
                }
            }
        }
    }

    // epilogue: write bf16 hi/lo planes for the Wo GEMM
    size_t orow0 = (size_t)(b*TT + q0 + r0loc) * CC + h*DD;
    size_t orow1 = (size_t)(b*TT + q0 + r1loc) * CC + h*DD;
    #pragma unroll
    for (int nd = 0; nd < 16; nd++) {
        int d0 = nd*8 + 2*tig;
        unsigned hh, ll;
        split2(O[nd][0], O[nd][1], hh, ll);
        *(unsigned*)&aoh[orow0 + d0] = hh;
        *(unsigned*)&aol[orow0 + d0] = ll;
        split2(O[nd][2], O[nd][3], hh, ll);
        *(unsigned*)&aoh[orow1 + d0] = hh;
        *(unsigned*)&aol[orow1 + d0] = ll;
    }
}

// ---------------------------------------------------------------------------
// Launcher
// ---------------------------------------------------------------------------
extern "C" void kernel_launch(void* const* d_in, const int* in_sizes, int n_in,
                              void* d_out, int out_size)
{
    const float* x   = (const float*)d_in[0];
    const float* Wq  = (const float*)d_in[1];
    const float* Wk  = (const float*)d_in[2];
    const float* Wv  = (const float*)d_in[3];
    const float* Wo  = (const float*)d_in[4];
    const float* lng = (const float*)d_in[5];
    const float* lnb = (const float*)d_in[6];
    const float* hsc = (const float*)d_in[7];
    const float* hdr = (const float*)d_in[8];
    float* out = (float*)d_out;

    unsigned char* base = nullptr;
    cudaGetSymbolAddress((void**)&base, g_scratch);
    __nv_bfloat16* xnh = (__nv_bfloat16*)(base + OFF_XNH);
    __nv_bfloat16* xnl = (__nv_bfloat16*)(base + OFF_XNL);
    __nv_bfloat16* wh  = (__nv_bfloat16*)(base + OFF_WH);
    __nv_bfloat16* wl  = (__nv_bfloat16*)(base + OFF_WL);
    float* qf = (float*)(base + OFF_QF);
    float* kf = (float*)(base + OFF_KF);
    __nv_bfloat16* qhp = (__nv_bfloat16*)(base + OFF_QH);
    __nv_bfloat16* qlp = (__nv_bfloat16*)(base + OFF_QL);
    __nv_bfloat16* khp = (__nv_bfloat16*)(base + OFF_KH);
    __nv_bfloat16* klp = (__nv_bfloat16*)(base + OFF_KL);
    __nv_bfloat16* vth = (__nv_bfloat16*)(base + OFF_VTH);
    __nv_bfloat16* vtl = (__nv_bfloat16*)(base + OFF_VTL);
    __nv_bfloat16* aoh = (__nv_bfloat16*)(base + OFF_AOH);
    __nv_bfloat16* aol = (__nv_bfloat16*)(base + OFF_AOL);
    float* gqp = (float*)(base + OFF_QP);
    float* gkp = (float*)(base + OFF_KP);

    cudaFuncSetAttribute(gemm2<0>,
                         cudaFuncAttributeMaxDynamicSharedMemorySize, GEMM_SMEM);
    cudaFuncSetAttribute(gemm2<1>,
                         cudaFuncAttributeMaxDynamicSharedMemorySize, GEMM_SMEM);
    cudaFuncSetAttribute(gemm2<2>,
                         cudaFuncAttributeMaxDynamicSharedMemorySize, GEMM_SMEM);
    cudaFuncSetAttribute(attn_mma,
                         cudaFuncAttributeMaxDynamicSharedMemorySize, ATTN_SMEM);

    ln_split<<<NTOK, 256>>>(x, lng, lnb, xnh, xnl);
    wsplit<<<4096, 256>>>(Wq, Wk, Wv, Wo, wh, wl);

    gemm2<0><<<dim3(16, NTOK/128), 256, GEMM_SMEM>>>(
        xnh, xnl, wh, wl, nullptr, qf, kf, nullptr, nullptr);
    gemm2<2><<<dim3(8, NTOK/128), 256, GEMM_SMEM>>>(
        xnh, xnl, wh + 2*WPL, wl + 2*WPL, nullptr, nullptr, nullptr, vth, vtl);

    rope_kernel<<<BH*TT, 128>>>(qf, kf, hdr, qhp, qlp, khp, klp, gqp, gkp);

    attn_mma<<<dim3(TT/64, BH), 128, ATTN_SMEM>>>(qhp, qlp, khp, klp, vth, vtl,
                                                  gqp, gkp, hsc, aoh, aol);

    gemm2<1><<<dim3(8, NTOK/128), 256, GEMM_SMEM>>>(
        aoh, aol, wh + 3*WPL, wl + 3*WPL, x, out, nullptr, nullptr, nullptr);
}

// round 6
// speedup vs baseline: 2.5826x; 1.0029x over previous
#include <cuda_runtime.h>
#include <cuda_bf16.h>
#include <math.h>

// Problem constants
#define BB 4
#define TT 2048
#define CC 1024
#define HH 8
#define DD 128
#define NTOK (BB*TT)          // 8192
#define BH   (BB*HH)          // 32
#define WPL  ((size_t)CC*CC)  // weight plane elems

// ---------------------------------------------------------------------------
// Scratch
// ---------------------------------------------------------------------------
#define SZ_F32 ((size_t)NTOK*CC*4)
#define SZ_BF  ((size_t)NTOK*CC*2)
#define SZ_WPL ((size_t)4*CC*CC*2)
#define SZ_P   ((size_t)BH*TT*4)

#define OFF_XNH ((size_t)0)
#define OFF_XNL (OFF_XNH + SZ_BF)
#define OFF_WH  (OFF_XNL + SZ_BF)
#define OFF_WL  (OFF_WH + SZ_WPL)
#define OFF_QF  (OFF_WL + SZ_WPL)
#define OFF_KF  (OFF_QF + SZ_F32)
#define OFF_QH  (OFF_KF + SZ_F32)
#define OFF_QL  (OFF_QH + SZ_BF)
#define OFF_KH  (OFF_QL + SZ_BF)
#define OFF_KL  (OFF_KH + SZ_BF)
#define OFF_VTH (OFF_KL + SZ_BF)
#define OFF_VTL (OFF_VTH + SZ_BF)
#define OFF_AOH (OFF_VTL + SZ_BF)
#define OFF_AOL (OFF_AOH + SZ_BF)
#define OFF_QP  (OFF_AOL + SZ_BF)
#define OFF_KP  (OFF_QP + SZ_P)
#define SCRATCH_BYTES (OFF_KP + SZ_P)

__device__ __align__(256) unsigned char g_scratch[SCRATCH_BYTES];

// ---------------------------------------------------------------------------
// helpers
// ---------------------------------------------------------------------------
__device__ __forceinline__ void mma_bf16(float* c, const unsigned* a,
                                         unsigned b0, unsigned b1) {
    asm volatile(
        "mma.sync.aligned.m16n8k16.row.col.f32.bf16.bf16.f32 "
        "{%0,%1,%2,%3},{%4,%5,%6,%7},{%8,%9},{%0,%1,%2,%3};"
        : "+f"(c[0]), "+f"(c[1]), "+f"(c[2]), "+f"(c[3])
        : "r"(a[0]), "r"(a[1]), "r"(a[2]), "r"(a[3]), "r"(b0), "r"(b1));
}

__device__ __forceinline__ void ldsm_x4(unsigned r[4], unsigned addr) {
    asm volatile("ldmatrix.sync.aligned.m8n8.x4.shared.b16 {%0,%1,%2,%3}, [%4];"
        : "=r"(r[0]), "=r"(r[1]), "=r"(r[2]), "=r"(r[3]) : "r"(addr));
}

#define CP16(dst, src) \
    asm volatile("cp.async.cg.shared.global [%0], [%1], 16;" :: "r"(dst), "l"(src))
#define CP_COMMIT() asm volatile("cp.async.commit_group;")
#define CP_WAIT0()  asm volatile("cp.async.wait_group 0;")

__device__ __forceinline__ void split2(float a, float b, unsigned& hi, unsigned& lo) {
    __nv_bfloat162 h = __floats2bfloat162_rn(a, b);
    float la = a - __bfloat162float(h.x);
    float lb = b - __bfloat162float(h.y);
    __nv_bfloat162 l = __floats2bfloat162_rn(la, lb);
    hi = *(unsigned*)&h;
    lo = *(unsigned*)&l;
}

// ---------------------------------------------------------------------------
// LayerNorm -> bf16 hi/lo planes
// ---------------------------------------------------------------------------
__global__ __launch_bounds__(256) void ln_split(
    const float* __restrict__ x, const float* __restrict__ gam,
    const float* __restrict__ bet,
    __nv_bfloat16* __restrict__ xnh, __nv_bfloat16* __restrict__ xnl)
{
    int row = blockIdx.x;
    int t   = threadIdx.x;
    const float4* xr = (const float4*)(x + (size_t)row * CC);
    float4 v = xr[t];
    float s  = v.x + v.y + v.z + v.w;
    float ss = v.x*v.x + v.y*v.y + v.z*v.z + v.w*v.w;
    #pragma unroll
    for (int o = 16; o; o >>= 1) {
        s  += __shfl_xor_sync(0xffffffffu, s,  o);
        ss += __shfl_xor_sync(0xffffffffu, ss, o);
    }
    __shared__ float ws[8], wss[8];
    int wid = t >> 5;
    if ((t & 31) == 0) { ws[wid] = s; wss[wid] = ss; }
    __syncthreads();
    s = 0.f; ss = 0.f;
    #pragma unroll
    for (int i = 0; i < 8; i++) { s += ws[i]; ss += wss[i]; }
    float mu  = s * (1.f / CC);
    float var = ss * (1.f / CC) - mu * mu;
    float inv = rsqrtf(var + 1e-5f);
    float4 g4 = ((const float4*)gam)[t];
    float4 b4 = ((const float4*)bet)[t];
    float4 o;
    o.x = (v.x - mu) * inv * g4.x + b4.x;
    o.y = (v.y - mu) * inv * g4.y + b4.y;
    o.z = (v.z - mu) * inv * g4.z + b4.z;
    o.w = (v.w - mu) * inv * g4.w + b4.w;
    unsigned h0, l0, h1, l1;
    split2(o.x, o.y, h0, l0);
    split2(o.z, o.w, h1, l1);
    size_t off = (size_t)row * CC + t*4;
    *(uint2*)&xnh[off] = make_uint2(h0, h1);
    *(uint2*)&xnl[off] = make_uint2(l0, l1);
}

// ---------------------------------------------------------------------------
// Split 4 weight matrices into bf16 hi/lo planes: plane order Wq,Wk,Wv,Wo
// ---------------------------------------------------------------------------
__global__ __launch_bounds__(256) void wsplit(
    const float* __restrict__ w0, const float* __restrict__ w1,
    const float* __restrict__ w2, const float* __restrict__ w3,
    __nv_bfloat16* __restrict__ wh, __nv_bfloat16* __restrict__ wl)
{
    int mid = blockIdx.x >> 10;
    const float* src = (mid == 0) ? w0 : (mid == 1) ? w1 : (mid == 2) ? w2 : w3;
    size_t idx = ((size_t)(blockIdx.x & 1023))*1024 + threadIdx.x*4;
    float4 v = *(const float4*)(src + idx);
    unsigned h0, l0, h1, l1;
    split2(v.x, v.y, h0, l0);
    split2(v.z, v.w, h1, l1);
    size_t off = (size_t)mid*WPL + idx;
    *(uint2*)&wh[off] = make_uint2(h0, h1);
    *(uint2*)&wl[off] = make_uint2(l0, l1);
}

// ---------------------------------------------------------------------------
// 3xBF16 GEMM v2: pre-split bf16 operands, cp.async double buffer, ldmatrix.
// BM=128, BN=128, BK=32, 256 thr (8 warps, 4x2), 2 CTA/SM.
// MODE 0: Q&K fused (grid.x=16; sel=x>>3) -> fp32 head-major [B,H,T,D]
// MODE 1: out0 = X + acc (fp32 row-major)
// MODE 2: V -> transposed bf16 hi/lo planes [B,H,D,T]
// ---------------------------------------------------------------------------
#define GSTR 40
#define GEMM_SMEM (4*2*128*GSTR*2)   // 81920 B

template<int MODE>
__global__ __launch_bounds__(256, 2) void gemm2(
    const __nv_bfloat16* __restrict__ Ah, const __nv_bfloat16* __restrict__ Al,
    const __nv_bfloat16* __restrict__ Wh, const __nv_bfloat16* __restrict__ Wl,
    const float* __restrict__ X,
    float* __restrict__ out0, float* __restrict__ out1,
    __nv_bfloat16* __restrict__ oh, __nv_bfloat16* __restrict__ ol)
{
    extern __shared__ __nv_bfloat16 smb[];
    __nv_bfloat16* sAh = smb;
    __nv_bfloat16* sAl = sAh + 2*128*GSTR;
    __nv_bfloat16* sBh = sAl + 2*128*GSTR;
    __nv_bfloat16* sBl = sBh + 2*128*GSTR;
    unsigned uAh = (unsigned)__cvta_generic_to_shared(sAh);
    unsigned uAl = (unsigned)__cvta_generic_to_shared(sAl);
    unsigned uBh = (unsigned)__cvta_generic_to_shared(sBh);
    unsigned uBl = (unsigned)__cvta_generic_to_shared(sBl);

    int tid = threadIdx.x, lane = tid & 31, warp = tid >> 5;
    int g = lane >> 2, tig = lane & 3;
    int wm = warp >> 1, wn = warp & 1;
    int sel = (MODE == 0) ? (blockIdx.x >> 3) : 0;
    int n0 = (MODE == 0) ? ((blockIdx.x & 7) << 7) : (blockIdx.x << 7);
    int m0 = blockIdx.y << 7;
    const __nv_bfloat16* Wph = Wh + (size_t)sel*WPL;
    const __nv_bfloat16* Wpl = Wl + (size_t)sel*WPL;

    int lr = tid >> 2;            // 0..63
    int lc8 = (tid & 3) * 8;

    float acc[16][4];
    #pragma unroll
    for (int i = 0; i < 16; i++)
        #pragma unroll
        for (int j = 0; j < 4; j++) acc[i][j] = 0.f;

    auto load_stage = [&](int buf, int k0) {
        size_t a0 = (size_t)(m0 + lr) * CC + k0 + lc8;
        size_t b0 = (size_t)(n0 + lr) * CC + k0 + lc8;
        unsigned d0 = (unsigned)(((buf*128 + lr)*GSTR + lc8) * 2);
        unsigned d1 = (unsigned)(((buf*128 + lr + 64)*GSTR + lc8) * 2);
        CP16(uAh + d0, Ah + a0);  CP16(uAh + d1, Ah + a0 + (size_t)64*CC);
        CP16(uAl + d0, Al + a0);  CP16(uAl + d1, Al + a0 + (size_t)64*CC);
        CP16(uBh + d0, Wph + b0); CP16(uBh + d1, Wph + b0 + (size_t)64*CC);
        CP16(uBl + d0, Wpl + b0); CP16(uBl + d1, Wpl + b0 + (size_t)64*CC);
    };

    load_stage(0, 0);
    CP_COMMIT();
    CP_WAIT0();
    __syncthreads();

    int lra = ((lane >> 3) & 1) * 8 + (lane & 7);
    int lca = (lane >> 4) * 8;
    const int NIT = CC / 32;

    for (int it = 0; it < NIT; it++) {
        int buf = it & 1;
        if (it + 1 < NIT) { load_stage(buf ^ 1, (it + 1) * 32); CP_COMMIT(); }

        int sb = buf * 128;
        #pragma unroll
        for (int kk = 0; kk < 2; kk++) {
            int col = kk*16 + lca;
            unsigned ah[2][4], al2[2][4];
            #pragma unroll
            for (int mi = 0; mi < 2; mi++) {
                unsigned offA = (unsigned)(((sb + wm*32 + mi*16 + lra)*GSTR + col) * 2);
                ldsm_x4(ah[mi],  uAh + offA);
                ldsm_x4(al2[mi], uAl + offA);
            }
            #pragma unroll
            for (int ng = 0; ng < 4; ng++) {
                unsigned offB = (unsigned)(((sb + wn*64 + ng*16 + lra)*GSTR + col) * 2);
                unsigned b4h[4], b4l[4];
                ldsm_x4(b4h, uBh + offB);
                ldsm_x4(b4l, uBl + offB);
                #pragma unroll
                for (int hf = 0; hf < 2; hf++) {
                    int ni = ng*2 + hf;
                    unsigned bh0 = b4h[hf], bh1 = b4h[2 + hf];
                    unsigned bl0 = b4l[hf], bl1 = b4l[2 + hf];
                    #pragma unroll
                    for (int mi = 0; mi < 2; mi++) {
                        float* c = acc[mi*8 + ni];
                        mma_bf16(c, ah[mi],  bh0, bh1);
                        mma_bf16(c, ah[mi],  bl0, bl1);
                        mma_bf16(c, al2[mi], bh0, bh1);
                    }
                }
            }
        }
        __syncthreads();
        if (it + 1 < NIT) { CP_WAIT0(); __syncthreads(); }
    }

    // epilogue
    float* outp = (MODE == 0) ? (sel ? out1 : out0) : out0;
    #pragma unroll
    for (int mi = 0; mi < 2; mi++) {
        #pragma unroll
        for (int ni = 0; ni < 8; ni++) {
            const float* c = acc[mi*8 + ni];
            int r0 = m0 + wm*32 + mi*16 + g;
            int c0 = n0 + wn*64 + ni*8 + 2*tig;
            #pragma unroll
            for (int half = 0; half < 2; half++) {
                int r = r0 + half*8;
                float v0 = c[half*2], v1 = c[half*2 + 1];
                if (MODE == 0) {
                    int b = r >> 11, t = r & 2047, h = c0 >> 7, d = c0 & 127;
                    *(float2*)&outp[(((size_t)(b*HH + h) * TT) + t) * DD + d] =
                        make_float2(v0, v1);
                } else if (MODE == 1) {
                    size_t o = (size_t)r * CC + c0;
                    float2 xv = *(const float2*)&X[o];
                    *(float2*)&outp[o] = make_float2(xv.x + v0, xv.y + v1);
                } else {
                    int b = r >> 11, t = r & 2047, h = c0 >> 7, d = c0 & 127;
                    size_t rb = ((size_t)((b*HH + h)*DD + d)) * TT + t;
                    __nv_bfloat16 h0 = __float2bfloat16(v0);
                    __nv_bfloat16 h1 = __float2bfloat16(v1);
                    oh[rb]      = h0;
                    ol[rb]      = __float2bfloat16(v0 - __bfloat162float(h0));
                    oh[rb + TT] = h1;
                    ol[rb + TT] = __float2bfloat16(v1 - __bfloat162float(h1));
                }
            }
        }
    }
}

// ---------------------------------------------------------------------------
// RoPE on q,k: read fp32 head-major, write bf16 hi/lo planes + qp/kp
// ---------------------------------------------------------------------------
__global__ __launch_bounds__(128) void rope_kernel(
    const float* __restrict__ qf, const float* __restrict__ kf,
    const float* __restrict__ dirs,
    __nv_bfloat16* __restrict__ qh, __nv_bfloat16* __restrict__ ql,
    __nv_bfloat16* __restrict__ kh, __nv_bfloat16* __restrict__ kl,
    float* __restrict__ qp, float* __restrict__ kp)
{
    int idx = blockIdx.x;
    int t = idx & (TT - 1);
    int h = (idx >> 11) & (HH - 1);
    int tid = threadIdx.x;
    int i = tid & 63;
    bool isq = tid < 64;
    const float* src = (isq ? qf : kf) + (size_t)idx * DD;
    __nv_bfloat16* dh = isq ? qh : kh;
    __nv_bfloat16* dl = isq ? ql : kl;
    float x1 = src[i], x2 = src[i + 64];
    float inv = expf(-9.210340371976184f * (float)i * (1.f / 64.f));
    float ang = (float)t * inv;
    float sn, cs;
    sincosf(ang, &sn, &cs);
    float y1 = x1 * cs - x2 * sn;
    float y2 = x2 * cs + x1 * sn;
    size_t o = (size_t)idx * DD;
    __nv_bfloat16 h1 = __float2bfloat16(y1);
    __nv_bfloat16 h2 = __float2bfloat16(y2);
    dh[o + i]      = h1;
    dl[o + i]      = __float2bfloat16(y1 - __bfloat162float(h1));
    dh[o + i + 64] = h2;
    dl[o + i + 64] = __float2bfloat16(y2 - __bfloat162float(h2));
    __shared__ float red[6];
    if (i < 3) red[(tid >> 6) * 3 + i] = y1 * dirs[h * 3 + i];
    __syncthreads();
    if (tid == 0)  qp[idx] = red[0] + red[1] + red[2];
    if (tid == 64) kp[idx] = red[3] + red[4] + red[5];
}

// ---------------------------------------------------------------------------
// Two-pass dual-softmax flash attention, 3xBF16 MMA + ldmatrix.
// ---------------------------------------------------------------------------
#define KSTR 136
#define VSTR 72
#define ATTN_SMEM ((4*64*KSTR + 2*128*VSTR)*2 + 3*64*4)
#define SCALE 0.08838834764831845f

__global__ __launch_bounds__(128, 1) void attn_mma(
    const __nv_bfloat16* __restrict__ qh, const __nv_bfloat16* __restrict__ ql,
    const __nv_bfloat16* __restrict__ kh, const __nv_bfloat16* __restrict__ kl,
    const __nv_bfloat16* __restrict__ vth, const __nv_bfloat16* __restrict__ vtl,
    const float* __restrict__ qp, const float* __restrict__ kp,
    const float* __restrict__ hsc,
    __nv_bfloat16* __restrict__ aoh, __nv_bfloat16* __restrict__ aol)
{
    extern __shared__ unsigned char sma[];
    __nv_bfloat16* Qh  = (__nv_bfloat16*)sma;
    __nv_bfloat16* Ql  = Qh + 64*KSTR;
    __nv_bfloat16* Kh  = Ql + 64*KSTR;
    __nv_bfloat16* Kl  = Kh + 64*KSTR;
    __nv_bfloat16* Vth = Kl + 64*KSTR;
    __nv_bfloat16* Vtl = Vth + 128*VSTR;
    float* kps = (float*)(Vtl + 128*VSTR);
    float* ls  = kps + 64;
    float* lgs = ls + 64;

    unsigned uQh = (unsigned)__cvta_generic_to_shared(Qh);
    unsigned uQl = (unsigned)__cvta_generic_to_shared(Ql);
    unsigned uKh = (unsigned)__cvta_generic_to_shared(Kh);
    unsigned uKl = (unsigned)__cvta_generic_to_shared(Kl);
    unsigned uVh = (unsigned)__cvta_generic_to_shared(Vth);
    unsigned uVl = (unsigned)__cvta_generic_to_shared(Vtl);

    int bh = blockIdx.y;
    int b = bh >> 3, h = bh & 7;
    int q0 = (gridDim.x - 1 - blockIdx.x) << 6;
    size_t tb = (size_t)bh * TT;
    int tid = threadIdx.x;
    int lane = tid & 31, warp = tid >> 5;
    int g = lane >> 2, tig = lane & 3;
    int r0loc = warp*16 + g, r1loc = r0loc + 8;
    int lra = ((lane >> 3) & 1) * 8 + (lane & 7);
    int lca = (lane >> 4) * 8;

    {
        const __nv_bfloat16* qhg = qh + (tb + q0) * DD;
        const __nv_bfloat16* qlg = ql + (tb + q0) * DD;
        for (int idx = tid; idx < 1024; idx += 128) {
            int r = idx >> 4, c = (idx & 15) << 3;
            *(uint4*)&Qh[r*KSTR + c] = *(const uint4*)&qhg[r*DD + c];
            *(uint4*)&Ql[r*KSTR + c] = *(const uint4*)&qlg[r*DD + c];
        }
    }
    float hs  = hsc[h];
    float qp0 = qp[tb + q0 + r0loc];
    float qp1 = qp[tb + q0 + r1loc];
    int ntiles = (q0 >> 6) + 1;

    auto computeS = [&](float s[8][4]) {
        #pragma unroll
        for (int i = 0; i < 8; i++)
            #pragma unroll
            for (int j = 0; j < 4; j++) s[i][j] = 0.f;
        #pragma unroll
        for (int kk = 0; kk < 8; kk++) {
            int col = kk*16 + lca;
            unsigned qoff = (unsigned)(((warp*16 + lra)*KSTR + col) * 2);
            unsigned qa[4], qb[4];
            ldsm_x4(qa, uQh + qoff);
            ldsm_x4(qb, uQl + qoff);
            #pragma unroll
            for (int ng = 0; ng < 4; ng++) {
                unsigned koff = (unsigned)(((ng*16 + lra)*KSTR + col) * 2);
                unsigned kh4[4], kl4[4];
                ldsm_x4(kh4, uKh + koff);
                ldsm_x4(kl4, uKl + koff);
                #pragma unroll
                for (int hf = 0; hf < 2; hf++) {
                    int ni = ng*2 + hf;
                    mma_bf16(s[ni], qa, kh4[hf], kh4[2 + hf]);
                    mma_bf16(s[ni], qa, kl4[hf], kl4[2 + hf]);
                    mma_bf16(s[ni], qb, kh4[hf], kh4[2 + hf]);
                }
            }
        }
    };

    // ---------------- PASS 1: row sums ----------------
    float l0 = 0.f, l1 = 0.f, lg0 = 0.f, lg1 = 0.f;
    for (int it = 0; it < ntiles; it++) {
        int n0 = it << 6;
        __syncthreads();
        {
            const __nv_bfloat16* khg = kh + (tb + n0) * DD;
            const __nv_bfloat16* klg = kl + (tb + n0) * DD;
            for (int idx = tid; idx < 1024; idx += 128) {
                int r = idx >> 4, c = (idx & 15) << 3;
                *(uint4*)&Kh[r*KSTR + c] = *(const uint4*)&khg[r*DD + c];
                *(uint4*)&Kl[r*KSTR + c] = *(const uint4*)&klg[r*DD + c];
            }
            if (tid < 64) kps[tid] = kp[tb + n0 + tid];
        }
        __syncthreads();

        float s[8][4];
        computeS(s);
        bool diag = (n0 == q0);
        #pragma unroll
        for (int ni = 0; ni < 8; ni++) {
            #pragma unroll
            for (int j = 0; j < 4; j++) {
                int cl = ni*8 + 2*tig + (j & 1);
                int rl = (j < 2) ? r0loc : r1loc;
                bool ok = !diag || (cl <= rl);
                float e  = ok ? __expf(s[ni][j] * SCALE) : 0.f;
                float ge = ok ? __expf(((j < 2) ? qp0 : qp1) * kps[cl]) : 0.f;
                if (j < 2) { l0 += e; lg0 += ge; }
                else       { l1 += e; lg1 += ge; }
            }
        }
    }
    #pragma unroll
    for (int o = 1; o <= 2; o <<= 1) {
        l0  += __shfl_xor_sync(0xffffffffu, l0,  o);
        l1  += __shfl_xor_sync(0xffffffffu, l1,  o);
        lg0 += __shfl_xor_sync(0xffffffffu, lg0, o);
        lg1 += __shfl_xor_sync(0xffffffffu, lg1, o);
    }
    if (tig == 0) {
        ls[r0loc] = l0;  lgs[r0loc] = lg0;
        ls[r1loc] = l1;  lgs[r1loc] = lg1;
    }
    __syncthreads();
    float c1a = (1.f - hs) / ls[r0loc], c2a = hs / lgs[r0loc];
    float c1b = (1.f - hs) / ls[r1loc], c2b = hs / lgs[r1loc];

    // ---------------- PASS 2: weighted PV ----------------
    float O[16][4];
    #pragma unroll
    for (int i = 0; i < 16; i++)
        #pragma unroll
        for (int j = 0; j < 4; j++) O[i][j] = 0.f;

    for (int it = 0; it < ntiles; it++) {
        int n0 = it << 6;
        __syncthreads();
        {
            const __nv_bfloat16* khg = kh + (tb + n0) * DD;
            const __nv_bfloat16* klg = kl + (tb + n0) * DD;
            for (int idx = tid; idx < 1024; idx += 128) {
                int r = idx >> 4, c = (idx & 15) << 3;
                *(uint4*)&Kh[r*KSTR + c] = *(const uint4*)&khg[r*DD + c];
                *(uint4*)&Kl[r*KSTR + c] = *(const uint4*)&klg[r*DD + c];
            }
            const __nv_bfloat16* vhg = vth + (size_t)bh*DD*TT + n0;
            const __nv_bfloat16* vlg = vtl + (size_t)bh*DD*TT + n0;
            for (int idx = tid; idx < 1024; idx += 128) {
                int d = idx >> 3, c = (idx & 7) << 3;
                *(uint4*)&Vth[d*VSTR + c] = *(const uint4*)&vhg[(size_t)d*TT + c];
                *(uint4*)&Vtl[d*VSTR + c] = *(const uint4*)&vlg[(size_t)d*TT + c];
            }
            if (tid < 64) kps[tid] = kp[tb + n0 + tid];
        }
        __syncthreads();

        float s[8][4];
        computeS(s);
        bool diag = (n0 == q0);
        #pragma unroll
        for (int ni = 0; ni < 8; ni++) {
            #pragma unroll
            for (int j = 0; j < 4; j++) {
                int cl = ni*8 + 2*tig + (j & 1);
                int rl = (j < 2) ? r0loc : r1loc;
                bool ok = !diag || (cl <= rl);
                float e  = __expf(s[ni][j] * SCALE);
                float ge = __expf(((j < 2) ? qp0 : qp1) * kps[cl]);
                float wv = ((j < 2) ? c1a : c1b) * e + ((j < 2) ? c2a : c2b) * ge;
                s[ni][j] = ok ? wv : 0.f;
            }
        }
        unsigned ph[4][4], pl[4][4];
        #pragma unroll
        for (int kc = 0; kc < 4; kc++) {
            split2(s[2*kc][0],   s[2*kc][1],   ph[kc][0], pl[kc][0]);
            split2(s[2*kc][2],   s[2*kc][3],   ph[kc][1], pl[kc][1]);
            split2(s[2*kc+1][0], s[2*kc+1][1], ph[kc][2], pl[kc][2]);
            split2(s[2*kc+1][2], s[2*kc+1][3], ph[kc][3], pl[kc][3]);
        }
        #pragma unroll
        for (int ndg = 0; ndg < 8; ndg++) {
            #pragma unroll
            for (int kc = 0; kc < 4; kc++) {
                unsigned voff = (unsigned)(((ndg*16 + lra)*VSTR + kc*16 + lca) * 2);
                unsigned vh4[4], vl4[4];
                ldsm_x4(vh4, uVh + voff);
                ldsm_x4(vl4, uVl + voff);
                #pragma unroll
                for (int hf = 0; hf < 2; hf++) {
                    int nd = ndg*2 + hf;
                    mma_bf16(O[nd], ph[kc], vh4[hf], vh4[2 + hf]);
                    mma_bf16(O[nd], ph[kc], vl4[hf], vl4[2 + hf]);
                    mma_bf16(O[nd], pl[kc], vh4[hf], vh4[2 + hf]);
                }
            }
        }
    }

    // epilogue: write bf16 hi/lo planes for the Wo GEMM
    size_t orow0 = (size_t)(b*TT + q0 + r0loc) * CC + h*DD;
    size_t orow1 = (size_t)(b*TT + q0 + r1loc) * CC + h*DD;
    #pragma unroll
    for (int nd = 0; nd < 16; nd++) {
        int d0 = nd*8 + 2*tig;
        unsigned hh, ll;
        split2(O[nd][0], O[nd][1], hh, ll);
        *(unsigned*)&aoh[orow0 + d0] = hh;
        *(unsigned*)&aol[orow0 + d0] = ll;
        split2(O[nd][2], O[nd][3], hh, ll);
        *(unsigned*)&aoh[orow1 + d0] = hh;
        *(unsigned*)&aol[orow1 + d0] = ll;
    }
}

// ---------------------------------------------------------------------------
// Launcher
// ---------------------------------------------------------------------------
extern "C" void kernel_launch(void* const* d_in, const int* in_sizes, int n_in,
                              void* d_out, int out_size)
{
    const float* x   = (const float*)d_in[0];
    const float* Wq  = (const float*)d_in[1];
    const float* Wk  = (const float*)d_in[2];
    const float* Wv  = (const float*)d_in[3];
    const float* Wo  = (const float*)d_in[4];
    const float* lng = (const float*)d_in[5];
    const float* lnb = (const float*)d_in[6];
    const float* hsc = (const float*)d_in[7];
    const float* hdr = (const float*)d_in[8];
    float* out = (float*)d_out;

    unsigned char* base = nullptr;
    cudaGetSymbolAddress((void**)&base, g_scratch);
    __nv_bfloat16* xnh = (__nv_bfloat16*)(base + OFF_XNH);
    __nv_bfloat16* xnl = (__nv_bfloat16*)(base + OFF_XNL);
    __nv_bfloat16* wh  = (__nv_bfloat16*)(base + OFF_WH);
    __nv_bfloat16* wl  = (__nv_bfloat16*)(base + OFF_WL);
    float* qf = (float*)(base + OFF_QF);
    float* kf = (float*)(base + OFF_KF);
    __nv_bfloat16* qhp = (__nv_bfloat16*)(base + OFF_QH);
    __nv_bfloat16* qlp = (__nv_bfloat16*)(base + OFF_QL);
    __nv_bfloat16* khp = (__nv_bfloat16*)(base + OFF_KH);
    __nv_bfloat16* klp = (__nv_bfloat16*)(base + OFF_KL);
    __nv_bfloat16* vth = (__nv_bfloat16*)(base + OFF_VTH);
    __nv_bfloat16* vtl = (__nv_bfloat16*)(base + OFF_VTL);
    __nv_bfloat16* aoh = (__nv_bfloat16*)(base + OFF_AOH);
    __nv_bfloat16* aol = (__nv_bfloat16*)(base + OFF_AOL);
    float* gqp = (float*)(base + OFF_QP);
    float* gkp = (float*)(base + OFF_KP);

    cudaFuncSetAttribute(gemm2<0>,
                         cudaFuncAttributeMaxDynamicSharedMemorySize, GEMM_SMEM);
    cudaFuncSetAttribute(gemm2<1>,
                         cudaFuncAttributeMaxDynamicSharedMemorySize, GEMM_SMEM);
    cudaFuncSetAttribute(gemm2<2>,
                         cudaFuncAttributeMaxDynamicSharedMemorySize, GEMM_SMEM);
    cudaFuncSetAttribute(attn_mma,
                         cudaFuncAttributeMaxDynamicSharedMemorySize, ATTN_SMEM);

    ln_split<<<NTOK, 256>>>(x, lng, lnb, xnh, xnl);
    wsplit<<<4096, 256>>>(Wq, Wk, Wv, Wo, wh, wl);

    gemm2<0><<<dim3(16, NTOK/128), 256, GEMM_SMEM>>>(
        xnh, xnl, wh, wl, nullptr, qf, kf, nullptr, nullptr);
    gemm2<2><<<dim3(8, NTOK/128), 256, GEMM_SMEM>>>(
        xnh, xnl, wh + 2*WPL, wl + 2*WPL, nullptr, nullptr, nullptr, vth, vtl);

    rope_kernel<<<BH*TT, 128>>>(qf, kf, hdr, qhp, qlp, khp, klp, gqp, gkp);

    attn_mma<<<dim3(TT/64, BH), 128, ATTN_SMEM>>>(qhp, qlp, khp, klp, vth, vtl,
                                                  gqp, gkp, hsc, aoh, aol);

    gemm2<1><<<dim3(8, NTOK/128), 256, GEMM_SMEM>>>(
        aoh, aol, wh + 3*WPL, wl + 3*WPL, x, out, nullptr, nullptr, nullptr);
}

// round 7
// speedup vs baseline: 2.6217x; 1.0151x over previous
#include <cuda_runtime.h>
#include <cuda_bf16.h>
#include <math.h>

// Problem constants
#define BB 4
#define TT 2048
#define CC 1024
#define HH 8
#define DD 128
#define NTOK (BB*TT)          // 8192
#define BH   (BB*HH)          // 32
#define WPL  ((size_t)CC*CC)  // weight plane elems

// ---------------------------------------------------------------------------
// Scratch
// ---------------------------------------------------------------------------
#define SZ_F32 ((size_t)NTOK*CC*4)
#define SZ_BF  ((size_t)NTOK*CC*2)
#define SZ_WPL ((size_t)4*CC*CC*2)
#define SZ_P   ((size_t)BH*TT*4)

#define OFF_XNH ((size_t)0)
#define OFF_XNL (OFF_XNH + SZ_BF)
#define OFF_WH  (OFF_XNL + SZ_BF)
#define OFF_WL  (OFF_WH + SZ_WPL)
#define OFF_QF  (OFF_WL + SZ_WPL)
#define OFF_KF  (OFF_QF + SZ_F32)
#define OFF_QH  (OFF_KF + SZ_F32)
#define OFF_QL  (OFF_QH + SZ_BF)
#define OFF_KH  (OFF_QL + SZ_BF)
#define OFF_KL  (OFF_KH + SZ_BF)
#define OFF_VTH (OFF_KL + SZ_BF)
#define OFF_VTL (OFF_VTH + SZ_BF)
#define OFF_AOH (OFF_VTL + SZ_BF)
#define OFF_AOL (OFF_AOH + SZ_BF)
#define OFF_QP  (OFF_AOL + SZ_BF)
#define OFF_KP  (OFF_QP + SZ_P)
#define SCRATCH_BYTES (OFF_KP + SZ_P)

__device__ __align__(256) unsigned char g_scratch[SCRATCH_BYTES];

// ---------------------------------------------------------------------------
// helpers
// ---------------------------------------------------------------------------
__device__ __forceinline__ void mma_bf16(float* c, const unsigned* a,
                                         unsigned b0, unsigned b1) {
    asm volatile(
        "mma.sync.aligned.m16n8k16.row.col.f32.bf16.bf16.f32 "
        "{%0,%1,%2,%3},{%4,%5,%6,%7},{%8,%9},{%0,%1,%2,%3};"
        : "+f"(c[0]), "+f"(c[1]), "+f"(c[2]), "+f"(c[3])
        : "r"(a[0]), "r"(a[1]), "r"(a[2]), "r"(a[3]), "r"(b0), "r"(b1));
}

__device__ __forceinline__ void ldsm_x4(unsigned r[4], unsigned addr) {
    asm volatile("ldmatrix.sync.aligned.m8n8.x4.shared.b16 {%0,%1,%2,%3}, [%4];"
        : "=r"(r[0]), "=r"(r[1]), "=r"(r[2]), "=r"(r[3]) : "r"(addr));
}

#define CP16(dst, src) \
    asm volatile("cp.async.cg.shared.global [%0], [%1], 16;" :: "r"(dst), "l"(src))
#define CP4(dst, src) \
    asm volatile("cp.async.ca.shared.global [%0], [%1], 4;" :: "r"(dst), "l"(src))
#define CP_COMMIT() asm volatile("cp.async.commit_group;")
#define CP_WAIT0()  asm volatile("cp.async.wait_group 0;")
#define CP_WAIT1()  asm volatile("cp.async.wait_group 1;")

__device__ __forceinline__ void split2(float a, float b, unsigned& hi, unsigned& lo) {
    __nv_bfloat162 h = __floats2bfloat162_rn(a, b);
    float la = a - __bfloat162float(h.x);
    float lb = b - __bfloat162float(h.y);
    __nv_bfloat162 l = __floats2bfloat162_rn(la, lb);
    hi = *(unsigned*)&h;
    lo = *(unsigned*)&l;
}

// ---------------------------------------------------------------------------
// LayerNorm -> bf16 hi/lo planes
// ---------------------------------------------------------------------------
__global__ __launch_bounds__(256) void ln_split(
    const float* __restrict__ x, const float* __restrict__ gam,
    const float* __restrict__ bet,
    __nv_bfloat16* __restrict__ xnh, __nv_bfloat16* __restrict__ xnl)
{
    int row = blockIdx.x;
    int t   = threadIdx.x;
    const float4* xr = (const float4*)(x + (size_t)row * CC);
    float4 v = xr[t];
    float s  = v.x + v.y + v.z + v.w;
    float ss = v.x*v.x + v.y*v.y + v.z*v.z + v.w*v.w;
    #pragma unroll
    for (int o = 16; o; o >>= 1) {
        s  += __shfl_xor_sync(0xffffffffu, s,  o);
        ss += __shfl_xor_sync(0xffffffffu, ss, o);
    }
    __shared__ float ws[8], wss[8];
    int wid = t >> 5;
    if ((t & 31) == 0) { ws[wid] = s; wss[wid] = ss; }
    __syncthreads();
    s = 0.f; ss = 0.f;
    #pragma unroll
    for (int i = 0; i < 8; i++) { s += ws[i]; ss += wss[i]; }
    float mu  = s * (1.f / CC);
    float var = ss * (1.f / CC) - mu * mu;
    float inv = rsqrtf(var + 1e-5f);
    float4 g4 = ((const float4*)gam)[t];
    float4 b4 = ((const float4*)bet)[t];
    float4 o;
    o.x = (v.x - mu) * inv * g4.x + b4.x;
    o.y = (v.y - mu) * inv * g4.y + b4.y;
    o.z = (v.z - mu) * inv * g4.z + b4.z;
    o.w = (v.w - mu) * inv * g4.w + b4.w;
    unsigned h0, l0, h1, l1;
    split2(o.x, o.y, h0, l0);
    split2(o.z, o.w, h1, l1);
    size_t off = (size_t)row * CC + t*4;
    *(uint2*)&xnh[off] = make_uint2(h0, h1);
    *(uint2*)&xnl[off] = make_uint2(l0, l1);
}

// ---------------------------------------------------------------------------
// Split 4 weight matrices into bf16 hi/lo planes: plane order Wq,Wk,Wv,Wo
// ---------------------------------------------------------------------------
__global__ __launch_bounds__(256) void wsplit(
    const float* __restrict__ w0, const float* __restrict__ w1,
    const float* __restrict__ w2, const float* __restrict__ w3,
    __nv_bfloat16* __restrict__ wh, __nv_bfloat16* __restrict__ wl)
{
    int mid = blockIdx.x >> 10;
    const float* src = (mid == 0) ? w0 : (mid == 1) ? w1 : (mid == 2) ? w2 : w3;
    size_t idx = ((size_t)(blockIdx.x & 1023))*1024 + threadIdx.x*4;
    float4 v = *(const float4*)(src + idx);
    unsigned h0, l0, h1, l1;
    split2(v.x, v.y, h0, l0);
    split2(v.z, v.w, h1, l1);
    size_t off = (size_t)mid*WPL + idx;
    *(uint2*)&wh[off] = make_uint2(h0, h1);
    *(uint2*)&wl[off] = make_uint2(l0, l1);
}

// ---------------------------------------------------------------------------
// 3xBF16 GEMM: cp.async double buffer + ldmatrix, 128x128x32, 2 CTA/SM.
// MODE 0: QKV fused (grid.x=24; sel = x>>3): sel 0/1 -> fp32 head-major
//         q/k buffers; sel 2 -> transposed bf16 hi/lo planes [B,H,D,T]
// MODE 1: out0 = X + acc (fp32 row-major)
// ---------------------------------------------------------------------------
#define GSTR 40
#define GEMM_SMEM (4*2*128*GSTR*2)   // 81920 B

template<int MODE>
__global__ __launch_bounds__(256, 2) void gemm2(
    const __nv_bfloat16* __restrict__ Ah, const __nv_bfloat16* __restrict__ Al,
    const __nv_bfloat16* __restrict__ Wh, const __nv_bfloat16* __restrict__ Wl,
    const float* __restrict__ X,
    float* __restrict__ out0, float* __restrict__ out1,
    __nv_bfloat16* __restrict__ oh, __nv_bfloat16* __restrict__ ol)
{
    extern __shared__ __nv_bfloat16 smb[];
    __nv_bfloat16* sAh = smb;
    __nv_bfloat16* sAl = sAh + 2*128*GSTR;
    __nv_bfloat16* sBh = sAl + 2*128*GSTR;
    __nv_bfloat16* sBl = sBh + 2*128*GSTR;
    unsigned uAh = (unsigned)__cvta_generic_to_shared(sAh);
    unsigned uAl = (unsigned)__cvta_generic_to_shared(sAl);
    unsigned uBh = (unsigned)__cvta_generic_to_shared(sBh);
    unsigned uBl = (unsigned)__cvta_generic_to_shared(sBl);

    int tid = threadIdx.x, lane = tid & 31, warp = tid >> 5;
    int g = lane >> 2, tig = lane & 3;
    int wm = warp >> 1, wn = warp & 1;
    int sel = (MODE == 0) ? (blockIdx.x >> 3) : 0;
    int n0 = (MODE == 0) ? ((blockIdx.x & 7) << 7) : (blockIdx.x << 7);
    int m0 = blockIdx.y << 7;
    const __nv_bfloat16* Wph = Wh + (size_t)sel*WPL;
    const __nv_bfloat16* Wpl = Wl + (size_t)sel*WPL;

    int lr = tid >> 2;
    int lc8 = (tid & 3) * 8;

    float acc[16][4];
    #pragma unroll
    for (int i = 0; i < 16; i++)
        #pragma unroll
        for (int j = 0; j < 4; j++) acc[i][j] = 0.f;

    auto load_stage = [&](int buf, int k0) {
        size_t a0 = (size_t)(m0 + lr) * CC + k0 + lc8;
        size_t b0 = (size_t)(n0 + lr) * CC + k0 + lc8;
        unsigned d0 = (unsigned)(((buf*128 + lr)*GSTR + lc8) * 2);
        unsigned d1 = (unsigned)(((buf*128 + lr + 64)*GSTR + lc8) * 2);
        CP16(uAh + d0, Ah + a0);  CP16(uAh + d1, Ah + a0 + (size_t)64*CC);
        CP16(uAl + d0, Al + a0);  CP16(uAl + d1, Al + a0 + (size_t)64*CC);
        CP16(uBh + d0, Wph + b0); CP16(uBh + d1, Wph + b0 + (size_t)64*CC);
        CP16(uBl + d0, Wpl + b0); CP16(uBl + d1, Wpl + b0 + (size_t)64*CC);
    };

    load_stage(0, 0);
    CP_COMMIT();
    CP_WAIT0();
    __syncthreads();

    int lra = ((lane >> 3) & 1) * 8 + (lane & 7);
    int lca = (lane >> 4) * 8;
    const int NIT = CC / 32;

    for (int it = 0; it < NIT; it++) {
        int buf = it & 1;
        if (it + 1 < NIT) { load_stage(buf ^ 1, (it + 1) * 32); CP_COMMIT(); }

        int sb = buf * 128;
        #pragma unroll
        for (int kk = 0; kk < 2; kk++) {
            int col = kk*16 + lca;
            unsigned ah[2][4], al2[2][4];
            #pragma unroll
            for (int mi = 0; mi < 2; mi++) {
                unsigned offA = (unsigned)(((sb + wm*32 + mi*16 + lra)*GSTR + col) * 2);
                ldsm_x4(ah[mi],  uAh + offA);
                ldsm_x4(al2[mi], uAl + offA);
            }
            #pragma unroll
            for (int ng = 0; ng < 4; ng++) {
                unsigned offB = (unsigned)(((sb + wn*64 + ng*16 + lra)*GSTR + col) * 2);
                unsigned b4h[4], b4l[4];
                ldsm_x4(b4h, uBh + offB);
                ldsm_x4(b4l, uBl + offB);
                #pragma unroll
                for (int hf = 0; hf < 2; hf++) {
                    int ni = ng*2 + hf;
                    unsigned bh0 = b4h[hf], bh1 = b4h[2 + hf];
                    unsigned bl0 = b4l[hf], bl1 = b4l[2 + hf];
                    #pragma unroll
                    for (int mi = 0; mi < 2; mi++) {
                        float* c = acc[mi*8 + ni];
                        mma_bf16(c, ah[mi],  bh0, bh1);
                        mma_bf16(c, ah[mi],  bl0, bl1);
                        mma_bf16(c, al2[mi], bh0, bh1);
                    }
                }
            }
        }
        if (it + 1 < NIT) CP_WAIT0();
        __syncthreads();
    }

    // epilogue
    #pragma unroll
    for (int mi = 0; mi < 2; mi++) {
        #pragma unroll
        for (int ni = 0; ni < 8; ni++) {
            const float* c = acc[mi*8 + ni];
            int r0 = m0 + wm*32 + mi*16 + g;
            int c0 = n0 + wn*64 + ni*8 + 2*tig;
            #pragma unroll
            for (int half = 0; half < 2; half++) {
                int r = r0 + half*8;
                float v0 = c[half*2], v1 = c[half*2 + 1];
                if (MODE == 1) {
                    size_t o = (size_t)r * CC + c0;
                    float2 xv = *(const float2*)&X[o];
                    *(float2*)&out0[o] = make_float2(xv.x + v0, xv.y + v1);
                } else if (sel < 2) {
                    int b = r >> 11, t = r & 2047, h = c0 >> 7, d = c0 & 127;
                    float* outp = sel ? out1 : out0;
                    *(float2*)&outp[(((size_t)(b*HH + h) * TT) + t) * DD + d] =
                        make_float2(v0, v1);
                } else {
                    int b = r >> 11, t = r & 2047, h = c0 >> 7, d = c0 & 127;
                    size_t rb = ((size_t)((b*HH + h)*DD + d)) * TT + t;
                    __nv_bfloat16 h0 = __float2bfloat16(v0);
                    __nv_bfloat16 h1 = __float2bfloat16(v1);
                    oh[rb]      = h0;
                    ol[rb]      = __float2bfloat16(v0 - __bfloat162float(h0));
                    oh[rb + TT] = h1;
                    ol[rb + TT] = __float2bfloat16(v1 - __bfloat162float(h1));
                }
            }
        }
    }
}

// ---------------------------------------------------------------------------
// RoPE on q,k: read fp32 head-major, write bf16 hi/lo planes + qp/kp
// ---------------------------------------------------------------------------
__global__ __launch_bounds__(128) void rope_kernel(
    const float* __restrict__ qf, const float* __restrict__ kf,
    const float* __restrict__ dirs,
    __nv_bfloat16* __restrict__ qh, __nv_bfloat16* __restrict__ ql,
    __nv_bfloat16* __restrict__ kh, __nv_bfloat16* __restrict__ kl,
    float* __restrict__ qp, float* __restrict__ kp)
{
    int idx = blockIdx.x;
    int t = idx & (TT - 1);
    int h = (idx >> 11) & (HH - 1);
    int tid = threadIdx.x;
    int i = tid & 63;
    bool isq = tid < 64;
    const float* src = (isq ? qf : kf) + (size_t)idx * DD;
    __nv_bfloat16* dh = isq ? qh : kh;
    __nv_bfloat16* dl = isq ? ql : kl;
    float x1 = src[i], x2 = src[i + 64];
    float inv = expf(-9.210340371976184f * (float)i * (1.f / 64.f));
    float ang = (float)t * inv;
    float sn, cs;
    sincosf(ang, &sn, &cs);
    float y1 = x1 * cs - x2 * sn;
    float y2 = x2 * cs + x1 * sn;
    size_t o = (size_t)idx * DD;
    __nv_bfloat16 h1 = __float2bfloat16(y1);
    __nv_bfloat16 h2 = __float2bfloat16(y2);
    dh[o + i]      = h1;
    dl[o + i]      = __float2bfloat16(y1 - __bfloat162float(h1));
    dh[o + i + 64] = h2;
    dl[o + i + 64] = __float2bfloat16(y2 - __bfloat162float(h2));
    __shared__ float red[6];
    if (i < 3) red[(tid >> 6) * 3 + i] = y1 * dirs[h * 3 + i];
    __syncthreads();
    if (tid == 0)  qp[idx] = red[0] + red[1] + red[2];
    if (tid == 64) kp[idx] = red[3] + red[4] + red[5];
}

// ---------------------------------------------------------------------------
// Two-pass dual-softmax flash attention v2.
// Br=128 (256 thr, 8 warps, warp owns 16 rows), Bc=64.
// cp.async double-buffered K/V/kp tiles; 3xBF16 MMA + ldmatrix.
// ---------------------------------------------------------------------------
#define KSTR 136
#define VSTR 72
#define Q_ELE (2*128*KSTR)
#define K_ELE (2*2*64*KSTR)          // 2 stages x (hi/lo) x 64 rows
#define V_ELE (2*2*128*VSTR)         // 2 stages x (hi/lo) x 128 rows
#define ATTN_SMEM ((Q_ELE + K_ELE + V_ELE)*2 + (2*64 + 2*128)*4)  // 214528 B
#define SCALE 0.08838834764831845f

__global__ __launch_bounds__(256, 1) void attn_mma(
    const __nv_bfloat16* __restrict__ qh, const __nv_bfloat16* __restrict__ ql,
    const __nv_bfloat16* __restrict__ kh, const __nv_bfloat16* __restrict__ kl,
    const __nv_bfloat16* __restrict__ vth, const __nv_bfloat16* __restrict__ vtl,
    const float* __restrict__ qp, const float* __restrict__ kp,
    const float* __restrict__ hsc,
    __nv_bfloat16* __restrict__ aoh, __nv_bfloat16* __restrict__ aol)
{
    extern __shared__ unsigned char sma[];
    __nv_bfloat16* Qh = (__nv_bfloat16*)sma;            // [128][KSTR]
    __nv_bfloat16* Kb = Qh + Q_ELE;                     // stages
    __nv_bfloat16* Vb = Kb + K_ELE;
    float* kps = (float*)(Vb + V_ELE);                  // [2][64]
    float* ls  = kps + 128;                             // [128]
    float* lgs = ls + 128;                              // [128]

    unsigned uQ = (unsigned)__cvta_generic_to_shared(Qh);
    unsigned uK = (unsigned)__cvta_generic_to_shared(Kb);
    unsigned uV = (unsigned)__cvta_generic_to_shared(Vb);
    unsigned uKps = (unsigned)__cvta_generic_to_shared(kps);

    int bh = blockIdx.y;
    int b = bh >> 3, h = bh & 7;
    int q0 = (gridDim.x - 1 - blockIdx.x) << 7;   // big tiles first
    size_t tb = (size_t)bh * TT;
    int tid = threadIdx.x;
    int lane = tid & 31, warp = tid >> 5;
    int g = lane >> 2, tig = lane & 3;
    int r0loc = warp*16 + g, r1loc = r0loc + 8;
    int lra = ((lane >> 3) & 1) * 8 + (lane & 7);
    int lca = (lane >> 4) * 8;

    // load Q tiles (hi/lo), 128 rows
    {
        const __nv_bfloat16* qhg = qh + (tb + q0) * DD;
        const __nv_bfloat16* qlg = ql + (tb + q0) * DD;
        for (int i = tid; i < 2048; i += 256) {
            int r = i >> 4, c = (i & 15) << 3;
            *(uint4*)&Qh[r*KSTR + c]              = *(const uint4*)&qhg[r*DD + c];
            *(uint4*)&Qh[(128 + r)*KSTR + c]      = *(const uint4*)&qlg[r*DD + c];
        }
    }
    float hs  = hsc[h];
    float qp0 = qp[tb + q0 + r0loc];
    float qp1 = qp[tb + q0 + r1loc];
    int ntiles = (q0 >> 6) + 2;

    auto prefetchK = [&](int st, int n0) {
        const __nv_bfloat16* khg = kh + (tb + n0) * DD;
        const __nv_bfloat16* klg = kl + (tb + n0) * DD;
        for (int i = tid; i < 1024; i += 256) {
            int r = i >> 4, c = (i & 15) << 3;
            CP16(uK + (unsigned)(((st*128 + r)*KSTR + c) * 2),      khg + r*DD + c);
            CP16(uK + (unsigned)(((st*128 + 64 + r)*KSTR + c) * 2), klg + r*DD + c);
        }
        if (tid < 64) CP4(uKps + (unsigned)((st*64 + tid) * 4), kp + tb + n0 + tid);
    };
    auto prefetchV = [&](int st, int n0) {
        const __nv_bfloat16* vhg = vth + (size_t)bh*DD*TT + n0;
        const __nv_bfloat16* vlg = vtl + (size_t)bh*DD*TT + n0;
        for (int i = tid; i < 1024; i += 256) {
            int d = i >> 3, c = (i & 7) << 3;
            CP16(uV + (unsigned)(((st*256 + d)*VSTR + c) * 2),       vhg + (size_t)d*TT + c);
            CP16(uV + (unsigned)(((st*256 + 128 + d)*VSTR + c) * 2), vlg + (size_t)d*TT + c);
        }
    };

    auto computeS = [&](int st, float s[8][4]) {
        #pragma unroll
        for (int i = 0; i < 8; i++)
            #pragma unroll
            for (int j = 0; j < 4; j++) s[i][j] = 0.f;
        #pragma unroll
        for (int kk = 0; kk < 8; kk++) {
            int col = kk*16 + lca;
            unsigned qoff = (unsigned)(((warp*16 + lra)*KSTR + col) * 2);
            unsigned qa[4], qb[4];
            ldsm_x4(qa, uQ + qoff);
            ldsm_x4(qb, uQ + qoff + (unsigned)(128*KSTR*2));
            #pragma unroll
            for (int ng = 0; ng < 4; ng++) {
                unsigned koff = (unsigned)(((st*128 + ng*16 + lra)*KSTR + col) * 2);
                unsigned kh4[4], kl4[4];
                ldsm_x4(kh4, uK + koff);
                ldsm_x4(kl4, uK + koff + (unsigned)(64*KSTR*2));
                #pragma unroll
                for (int hf = 0; hf < 2; hf++) {
                    int ni = ng*2 + hf;
                    mma_bf16(s[ni], qa, kh4[hf], kh4[2 + hf]);
                    mma_bf16(s[ni], qa, kl4[hf], kl4[2 + hf]);
                    mma_bf16(s[ni], qb, kh4[hf], kh4[2 + hf]);
                }
            }
        }
    };

    // ---------------- PASS 1: row sums ----------------
    float l0 = 0.f, l1 = 0.f, lg0 = 0.f, lg1 = 0.f;
    prefetchK(0, 0);
    CP_COMMIT();
    for (int it = 0; it < ntiles; it++) {
        int st = it & 1;
        int n0 = it << 6;
        if (it + 1 < ntiles) { prefetchK(st ^ 1, (it + 1) << 6); CP_COMMIT(); CP_WAIT1(); }
        else                 { CP_WAIT0(); }
        __syncthreads();

        float s[8][4];
        computeS(st, s);
        int relq = q0 - n0;
        const float* kpst = kps + st*64;
        #pragma unroll
        for (int ni = 0; ni < 8; ni++) {
            #pragma unroll
            for (int j = 0; j < 4; j++) {
                int cl = ni*8 + 2*tig + (j & 1);
                int rl = (j < 2) ? r0loc : r1loc;
                bool ok = (cl - rl <= relq);
                float e  = ok ? __expf(s[ni][j] * SCALE) : 0.f;
                float ge = ok ? __expf(((j < 2) ? qp0 : qp1) * kpst[cl]) : 0.f;
                if (j < 2) { l0 += e; lg0 += ge; }
                else       { l1 += e; lg1 += ge; }
            }
        }
        __syncthreads();
    }
    #pragma unroll
    for (int o = 1; o <= 2; o <<= 1) {
        l0  += __shfl_xor_sync(0xffffffffu, l0,  o);
        l1  += __shfl_xor_sync(0xffffffffu, l1,  o);
        lg0 += __shfl_xor_sync(0xffffffffu, lg0, o);
        lg1 += __shfl_xor_sync(0xffffffffu, lg1, o);
    }
    if (tig == 0) {
        ls[r0loc] = l0;  lgs[r0loc] = lg0;
        ls[r1loc] = l1;  lgs[r1loc] = lg1;
    }
    __syncthreads();
    float c1a = (1.f - hs) / ls[r0loc], c2a = hs / lgs[r0loc];
    float c1b = (1.f - hs) / ls[r1loc], c2b = hs / lgs[r1loc];

    // ---------------- PASS 2: weighted PV ----------------
    float O[16][4];
    #pragma unroll
    for (int i = 0; i < 16; i++)
        #pragma unroll
        for (int j = 0; j < 4; j++) O[i][j] = 0.f;

    prefetchK(0, 0);
    prefetchV(0, 0);
    CP_COMMIT();
    for (int it = 0; it < ntiles; it++) {
        int st = it & 1;
        int n0 = it << 6;
        if (it + 1 < ntiles) {
            prefetchK(st ^ 1, (it + 1) << 6);
            prefetchV(st ^ 1, (it + 1) << 6);
            CP_COMMIT(); CP_WAIT1();
        } else { CP_WAIT0(); }
        __syncthreads();

        float s[8][4];
        computeS(st, s);
        int relq = q0 - n0;
        const float* kpst = kps + st*64;
        #pragma unroll
        for (int ni = 0; ni < 8; ni++) {
            #pragma unroll
            for (int j = 0; j < 4; j++) {
                int cl = ni*8 + 2*tig + (j & 1);
                int rl = (j < 2) ? r0loc : r1loc;
                bool ok = (cl - rl <= relq);
                float e  = __expf(s[ni][j] * SCALE);
                float ge = __expf(((j < 2) ? qp0 : qp1) * kpst[cl]);
                float wv = ((j < 2) ? c1a : c1b) * e + ((j < 2) ? c2a : c2b) * ge;
                s[ni][j] = ok ? wv : 0.f;
            }
        }
        unsigned ph[4][4], pl[4][4];
        #pragma unroll
        for (int kc = 0; kc < 4; kc++) {
            split2(s[2*kc][0],   s[2*kc][1],   ph[kc][0], pl[kc][0]);
            split2(s[2*kc][2],   s[2*kc][3],   ph[kc][1], pl[kc][1]);
            split2(s[2*kc+1][0], s[2*kc+1][1], ph[kc][2], pl[kc][2]);
            split2(s[2*kc+1][2], s[2*kc+1][3], ph[kc][3], pl[kc][3]);
        }
        #pragma unroll
        for (int ndg = 0; ndg < 8; ndg++) {
            #pragma unroll
            for (int kc = 0; kc < 4; kc++) {
                unsigned voff = (unsigned)(((st*256 + ndg*16 + lra)*VSTR + kc*16 + lca) * 2);
                unsigned vh4[4], vl4[4];
                ldsm_x4(vh4, uV + voff);
                ldsm_x4(vl4, uV + voff + (unsigned)(128*VSTR*2));
                #pragma unroll
                for (int hf = 0; hf < 2; hf++) {
                    int nd = ndg*2 + hf;
                    mma_bf16(O[nd], ph[kc], vh4[hf], vh4[2 + hf]);
                    mma_bf16(O[nd], ph[kc], vl4[hf], vl4[2 + hf]);
                    mma_bf16(O[nd], pl[kc], vh4[hf], vh4[2 + hf]);
                }
            }
        }
        __syncthreads();
    }

    // epilogue: write bf16 hi/lo planes for the Wo GEMM
    size_t orow0 = (size_t)(b*TT + q0 + r0loc) * CC + h*DD;
    size_t orow1 = (size_t)(b*TT + q0 + r1loc) * CC + h*DD;
    #pragma unroll
    for (int nd = 0; nd < 16; nd++) {
        int d0 = nd*8 + 2*tig;
        unsigned hh, ll;
        split2(O[nd][0], O[nd][1], hh, ll);
        *(unsigned*)&aoh[orow0 + d0] = hh;
        *(unsigned*)&aol[orow0 + d0] = ll;
        split2(O[nd][2], O[nd][3], hh, ll);
        *(unsigned*)&aoh[orow1 + d0] = hh;
        *(unsigned*)&aol[orow1 + d0] = ll;
    }
}

// ---------------------------------------------------------------------------
// Launcher
// ---------------------------------------------------------------------------
extern "C" void kernel_launch(void* const* d_in, const int* in_sizes, int n_in,
                              void* d_out, int out_size)
{
    const float* x   = (const float*)d_in[0];
    const float* Wq  = (const float*)d_in[1];
    const float* Wk  = (const float*)d_in[2];
    const float* Wv  = (const float*)d_in[3];
    const float* Wo  = (const float*)d_in[4];
    const float* lng = (const float*)d_in[5];
    const float* lnb = (const float*)d_in[6];
    const float* hsc = (const float*)d_in[7];
    const float* hdr = (const float*)d_in[8];
    float* out = (float*)d_out;

    unsigned char* base = nullptr;
    cudaGetSymbolAddress((void**)&base, g_scratch);
    __nv_bfloat16* xnh = (__nv_bfloat16*)(base + OFF_XNH);
    __nv_bfloat16* xnl = (__nv_bfloat16*)(base + OFF_XNL);
    __nv_bfloat16* wh  = (__nv_bfloat16*)(base + OFF_WH);
    __nv_bfloat16* wl  = (__nv_bfloat16*)(base + OFF_WL);
    float* qf = (float*)(base + OFF_QF);
    float* kf = (float*)(base + OFF_KF);
    __nv_bfloat16* qhp = (__nv_bfloat16*)(base + OFF_QH);
    __nv_bfloat16* qlp = (__nv_bfloat16*)(base + OFF_QL);
    __nv_bfloat16* khp = (__nv_bfloat16*)(base + OFF_KH);
    __nv_bfloat16* klp = (__nv_bfloat16*)(base + OFF_KL);
    __nv_bfloat16* vth = (__nv_bfloat16*)(base + OFF_VTH);
    __nv_bfloat16* vtl = (__nv_bfloat16*)(base + OFF_VTL);
    __nv_bfloat16* aoh = (__nv_bfloat16*)(base + OFF_AOH);
    __nv_bfloat16* aol = (__nv_bfloat16*)(base + OFF_AOL);
    float* gqp = (float*)(base + OFF_QP);
    float* gkp = (float*)(base + OFF_KP);

    cudaFuncSetAttribute(gemm2<0>,
                         cudaFuncAttributeMaxDynamicSharedMemorySize, GEMM_SMEM);
    cudaFuncSetAttribute(gemm2<1>,
                         cudaFuncAttributeMaxDynamicSharedMemorySize, GEMM_SMEM);
    cudaFuncSetAttribute(attn_mma,
                         cudaFuncAttributeMaxDynamicSharedMemorySize, ATTN_SMEM);

    ln_split<<<NTOK, 256>>>(x, lng, lnb, xnh, xnl);
    wsplit<<<4096, 256>>>(Wq, Wk, Wv, Wo, wh, wl);

    gemm2<0><<<dim3(24, NTOK/128), 256, GEMM_SMEM>>>(
        xnh, xnl, wh, wl, nullptr, qf, kf, vth, vtl);

    rope_kernel<<<BH*TT, 128>>>(qf, kf, hdr, qhp, qlp, khp, klp, gqp, gkp);

    attn_mma<<<dim3(TT/128, BH), 256, ATTN_SMEM>>>(qhp, qlp, khp, klp, vth, vtl,
                                                   gqp, gkp, hsc, aoh, aol);

    gemm2<1><<<dim3(8, NTOK/128), 256, GEMM_SMEM>>>(
        aoh, aol, wh + 3*WPL, wl + 3*WPL, x, out, nullptr, nullptr, nullptr);
}

// round 8
// speedup vs baseline: 2.6228x; 1.0004x over previous
#include <cuda_runtime.h>
#include <cuda_bf16.h>
#include <math.h>

// Problem constants
#define BB 4
#define TT 2048
#define CC 1024
#define HH 8
#define DD 128
#define NTOK (BB*TT)          // 8192
#define BH   (BB*HH)          // 32
#define WPL  ((size_t)CC*CC)  // weight plane elems

// ---------------------------------------------------------------------------
// Scratch
// ---------------------------------------------------------------------------
#define SZ_F32 ((size_t)NTOK*CC*4)
#define SZ_BF  ((size_t)NTOK*CC*2)
#define SZ_WPL ((size_t)4*CC*CC*2)
#define SZ_P   ((size_t)BH*TT*4)

#define OFF_XNH ((size_t)0)
#define OFF_XNL (OFF_XNH + SZ_BF)
#define OFF_WH  (OFF_XNL + SZ_BF)
#define OFF_WL  (OFF_WH + SZ_WPL)
#define OFF_QF  (OFF_WL + SZ_WPL)
#define OFF_KF  (OFF_QF + SZ_F32)
#define OFF_QH  (OFF_KF + SZ_F32)
#define OFF_QL  (OFF_QH + SZ_BF)
#define OFF_KH  (OFF_QL + SZ_BF)
#define OFF_KL  (OFF_KH + SZ_BF)
#define OFF_VTH (OFF_KL + SZ_BF)
#define OFF_VTL (OFF_VTH + SZ_BF)
#define OFF_AOH (OFF_VTL + SZ_BF)
#define OFF_AOL (OFF_AOH + SZ_BF)
#define OFF_QP  (OFF_AOL + SZ_BF)
#define OFF_KP  (OFF_QP + SZ_P)
#define SCRATCH_BYTES (OFF_KP + SZ_P)

__device__ __align__(256) unsigned char g_scratch[SCRATCH_BYTES];

// ---------------------------------------------------------------------------
// helpers
// ---------------------------------------------------------------------------
__device__ __forceinline__ void mma_bf16(float* c, const unsigned* a,
                                         unsigned b0, unsigned b1) {
    asm volatile(
        "mma.sync.aligned.m16n8k16.row.col.f32.bf16.bf16.f32 "
        "{%0,%1,%2,%3},{%4,%5,%6,%7},{%8,%9},{%0,%1,%2,%3};"
        : "+f"(c[0]), "+f"(c[1]), "+f"(c[2]), "+f"(c[3])
        : "r"(a[0]), "r"(a[1]), "r"(a[2]), "r"(a[3]), "r"(b0), "r"(b1));
}

__device__ __forceinline__ void ldsm_x4(unsigned r[4], unsigned addr) {
    asm volatile("ldmatrix.sync.aligned.m8n8.x4.shared.b16 {%0,%1,%2,%3}, [%4];"
        : "=r"(r[0]), "=r"(r[1]), "=r"(r[2]), "=r"(r[3]) : "r"(addr));
}

#define CP16(dst, src) \
    asm volatile("cp.async.cg.shared.global [%0], [%1], 16;" :: "r"(dst), "l"(src))
#define CP4(dst, src) \
    asm volatile("cp.async.ca.shared.global [%0], [%1], 4;" :: "r"(dst), "l"(src))
#define CP_COMMIT() asm volatile("cp.async.commit_group;")
#define CP_WAIT0()  asm volatile("cp.async.wait_group 0;")
#define CP_WAIT1()  asm volatile("cp.async.wait_group 1;")

__device__ __forceinline__ void split2(float a, float b, unsigned& hi, unsigned& lo) {
    __nv_bfloat162 h = __floats2bfloat162_rn(a, b);
    float la = a - __bfloat162float(h.x);
    float lb = b - __bfloat162float(h.y);
    __nv_bfloat162 l = __floats2bfloat162_rn(la, lb);
    hi = *(unsigned*)&h;
    lo = *(unsigned*)&l;
}

// ---------------------------------------------------------------------------
// LayerNorm -> bf16 hi/lo planes
// ---------------------------------------------------------------------------
__global__ __launch_bounds__(256) void ln_split(
    const float* __restrict__ x, const float* __restrict__ gam,
    const float* __restrict__ bet,
    __nv_bfloat16* __restrict__ xnh, __nv_bfloat16* __restrict__ xnl)
{
    int row = blockIdx.x;
    int t   = threadIdx.x;
    const float4* xr = (const float4*)(x + (size_t)row * CC);
    float4 v = xr[t];
    float s  = v.x + v.y + v.z + v.w;
    float ss = v.x*v.x + v.y*v.y + v.z*v.z + v.w*v.w;
    #pragma unroll
    for (int o = 16; o; o >>= 1) {
        s  += __shfl_xor_sync(0xffffffffu, s,  o);
        ss += __shfl_xor_sync(0xffffffffu, ss, o);
    }
    __shared__ float ws[8], wss[8];
    int wid = t >> 5;
    if ((t & 31) == 0) { ws[wid] = s; wss[wid] = ss; }
    __syncthreads();
    s = 0.f; ss = 0.f;
    #pragma unroll
    for (int i = 0; i < 8; i++) { s += ws[i]; ss += wss[i]; }
    float mu  = s * (1.f / CC);
    float var = ss * (1.f / CC) - mu * mu;
    float inv = rsqrtf(var + 1e-5f);
    float4 g4 = ((const float4*)gam)[t];
    float4 b4 = ((const float4*)bet)[t];
    float4 o;
    o.x = (v.x - mu) * inv * g4.x + b4.x;
    o.y = (v.y - mu) * inv * g4.y + b4.y;
    o.z = (v.z - mu) * inv * g4.z + b4.z;
    o.w = (v.w - mu) * inv * g4.w + b4.w;
    unsigned h0, l0, h1, l1;
    split2(o.x, o.y, h0, l0);
    split2(o.z, o.w, h1, l1);
    size_t off = (size_t)row * CC + t*4;
    *(uint2*)&xnh[off] = make_uint2(h0, h1);
    *(uint2*)&xnl[off] = make_uint2(l0, l1);
}

// ---------------------------------------------------------------------------
// Split 4 weight matrices into bf16 hi/lo planes: plane order Wq,Wk,Wv,Wo
// ---------------------------------------------------------------------------
__global__ __launch_bounds__(256) void wsplit(
    const float* __restrict__ w0, const float* __restrict__ w1,
    const float* __restrict__ w2, const float* __restrict__ w3,
    __nv_bfloat16* __restrict__ wh, __nv_bfloat16* __restrict__ wl)
{
    int mid = blockIdx.x >> 10;
    const float* src = (mid == 0) ? w0 : (mid == 1) ? w1 : (mid == 2) ? w2 : w3;
    size_t idx = ((size_t)(blockIdx.x & 1023))*1024 + threadIdx.x*4;
    float4 v = *(const float4*)(src + idx);
    unsigned h0, l0, h1, l1;
    split2(v.x, v.y, h0, l0);
    split2(v.z, v.w, h1, l1);
    size_t off = (size_t)mid*WPL + idx;
    *(uint2*)&wh[off] = make_uint2(h0, h1);
    *(uint2*)&wl[off] = make_uint2(l0, l1);
}

// ---------------------------------------------------------------------------
// 3xBF16 GEMM: cp.async double buffer + ldmatrix, 128x128x32, 2 CTA/SM.
// MODE 0: QKV fused (grid.x=24; sel = x>>3): sel 0/1 -> fp32 head-major
//         q/k buffers; sel 2 -> transposed bf16 hi/lo planes [B,H,D,T]
// MODE 1: out0 = X + acc (fp32 row-major)
// ---------------------------------------------------------------------------
#define GSTR 40
#define GEMM_SMEM (4*2*128*GSTR*2)   // 81920 B

template<int MODE>
__global__ __launch_bounds__(256, 2) void gemm2(
    const __nv_bfloat16* __restrict__ Ah, const __nv_bfloat16* __restrict__ Al,
    const __nv_bfloat16* __restrict__ Wh, const __nv_bfloat16* __restrict__ Wl,
    const float* __restrict__ X,
    float* __restrict__ out0, float* __restrict__ out1,
    __nv_bfloat16* __restrict__ oh, __nv_bfloat16* __restrict__ ol)
{
    extern __shared__ __nv_bfloat16 smb[];
    __nv_bfloat16* sAh = smb;
    __nv_bfloat16* sAl = sAh + 2*128*GSTR;
    __nv_bfloat16* sBh = sAl + 2*128*GSTR;
    __nv_bfloat16* sBl = sBh + 2*128*GSTR;
    unsigned uAh = (unsigned)__cvta_generic_to_shared(sAh);
    unsigned uAl = (unsigned)__cvta_generic_to_shared(sAl);
    unsigned uBh = (unsigned)__cvta_generic_to_shared(sBh);
    unsigned uBl = (unsigned)__cvta_generic_to_shared(sBl);

    int tid = threadIdx.x, lane = tid & 31, warp = tid >> 5;
    int g = lane >> 2, tig = lane & 3;
    int wm = warp >> 1, wn = warp & 1;
    int sel = (MODE == 0) ? (blockIdx.x >> 3) : 0;
    int n0 = (MODE == 0) ? ((blockIdx.x & 7) << 7) : (blockIdx.x << 7);
    int m0 = blockIdx.y << 7;
    const __nv_bfloat16* Wph = Wh + (size_t)sel*WPL;
    const __nv_bfloat16* Wpl = Wl + (size_t)sel*WPL;

    int lr = tid >> 2;
    int lc8 = (tid & 3) * 8;

    float acc[16][4];
    #pragma unroll
    for (int i = 0; i < 16; i++)
        #pragma unroll
        for (int j = 0; j < 4; j++) acc[i][j] = 0.f;

    auto load_stage = [&](int buf, int k0) {
        size_t a0 = (size_t)(m0 + lr) * CC + k0 + lc8;
        size_t b0 = (size_t)(n0 + lr) * CC + k0 + lc8;
        unsigned d0 = (unsigned)(((buf*128 + lr)*GSTR + lc8) * 2);
        unsigned d1 = (unsigned)(((buf*128 + lr + 64)*GSTR + lc8) * 2);
        CP16(uAh + d0, Ah + a0);  CP16(uAh + d1, Ah + a0 + (size_t)64*CC);
        CP16(uAl + d0, Al + a0);  CP16(uAl + d1, Al + a0 + (size_t)64*CC);
        CP16(uBh + d0, Wph + b0); CP16(uBh + d1, Wph + b0 + (size_t)64*CC);
        CP16(uBl + d0, Wpl + b0); CP16(uBl + d1, Wpl + b0 + (size_t)64*CC);
    };

    load_stage(0, 0);
    CP_COMMIT();
    CP_WAIT0();
    __syncthreads();

    int lra = ((lane >> 3) & 1) * 8 + (lane & 7);
    int lca = (lane >> 4) * 8;
    const int NIT = CC / 32;

    for (int it = 0; it < NIT; it++) {
        int buf = it & 1;
        if (it + 1 < NIT) { load_stage(buf ^ 1, (it + 1) * 32); CP_COMMIT(); }

        int sb = buf * 128;
        #pragma unroll
        for (int kk = 0; kk < 2; kk++) {
            int col = kk*16 + lca;
            unsigned ah[2][4], al2[2][4];
            #pragma unroll
            for (int mi = 0; mi < 2; mi++) {
                unsigned offA = (unsigned)(((sb + wm*32 + mi*16 + lra)*GSTR + col) * 2);
                ldsm_x4(ah[mi],  uAh + offA);
                ldsm_x4(al2[mi], uAl + offA);
            }
            #pragma unroll
            for (int ng = 0; ng < 4; ng++) {
                unsigned offB = (unsigned)(((sb + wn*64 + ng*16 + lra)*GSTR + col) * 2);
                unsigned b4h[4], b4l[4];
                ldsm_x4(b4h, uBh + offB);
                ldsm_x4(b4l, uBl + offB);
                #pragma unroll
                for (int hf = 0; hf < 2; hf++) {
                    int ni = ng*2 + hf;
                    unsigned bh0 = b4h[hf], bh1 = b4h[2 + hf];
                    unsigned bl0 = b4l[hf], bl1 = b4l[2 + hf];
                    #pragma unroll
                    for (int mi = 0; mi < 2; mi++) {
                        float* c = acc[mi*8 + ni];
                        mma_bf16(c, ah[mi],  bh0, bh1);
                        mma_bf16(c, ah[mi],  bl0, bl1);
                        mma_bf16(c, al2[mi], bh0, bh1);
                    }
                }
            }
        }
        if (it + 1 < NIT) CP_WAIT0();
        __syncthreads();
    }

    // epilogue
    #pragma unroll
    for (int mi = 0; mi < 2; mi++) {
        #pragma unroll
        for (int ni = 0; ni < 8; ni++) {
            const float* c = acc[mi*8 + ni];
            int r0 = m0 + wm*32 + mi*16 + g;
            int c0 = n0 + wn*64 + ni*8 + 2*tig;
            #pragma unroll
            for (int half = 0; half < 2; half++) {
                int r = r0 + half*8;
                float v0 = c[half*2], v1 = c[half*2 + 1];
                if (MODE == 1) {
                    size_t o = (size_t)r * CC + c0;
                    float2 xv = *(const float2*)&X[o];
                    *(float2*)&out0[o] = make_float2(xv.x + v0, xv.y + v1);
                } else if (sel < 2) {
                    int b = r >> 11, t = r & 2047, h = c0 >> 7, d = c0 & 127;
                    float* outp = sel ? out1 : out0;
                    *(float2*)&outp[(((size_t)(b*HH + h) * TT) + t) * DD + d] =
                        make_float2(v0, v1);
                } else {
                    int b = r >> 11, t = r & 2047, h = c0 >> 7, d = c0 & 127;
                    size_t rb = ((size_t)((b*HH + h)*DD + d)) * TT + t;
                    __nv_bfloat16 h0 = __float2bfloat16(v0);
                    __nv_bfloat16 h1 = __float2bfloat16(v1);
                    oh[rb]      = h0;
                    ol[rb]      = __float2bfloat16(v0 - __bfloat162float(h0));
                    oh[rb + TT] = h1;
                    ol[rb + TT] = __float2bfloat16(v1 - __bfloat162float(h1));
                }
            }
        }
    }
}

// ---------------------------------------------------------------------------
// RoPE on q,k: read fp32 head-major, write bf16 hi/lo planes + qp/kp
// ---------------------------------------------------------------------------
__global__ __launch_bounds__(128) void rope_kernel(
    const float* __restrict__ qf, const float* __restrict__ kf,
    const float* __restrict__ dirs,
    __nv_bfloat16* __restrict__ qh, __nv_bfloat16* __restrict__ ql,
    __nv_bfloat16* __restrict__ kh, __nv_bfloat16* __restrict__ kl,
    float* __restrict__ qp, float* __restrict__ kp)
{
    int idx = blockIdx.x;
    int t = idx & (TT - 1);
    int h = (idx >> 11) & (HH - 1);
    int tid = threadIdx.x;
    int i = tid & 63;
    bool isq = tid < 64;
    const float* src = (isq ? qf : kf) + (size_t)idx * DD;
    __nv_bfloat16* dh = isq ? qh : kh;
    __nv_bfloat16* dl = isq ? ql : kl;
    float x1 = src[i], x2 = src[i + 64];
    float inv = expf(-9.210340371976184f * (float)i * (1.f / 64.f));
    float ang = (float)t * inv;
    float sn, cs;
    sincosf(ang, &sn, &cs);
    float y1 = x1 * cs - x2 * sn;
    float y2 = x2 * cs + x1 * sn;
    size_t o = (size_t)idx * DD;
    __nv_bfloat16 h1 = __float2bfloat16(y1);
    __nv_bfloat16 h2 = __float2bfloat16(y2);
    dh[o + i]      = h1;
    dl[o + i]      = __float2bfloat16(y1 - __bfloat162float(h1));
    dh[o + i + 64] = h2;
    dl[o + i + 64] = __float2bfloat16(y2 - __bfloat162float(h2));
    __shared__ float red[6];
    if (i < 3) red[(tid >> 6) * 3 + i] = y1 * dirs[h * 3 + i];
    __syncthreads();
    if (tid == 0)  qp[idx] = red[0] + red[1] + red[2];
    if (tid == 64) kp[idx] = red[3] + red[4] + red[5];
}

// ---------------------------------------------------------------------------
// Two-pass dual-softmax flash attention v2.
// Br=128 (256 thr, 8 warps, warp owns 16 rows), Bc=64.
// cp.async double-buffered K/V/kp tiles; 3xBF16 MMA + ldmatrix.
// ---------------------------------------------------------------------------
#define KSTR 136
#define VSTR 72
#define Q_ELE (2*128*KSTR)
#define K_ELE (2*2*64*KSTR)          // 2 stages x (hi/lo) x 64 rows
#define V_ELE (2*2*128*VSTR)         // 2 stages x (hi/lo) x 128 rows
#define ATTN_SMEM ((Q_ELE + K_ELE + V_ELE)*2 + (2*64 + 2*128)*4)  // 214528 B
#define SCALE 0.08838834764831845f

__global__ __launch_bounds__(256, 1) void attn_mma(
    const __nv_bfloat16* __restrict__ qh, const __nv_bfloat16* __restrict__ ql,
    const __nv_bfloat16* __restrict__ kh, const __nv_bfloat16* __restrict__ kl,
    const __nv_bfloat16* __restrict__ vth, const __nv_bfloat16* __restrict__ vtl,
    const float* __restrict__ qp, const float* __restrict__ kp,
    const float* __restrict__ hsc,
    __nv_bfloat16* __restrict__ aoh, __nv_bfloat16* __restrict__ aol)
{
    extern __shared__ unsigned char sma[];
    __nv_bfloat16* Qh = (__nv_bfloat16*)sma;            // [128][KSTR]
    __nv_bfloat16* Kb = Qh + Q_ELE;                     // stages
    __nv_bfloat16* Vb = Kb + K_ELE;
    float* kps = (float*)(Vb + V_ELE);                  // [2][64]
    float* ls  = kps + 128;                             // [128]
    float* lgs = ls + 128;                              // [128]

    unsigned uQ = (unsigned)__cvta_generic_to_shared(Qh);
    unsigned uK = (unsigned)__cvta_generic_to_shared(Kb);
    unsigned uV = (unsigned)__cvta_generic_to_shared(Vb);
    unsigned uKps = (unsigned)__cvta_generic_to_shared(kps);

    int bh = blockIdx.y;
    int b = bh >> 3, h = bh & 7;
    int q0 = (gridDim.x - 1 - blockIdx.x) << 7;   // big tiles first
    size_t tb = (size_t)bh * TT;
    int tid = threadIdx.x;
    int lane = tid & 31, warp = tid >> 5;
    int g = lane >> 2, tig = lane & 3;
    int r0loc = warp*16 + g, r1loc = r0loc + 8;
    int lra = ((lane >> 3) & 1) * 8 + (lane & 7);
    int lca = (lane >> 4) * 8;

    // load Q tiles (hi/lo), 128 rows
    {
        const __nv_bfloat16* qhg = qh + (tb + q0) * DD;
        const __nv_bfloat16* qlg = ql + (tb + q0) * DD;
        for (int i = tid; i < 2048; i += 256) {
            int r = i >> 4, c = (i & 15) << 3;
            *(uint4*)&Qh[r*KSTR + c]              = *(const uint4*)&qhg[r*DD + c];
            *(uint4*)&Qh[(128 + r)*KSTR + c]      = *(const uint4*)&qlg[r*DD + c];
        }
    }
    float hs  = hsc[h];
    float qp0 = qp[tb + q0 + r0loc];
    float qp1 = qp[tb + q0 + r1loc];
    int ntiles = (q0 >> 6) + 2;

    auto prefetchK = [&](int st, int n0) {
        const __nv_bfloat16* khg = kh + (tb + n0) * DD;
        const __nv_bfloat16* klg = kl + (tb + n0) * DD;
        for (int i = tid; i < 1024; i += 256) {
            int r = i >> 4, c = (i & 15) << 3;
            CP16(uK + (unsigned)(((st*128 + r)*KSTR + c) * 2),      khg + r*DD + c);
            CP16(uK + (unsigned)(((st*128 + 64 + r)*KSTR + c) * 2), klg + r*DD + c);
        }
        if (tid < 64) CP4(uKps + (unsigned)((st*64 + tid) * 4), kp + tb + n0 + tid);
    };
    auto prefetchV = [&](int st, int n0) {
        const __nv_bfloat16* vhg = vth + (size_t)bh*DD*TT + n0;
        const __nv_bfloat16* vlg = vtl + (size_t)bh*DD*TT + n0;
        for (int i = tid; i < 1024; i += 256) {
            int d = i >> 3, c = (i & 7) << 3;
            CP16(uV + (unsigned)(((st*256 + d)*VSTR + c) * 2),       vhg + (size_t)d*TT + c);
            CP16(uV + (unsigned)(((st*256 + 128 + d)*VSTR + c) * 2), vlg + (size_t)d*TT + c);
        }
    };

    auto computeS = [&](int st, float s[8][4]) {
        #pragma unroll
        for (int i = 0; i < 8; i++)
            #pragma unroll
            for (int j = 0; j < 4; j++) s[i][j] = 0.f;
        #pragma unroll
        for (int kk = 0; kk < 8; kk++) {
            int col = kk*16 + lca;
            unsigned qoff = (unsigned)(((warp*16 + lra)*KSTR + col) * 2);
            unsigned qa[4], qb[4];
            ldsm_x4(qa, uQ + qoff);
            ldsm_x4(qb, uQ + qoff + (unsigned)(128*KSTR*2));
            #pragma unroll
            for (int ng = 0; ng < 4; ng++) {
                unsigned koff = (unsigned)(((st*128 + ng*16 + lra)*KSTR + col) * 2);
                unsigned kh4[4], kl4[4];
                ldsm_x4(kh4, uK + koff);
                ldsm_x4(kl4, uK + koff + (unsigned)(64*KSTR*2));
                #pragma unroll
                for (int hf = 0; hf < 2; hf++) {
                    int ni = ng*2 + hf;
                    mma_bf16(s[ni], qa, kh4[hf], kh4[2 + hf]);
                    mma_bf16(s[ni], qa, kl4[hf], kl4[2 + hf]);
                    mma_bf16(s[ni], qb, kh4[hf], kh4[2 + hf]);
                }
            }
        }
    };

    // ---------------- PASS 1: row sums ----------------
    float l0 = 0.f, l1 = 0.f, lg0 = 0.f, lg1 = 0.f;
    prefetchK(0, 0);
    CP_COMMIT();
    for (int it = 0; it < ntiles; it++) {
        int st = it & 1;
        int n0 = it << 6;
        if (it + 1 < ntiles) { prefetchK(st ^ 1, (it + 1) << 6); CP_COMMIT(); CP_WAIT1(); }
        else                 { CP_WAIT0(); }
        __syncthreads();

        float s[8][4];
        computeS(st, s);
        int relq = q0 - n0;
        const float* kpst = kps + st*64;
        #pragma unroll
        for (int ni = 0; ni < 8; ni++) {
            #pragma unroll
            for (int j = 0; j < 4; j++) {
                int cl = ni*8 + 2*tig + (j & 1);
                int rl = (j < 2) ? r0loc : r1loc;
                bool ok = (cl - rl <= relq);
                float e  = ok ? __expf(s[ni][j] * SCALE) : 0.f;
                float ge = ok ? __expf(((j < 2) ? qp0 : qp1) * kpst[cl]) : 0.f;
                if (j < 2) { l0 += e; lg0 += ge; }
                else       { l1 += e; lg1 += ge; }
            }
        }
        __syncthreads();
    }
    #pragma unroll
    for (int o = 1; o <= 2; o <<= 1) {
        l0  += __shfl_xor_sync(0xffffffffu, l0,  o);
        l1  += __shfl_xor_sync(0xffffffffu, l1,  o);
        lg0 += __shfl_xor_sync(0xffffffffu, lg0, o);
        lg1 += __shfl_xor_sync(0xffffffffu, lg1, o);
    }
    if (tig == 0) {
        ls[r0loc] = l0;  lgs[r0loc] = lg0;
        ls[r1loc] = l1;  lgs[r1loc] = lg1;
    }
    __syncthreads();
    float c1a = (1.f - hs) / ls[r0loc], c2a = hs / lgs[r0loc];
    float c1b = (1.f - hs) / ls[r1loc], c2b = hs / lgs[r1loc];

    // ---------------- PASS 2: weighted PV ----------------
    float O[16][4];
    #pragma unroll
    for (int i = 0; i < 16; i++)
        #pragma unroll
        for (int j = 0; j < 4; j++) O[i][j] = 0.f;

    prefetchK(0, 0);
    prefetchV(0, 0);
    CP_COMMIT();
    for (int it = 0; it < ntiles; it++) {
        int st = it & 1;
        int n0 = it << 6;
        if (it + 1 < ntiles) {
            prefetchK(st ^ 1, (it + 1) << 6);
            prefetchV(st ^ 1, (it + 1) << 6);
            CP_COMMIT(); CP_WAIT1();
        } else { CP_WAIT0(); }
        __syncthreads();

        float s[8][4];
        computeS(st, s);
        int relq = q0 - n0;
        const float* kpst = kps + st*64;
        #pragma unroll
        for (int ni = 0; ni < 8; ni++) {
            #pragma unroll
            for (int j = 0; j < 4; j++) {
                int cl = ni*8 + 2*tig + (j & 1);
                int rl = (j < 2) ? r0loc : r1loc;
                bool ok = (cl - rl <= relq);
                float e  = __expf(s[ni][j] * SCALE);
                float ge = __expf(((j < 2) ? qp0 : qp1) * kpst[cl]);
                float wv = ((j < 2) ? c1a : c1b) * e + ((j < 2) ? c2a : c2b) * ge;
                s[ni][j] = ok ? wv : 0.f;
            }
        }
        unsigned ph[4][4], pl[4][4];
        #pragma unroll
        for (int kc = 0; kc < 4; kc++) {
            split2(s[2*kc][0],   s[2*kc][1],   ph[kc][0], pl[kc][0]);
            split2(s[2*kc][2],   s[2*kc][3],   ph[kc][1], pl[kc][1]);
            split2(s[2*kc+1][0], s[2*kc+1][1], ph[kc][2], pl[kc][2]);
            split2(s[2*kc+1][2], s[2*kc+1][3], ph[kc][3], pl[kc][3]);
        }
        #pragma unroll
        for (int ndg = 0; ndg < 8; ndg++) {
            #pragma unroll
            for (int kc = 0; kc < 4; kc++) {
                unsigned voff = (unsigned)(((st*256 + ndg*16 + lra)*VSTR + kc*16 + lca) * 2);
                unsigned vh4[4], vl4[4];
                ldsm_x4(vh4, uV + voff);
                ldsm_x4(vl4, uV + voff + (unsigned)(128*VSTR*2));
                #pragma unroll
                for (int hf = 0; hf < 2; hf++) {
                    int nd = ndg*2 + hf;
                    mma_bf16(O[nd], ph[kc], vh4[hf], vh4[2 + hf]);
                    mma_bf16(O[nd], ph[kc], vl4[hf], vl4[2 + hf]);
                    mma_bf16(O[nd], pl[kc], vh4[hf], vh4[2 + hf]);
                }
            }
        }
        __syncthreads();
    }

    // epilogue: write bf16 hi/lo planes for the Wo GEMM
    size_t orow0 = (size_t)(b*TT + q0 + r0loc) * CC + h*DD;
    size_t orow1 = (size_t)(b*TT + q0 + r1loc) * CC + h*DD;
    #pragma unroll
    for (int nd = 0; nd < 16; nd++) {
        int d0 = nd*8 + 2*tig;
        unsigned hh, ll;
        split2(O[nd][0], O[nd][1], hh, ll);
        *(unsigned*)&aoh[orow0 + d0] = hh;
        *(unsigned*)&aol[orow0 + d0] = ll;
        split2(O[nd][2], O[nd][3], hh, ll);
        *(unsigned*)&aoh[orow1 + d0] = hh;
        *(unsigned*)&aol[orow1 + d0] = ll;
    }
}

// ---------------------------------------------------------------------------
// Launcher
// ---------------------------------------------------------------------------
extern "C" void kernel_launch(void* const* d_in, const int* in_sizes, int n_in,
                              void* d_out, int out_size)
{
    const float* x   = (const float*)d_in[0];
    const float* Wq  = (const float*)d_in[1];
    const float* Wk  = (const float*)d_in[2];
    const float* Wv  = (const float*)d_in[3];
    const float* Wo  = (const float*)d_in[4];
    const float* lng = (const float*)d_in[5];
    const float* lnb = (const float*)d_in[6];
    const float* hsc = (const float*)d_in[7];
    const float* hdr = (const float*)d_in[8];
    float* out = (float*)d_out;

    unsigned char* base = nullptr;
    cudaGetSymbolAddress((void**)&base, g_scratch);
    __nv_bfloat16* xnh = (__nv_bfloat16*)(base + OFF_XNH);
    __nv_bfloat16* xnl = (__nv_bfloat16*)(base + OFF_XNL);
    __nv_bfloat16* wh  = (__nv_bfloat16*)(base + OFF_WH);
    __nv_bfloat16* wl  = (__nv_bfloat16*)(base + OFF_WL);
    float* qf = (float*)(base + OFF_QF);
    float* kf = (float*)(base + OFF_KF);
    __nv_bfloat16* qhp = (__nv_bfloat16*)(base + OFF_QH);
    __nv_bfloat16* qlp = (__nv_bfloat16*)(base + OFF_QL);
    __nv_bfloat16* khp = (__nv_bfloat16*)(base + OFF_KH);
    __nv_bfloat16* klp = (__nv_bfloat16*)(base + OFF_KL);
    __nv_bfloat16* vth = (__nv_bfloat16*)(base + OFF_VTH);
    __nv_bfloat16* vtl = (__nv_bfloat16*)(base + OFF_VTL);
    __nv_bfloat16* aoh = (__nv_bfloat16*)(base + OFF_AOH);
    __nv_bfloat16* aol = (__nv_bfloat16*)(base + OFF_AOL);
    float* gqp = (float*)(base + OFF_QP);
    float* gkp = (float*)(base + OFF_KP);

    cudaFuncSetAttribute(gemm2<0>,
                         cudaFuncAttributeMaxDynamicSharedMemorySize, GEMM_SMEM);
    cudaFuncSetAttribute(gemm2<1>,
                         cudaFuncAttributeMaxDynamicSharedMemorySize, GEMM_SMEM);
    cudaFuncSetAttribute(attn_mma,
                         cudaFuncAttributeMaxDynamicSharedMemorySize, ATTN_SMEM);

    ln_split<<<NTOK, 256>>>(x, lng, lnb, xnh, xnl);
    wsplit<<<4096, 256>>>(Wq, Wk, Wv, Wo, wh, wl);

    gemm2<0><<<dim3(24, NTOK/128), 256, GEMM_SMEM>>>(
        xnh, xnl, wh, wl, nullptr, qf, kf, vth, vtl);

    rope_kernel<<<BH*TT, 128>>>(qf, kf, hdr, qhp, qlp, khp, klp, gqp, gkp);

    attn_mma<<<dim3(TT/128, BH), 256, ATTN_SMEM>>>(qhp, qlp, khp, klp, vth, vtl,
                                                   gqp, gkp, hsc, aoh, aol);

    gemm2<1><<<dim3(8, NTOK/128), 256, GEMM_SMEM>>>(
        aoh, aol, wh + 3*WPL, wl + 3*WPL, x, out, nullptr, nullptr, nullptr);
}

// round 9
// speedup vs baseline: 2.8183x; 1.0745x over previous
#include <cuda_runtime.h>
#include <cuda_bf16.h>
#include <math.h>

// Problem constants
#define BB 4
#define TT 2048
#define CC 1024
#define HH 8
#define DD 128
#define NTOK (BB*TT)          // 8192
#define BH   (BB*HH)          // 32
#define WPL  ((size_t)CC*CC)  // weight plane elems

// ---------------------------------------------------------------------------
// Scratch
// ---------------------------------------------------------------------------
#define SZ_F32 ((size_t)NTOK*CC*4)
#define SZ_BF  ((size_t)NTOK*CC*2)
#define SZ_WPL ((size_t)4*CC*CC*2)
#define SZ_P   ((size_t)BH*TT*4)

#define OFF_XNH ((size_t)0)
#define OFF_XNL (OFF_XNH + SZ_BF)
#define OFF_WH  (OFF_XNL + SZ_BF)
#define OFF_WL  (OFF_WH + SZ_WPL)
#define OFF_QF  (OFF_WL + SZ_WPL)
#define OFF_KF  (OFF_QF + SZ_F32)
#define OFF_QH  (OFF_KF + SZ_F32)
#define OFF_QL  (OFF_QH + SZ_BF)
#define OFF_KH  (OFF_QL + SZ_BF)
#define OFF_KL  (OFF_KH + SZ_BF)
#define OFF_VTH (OFF_KL + SZ_BF)
#define OFF_VTL (OFF_VTH + SZ_BF)
#define OFF_AOH (OFF_VTL + SZ_BF)
#define OFF_AOL (OFF_AOH + SZ_BF)
#define OFF_QP  (OFF_AOL + SZ_BF)
#define OFF_KP  (OFF_QP + SZ_P)
#define SCRATCH_BYTES (OFF_KP + SZ_P)

__device__ __align__(256) unsigned char g_scratch[SCRATCH_BYTES];

// ---------------------------------------------------------------------------
// helpers
// ---------------------------------------------------------------------------
__device__ __forceinline__ void mma_bf16(float* c, const unsigned* a,
                                         unsigned b0, unsigned b1) {
    asm volatile(
        "mma.sync.aligned.m16n8k16.row.col.f32.bf16.bf16.f32 "
        "{%0,%1,%2,%3},{%4,%5,%6,%7},{%8,%9},{%0,%1,%2,%3};"
        : "+f"(c[0]), "+f"(c[1]), "+f"(c[2]), "+f"(c[3])
        : "r"(a[0]), "r"(a[1]), "r"(a[2]), "r"(a[3]), "r"(b0), "r"(b1));
}

__device__ __forceinline__ void ldsm_x4(unsigned r[4], unsigned addr) {
    asm volatile("ldmatrix.sync.aligned.m8n8.x4.shared.b16 {%0,%1,%2,%3}, [%4];"
        : "=r"(r[0]), "=r"(r[1]), "=r"(r[2]), "=r"(r[3]) : "r"(addr));
}

#define CP16(dst, src) \
    asm volatile("cp.async.cg.shared.global [%0], [%1], 16;" :: "r"(dst), "l"(src))
#define CP4(dst, src) \
    asm volatile("cp.async.ca.shared.global [%0], [%1], 4;" :: "r"(dst), "l"(src))
#define CP_COMMIT() asm volatile("cp.async.commit_group;")
#define CP_WAIT0()  asm volatile("cp.async.wait_group 0;")
#define CP_WAIT1()  asm volatile("cp.async.wait_group 1;")

__device__ __forceinline__ void split2(float a, float b, unsigned& hi, unsigned& lo) {
    __nv_bfloat162 h = __floats2bfloat162_rn(a, b);
    float la = a - __bfloat162float(h.x);
    float lb = b - __bfloat162float(h.y);
    __nv_bfloat162 l = __floats2bfloat162_rn(la, lb);
    hi = *(unsigned*)&h;
    lo = *(unsigned*)&l;
}

// ---------------------------------------------------------------------------
// LayerNorm -> bf16 hi/lo planes
// ---------------------------------------------------------------------------
__global__ __launch_bounds__(256) void ln_split(
    const float* __restrict__ x, const float* __restrict__ gam,
    const float* __restrict__ bet,
    __nv_bfloat16* __restrict__ xnh, __nv_bfloat16* __restrict__ xnl)
{
    int row = blockIdx.x;
    int t   = threadIdx.x;
    const float4* xr = (const float4*)(x + (size_t)row * CC);
    float4 v = xr[t];
    float s  = v.x + v.y + v.z + v.w;
    float ss = v.x*v.x + v.y*v.y + v.z*v.z + v.w*v.w;
    #pragma unroll
    for (int o = 16; o; o >>= 1) {
        s  += __shfl_xor_sync(0xffffffffu, s,  o);
        ss += __shfl_xor_sync(0xffffffffu, ss, o);
    }
    __shared__ float ws[8], wss[8];
    int wid = t >> 5;
    if ((t & 31) == 0) { ws[wid] = s; wss[wid] = ss; }
    __syncthreads();
    s = 0.f; ss = 0.f;
    #pragma unroll
    for (int i = 0; i < 8; i++) { s += ws[i]; ss += wss[i]; }
    float mu  = s * (1.f / CC);
    float var = ss * (1.f / CC) - mu * mu;
    float inv = rsqrtf(var + 1e-5f);
    float4 g4 = ((const float4*)gam)[t];
    float4 b4 = ((const float4*)bet)[t];
    float4 o;
    o.x = (v.x - mu) * inv * g4.x + b4.x;
    o.y = (v.y - mu) * inv * g4.y + b4.y;
    o.z = (v.z - mu) * inv * g4.z + b4.z;
    o.w = (v.w - mu) * inv * g4.w + b4.w;
    unsigned h0, l0, h1, l1;
    split2(o.x, o.y, h0, l0);
    split2(o.z, o.w, h1, l1);
    size_t off = (size_t)row * CC + t*4;
    *(uint2*)&xnh[off] = make_uint2(h0, h1);
    *(uint2*)&xnl[off] = make_uint2(l0, l1);
}

// ---------------------------------------------------------------------------
// Split 4 weight matrices into bf16 hi/lo planes: plane order Wq,Wk,Wv,Wo
// ---------------------------------------------------------------------------
__global__ __launch_bounds__(256) void wsplit(
    const float* __restrict__ w0, const float* __restrict__ w1,
    const float* __restrict__ w2, const float* __restrict__ w3,
    __nv_bfloat16* __restrict__ wh, __nv_bfloat16* __restrict__ wl)
{
    int mid = blockIdx.x >> 10;
    const float* src = (mid == 0) ? w0 : (mid == 1) ? w1 : (mid == 2) ? w2 : w3;
    size_t idx = ((size_t)(blockIdx.x & 1023))*1024 + threadIdx.x*4;
    float4 v = *(const float4*)(src + idx);
    unsigned h0, l0, h1, l1;
    split2(v.x, v.y, h0, l0);
    split2(v.z, v.w, h1, l1);
    size_t off = (size_t)mid*WPL + idx;
    *(uint2*)&wh[off] = make_uint2(h0, h1);
    *(uint2*)&wl[off] = make_uint2(l0, l1);
}

// ---------------------------------------------------------------------------
// 3xBF16 GEMM: cp.async double buffer + ldmatrix, 128x128x32, 2 CTA/SM.
// MODE 0: QKV fused (grid.x=24; sel = x>>3): sel 0/1 -> fp32 head-major
//         q/k buffers; sel 2 -> transposed bf16 hi/lo planes [B,H,D,T]
// MODE 1: out0 = X + acc (fp32 row-major)
// ---------------------------------------------------------------------------
#define GSTR 40
#define GEMM_SMEM (4*2*128*GSTR*2)   // 81920 B

template<int MODE>
__global__ __launch_bounds__(256, 2) void gemm2(
    const __nv_bfloat16* __restrict__ Ah, const __nv_bfloat16* __restrict__ Al,
    const __nv_bfloat16* __restrict__ Wh, const __nv_bfloat16* __restrict__ Wl,
    const float* __restrict__ X,
    float* __restrict__ out0, float* __restrict__ out1,
    __nv_bfloat16* __restrict__ oh, __nv_bfloat16* __restrict__ ol)
{
    extern __shared__ __nv_bfloat16 smb[];
    __nv_bfloat16* sAh = smb;
    __nv_bfloat16* sAl = sAh + 2*128*GSTR;
    __nv_bfloat16* sBh = sAl + 2*128*GSTR;
    __nv_bfloat16* sBl = sBh + 2*128*GSTR;
    unsigned uAh = (unsigned)__cvta_generic_to_shared(sAh);
    unsigned uAl = (unsigned)__cvta_generic_to_shared(sAl);
    unsigned uBh = (unsigned)__cvta_generic_to_shared(sBh);
    unsigned uBl = (unsigned)__cvta_generic_to_shared(sBl);

    int tid = threadIdx.x, lane = tid & 31, warp = tid >> 5;
    int g = lane >> 2, tig = lane & 3;
    int wm = warp >> 1, wn = warp & 1;
    int sel = (MODE == 0) ? (blockIdx.x >> 3) : 0;
    int n0 = (MODE == 0) ? ((blockIdx.x & 7) << 7) : (blockIdx.x << 7);
    int m0 = blockIdx.y << 7;
    const __nv_bfloat16* Wph = Wh + (size_t)sel*WPL;
    const __nv_bfloat16* Wpl = Wl + (size_t)sel*WPL;

    int lr = tid >> 2;
    int lc8 = (tid & 3) * 8;

    float acc[16][4];
    #pragma unroll
    for (int i = 0; i < 16; i++)
        #pragma unroll
        for (int j = 0; j < 4; j++) acc[i][j] = 0.f;

    auto load_stage = [&](int buf, int k0) {
        size_t a0 = (size_t)(m0 + lr) * CC + k0 + lc8;
        size_t b0 = (size_t)(n0 + lr) * CC + k0 + lc8;
        unsigned d0 = (unsigned)(((buf*128 + lr)*GSTR + lc8) * 2);
        unsigned d1 = (unsigned)(((buf*128 + lr + 64)*GSTR + lc8) * 2);
        CP16(uAh + d0, Ah + a0);  CP16(uAh + d1, Ah + a0 + (size_t)64*CC);
        CP16(uAl + d0, Al + a0);  CP16(uAl + d1, Al + a0 + (size_t)64*CC);
        CP16(uBh + d0, Wph + b0); CP16(uBh + d1, Wph + b0 + (size_t)64*CC);
        CP16(uBl + d0, Wpl + b0); CP16(uBl + d1, Wpl + b0 + (size_t)64*CC);
    };

    load_stage(0, 0);
    CP_COMMIT();
    CP_WAIT0();
    __syncthreads();

    int lra = ((lane >> 3) & 1) * 8 + (lane & 7);
    int lca = (lane >> 4) * 8;
    const int NIT = CC / 32;

    for (int it = 0; it < NIT; it++) {
        int buf = it & 1;
        if (it + 1 < NIT) { load_stage(buf ^ 1, (it + 1) * 32); CP_COMMIT(); }

        int sb = buf * 128;
        #pragma unroll
        for (int kk = 0; kk < 2; kk++) {
            int col = kk*16 + lca;
            unsigned ah[2][4], al2[2][4];
            #pragma unroll
            for (int mi = 0; mi < 2; mi++) {
                unsigned offA = (unsigned)(((sb + wm*32 + mi*16 + lra)*GSTR + col) * 2);
                ldsm_x4(ah[mi],  uAh + offA);
                ldsm_x4(al2[mi], uAl + offA);
            }
            #pragma unroll
            for (int ng = 0; ng < 4; ng++) {
                unsigned offB = (unsigned)(((sb + wn*64 + ng*16 + lra)*GSTR + col) * 2);
                unsigned b4h[4], b4l[4];
                ldsm_x4(b4h, uBh + offB);
                ldsm_x4(b4l, uBl + offB);
                #pragma unroll
                for (int hf = 0; hf < 2; hf++) {
                    int ni = ng*2 + hf;
                    unsigned bh0 = b4h[hf], bh1 = b4h[2 + hf];
                    unsigned bl0 = b4l[hf], bl1 = b4l[2 + hf];
                    #pragma unroll
                    for (int mi = 0; mi < 2; mi++) {
                        float* c = acc[mi*8 + ni];
                        mma_bf16(c, ah[mi],  bh0, bh1);
                        mma_bf16(c, ah[mi],  bl0, bl1);
                        mma_bf16(c, al2[mi], bh0, bh1);
                    }
                }
            }
        }
        if (it + 1 < NIT) CP_WAIT0();
        __syncthreads();
    }

    // epilogue
    #pragma unroll
    for (int mi = 0; mi < 2; mi++) {
        #pragma unroll
        for (int ni = 0; ni < 8; ni++) {
            const float* c = acc[mi*8 + ni];
            int r0 = m0 + wm*32 + mi*16 + g;
            int c0 = n0 + wn*64 + ni*8 + 2*tig;
            #pragma unroll
            for (int half = 0; half < 2; half++) {
                int r = r0 + half*8;
                float v0 = c[half*2], v1 = c[half*2 + 1];
                if (MODE == 1) {
                    size_t o = (size_t)r * CC + c0;
                    float2 xv = *(const float2*)&X[o];
                    *(float2*)&out0[o] = make_float2(xv.x + v0, xv.y + v1);
                } else if (sel < 2) {
                    int b = r >> 11, t = r & 2047, h = c0 >> 7, d = c0 & 127;
                    float* outp = sel ? out1 : out0;
                    *(float2*)&outp[(((size_t)(b*HH + h) * TT) + t) * DD + d] =
                        make_float2(v0, v1);
                } else {
                    int b = r >> 11, t = r & 2047, h = c0 >> 7, d = c0 & 127;
                    size_t rb = ((size_t)((b*HH + h)*DD + d)) * TT + t;
                    __nv_bfloat16 h0 = __float2bfloat16(v0);
                    __nv_bfloat16 h1 = __float2bfloat16(v1);
                    oh[rb]      = h0;
                    ol[rb]      = __float2bfloat16(v0 - __bfloat162float(h0));
                    oh[rb + TT] = h1;
                    ol[rb + TT] = __float2bfloat16(v1 - __bfloat162float(h1));
                }
            }
        }
    }
}

// ---------------------------------------------------------------------------
// RoPE on q,k: read fp32 head-major, write bf16 hi/lo planes + qp/kp
// ---------------------------------------------------------------------------
__global__ __launch_bounds__(128) void rope_kernel(
    const float* __restrict__ qf, const float* __restrict__ kf,
    const float* __restrict__ dirs,
    __nv_bfloat16* __restrict__ qh, __nv_bfloat16* __restrict__ ql,
    __nv_bfloat16* __restrict__ kh, __nv_bfloat16* __restrict__ kl,
    float* __restrict__ qp, float* __restrict__ kp)
{
    int idx = blockIdx.x;
    int t = idx & (TT - 1);
    int h = (idx >> 11) & (HH - 1);
    int tid = threadIdx.x;
    int i = tid & 63;
    bool isq = tid < 64;
    const float* src = (isq ? qf : kf) + (size_t)idx * DD;
    __nv_bfloat16* dh = isq ? qh : kh;
    __nv_bfloat16* dl = isq ? ql : kl;
    float x1 = src[i], x2 = src[i + 64];
    float inv = expf(-9.210340371976184f * (float)i * (1.f / 64.f));
    float ang = (float)t * inv;
    float sn, cs;
    sincosf(ang, &sn, &cs);
    float y1 = x1 * cs - x2 * sn;
    float y2 = x2 * cs + x1 * sn;
    size_t o = (size_t)idx * DD;
    __nv_bfloat16 h1 = __float2bfloat16(y1);
    __nv_bfloat16 h2 = __float2bfloat16(y2);
    dh[o + i]      = h1;
    dl[o + i]      = __float2bfloat16(y1 - __bfloat162float(h1));
    dh[o + i + 64] = h2;
    dl[o + i + 64] = __float2bfloat16(y2 - __bfloat162float(h2));
    __shared__ float red[6];
    if (i < 3) red[(tid >> 6) * 3 + i] = y1 * dirs[h * 3 + i];
    __syncthreads();
    if (tid == 0)  qp[idx] = red[0] + red[1] + red[2];
    if (tid == 64) kp[idx] = red[3] + red[4] + red[5];
}

// ---------------------------------------------------------------------------
// ONE-PASS dual-softmax flash attention.
// Br=128 (256 thr, 8 warps, warp owns 16 rows), Bc=64.
// Accumulates unnormalized O = sum e*V, Og = sum ge*V plus row sums l, lg;
// epilogue applies (1-hs)*O/l + hs*Og/lg. Geo fragments generated inline
// from qp/kp (no S dependence). cp.async double-buffered K/V/kp tiles.
// ---------------------------------------------------------------------------
#define KSTR 136
#define VSTR 72
#define Q_ELE (2*128*KSTR)
#define K_ELE (2*2*64*KSTR)          // 2 stages x (hi/lo) x 64 rows
#define V_ELE (2*2*128*VSTR)         // 2 stages x (hi/lo) x 128 rows
#define ATTN_SMEM ((Q_ELE + K_ELE + V_ELE)*2 + 2*64*4)  // ~214 KB
#define SCALE 0.08838834764831845f

__global__ __launch_bounds__(256, 1) void attn_mma(
    const __nv_bfloat16* __restrict__ qh, const __nv_bfloat16* __restrict__ ql,
    const __nv_bfloat16* __restrict__ kh, const __nv_bfloat16* __restrict__ kl,
    const __nv_bfloat16* __restrict__ vth, const __nv_bfloat16* __restrict__ vtl,
    const float* __restrict__ qp, const float* __restrict__ kp,
    const float* __restrict__ hsc,
    __nv_bfloat16* __restrict__ aoh, __nv_bfloat16* __restrict__ aol)
{
    extern __shared__ unsigned char sma[];
    __nv_bfloat16* Qh = (__nv_bfloat16*)sma;            // [2][128][KSTR] hi/lo
    __nv_bfloat16* Kb = Qh + Q_ELE;                     // stages
    __nv_bfloat16* Vb = Kb + K_ELE;
    float* kps = (float*)(Vb + V_ELE);                  // [2][64]

    unsigned uQ = (unsigned)__cvta_generic_to_shared(Qh);
    unsigned uK = (unsigned)__cvta_generic_to_shared(Kb);
    unsigned uV = (unsigned)__cvta_generic_to_shared(Vb);
    unsigned uKps = (unsigned)__cvta_generic_to_shared(kps);

    int bh = blockIdx.y;
    int b = bh >> 3, h = bh & 7;
    int q0 = (gridDim.x - 1 - blockIdx.x) << 7;   // big tiles first
    size_t tb = (size_t)bh * TT;
    int tid = threadIdx.x;
    int lane = tid & 31, warp = tid >> 5;
    int g = lane >> 2, tig = lane & 3;
    int r0loc = warp*16 + g, r1loc = r0loc + 8;
    int lra = ((lane >> 3) & 1) * 8 + (lane & 7);
    int lca = (lane >> 4) * 8;

    // load Q tiles (hi/lo), 128 rows
    {
        const __nv_bfloat16* qhg = qh + (tb + q0) * DD;
        const __nv_bfloat16* qlg = ql + (tb + q0) * DD;
        for (int i = tid; i < 2048; i += 256) {
            int r = i >> 4, c = (i & 15) << 3;
            *(uint4*)&Qh[r*KSTR + c]         = *(const uint4*)&qhg[r*DD + c];
            *(uint4*)&Qh[(128 + r)*KSTR + c] = *(const uint4*)&qlg[r*DD + c];
        }
    }
    float hs  = hsc[h];
    float qp0 = qp[tb + q0 + r0loc];
    float qp1 = qp[tb + q0 + r1loc];
    int ntiles = (q0 >> 6) + 2;

    auto prefetch = [&](int st, int n0) {
        const __nv_bfloat16* khg = kh + (tb + n0) * DD;
        const __nv_bfloat16* klg = kl + (tb + n0) * DD;
        for (int i = tid; i < 1024; i += 256) {
            int r = i >> 4, c = (i & 15) << 3;
            CP16(uK + (unsigned)(((st*128 + r)*KSTR + c) * 2),      khg + r*DD + c);
            CP16(uK + (unsigned)(((st*128 + 64 + r)*KSTR + c) * 2), klg + r*DD + c);
        }
        const __nv_bfloat16* vhg = vth + (size_t)bh*DD*TT + n0;
        const __nv_bfloat16* vlg = vtl + (size_t)bh*DD*TT + n0;
        for (int i = tid; i < 1024; i += 256) {
            int d = i >> 3, c = (i & 7) << 3;
            CP16(uV + (unsigned)(((st*256 + d)*VSTR + c) * 2),       vhg + (size_t)d*TT + c);
            CP16(uV + (unsigned)(((st*256 + 128 + d)*VSTR + c) * 2), vlg + (size_t)d*TT + c);
        }
        if (tid < 64) CP4(uKps + (unsigned)((st*64 + tid) * 4), kp + tb + n0 + tid);
    };

    float O[16][4], Og[16][4];
    #pragma unroll
    for (int i = 0; i < 16; i++)
        #pragma unroll
        for (int j = 0; j < 4; j++) { O[i][j] = 0.f; Og[i][j] = 0.f; }
    float l0 = 0.f, l1 = 0.f, lg0 = 0.f, lg1 = 0.f;

    prefetch(0, 0);
    CP_COMMIT();
    for (int it = 0; it < ntiles; it++) {
        int st = it & 1;
        int n0 = it << 6;
        if (it + 1 < ntiles) { prefetch(st ^ 1, (it + 1) << 6); CP_COMMIT(); CP_WAIT1(); }
        else                 { CP_WAIT0(); }
        __syncthreads();

        // ---- S = Q K^T (3xBF16)
        float s[8][4];
        #pragma unroll
        for (int i = 0; i < 8; i++)
            #pragma unroll
            for (int j = 0; j < 4; j++) s[i][j] = 0.f;
        #pragma unroll
        for (int kk = 0; kk < 8; kk++) {
            int col = kk*16 + lca;
            unsigned qoff = (unsigned)(((warp*16 + lra)*KSTR + col) * 2);
            unsigned qa[4], qb[4];
            ldsm_x4(qa, uQ + qoff);
            ldsm_x4(qb, uQ + qoff + (unsigned)(128*KSTR*2));
            #pragma unroll
            for (int ng = 0; ng < 4; ng++) {
                unsigned koff = (unsigned)(((st*128 + ng*16 + lra)*KSTR + col) * 2);
                unsigned kh4[4], kl4[4];
                ldsm_x4(kh4, uK + koff);
                ldsm_x4(kl4, uK + koff + (unsigned)(64*KSTR*2));
                #pragma unroll
                for (int hf = 0; hf < 2; hf++) {
                    int ni = ng*2 + hf;
                    mma_bf16(s[ni], qa, kh4[hf], kh4[2 + hf]);
                    mma_bf16(s[ni], qa, kl4[hf], kl4[2 + hf]);
                    mma_bf16(s[ni], qb, kh4[hf], kh4[2 + hf]);
                }
            }
        }

        // ---- attn weights e = exp(s*scale), masked; accumulate l
        int relq = q0 - n0;
        #pragma unroll
        for (int ni = 0; ni < 8; ni++) {
            #pragma unroll
            for (int j = 0; j < 4; j++) {
                int cl = ni*8 + 2*tig + (j & 1);
                int rl = (j < 2) ? r0loc : r1loc;
                bool ok = (cl - rl <= relq);
                float e = ok ? __expf(s[ni][j] * SCALE) : 0.f;
                s[ni][j] = e;
                if (j < 2) l0 += e; else l1 += e;
            }
        }

        const float* kpst = kps + st*64;
        // ---- dual PV: per kc chunk pack P (attn) and Pg (geo) and MMA both
        #pragma unroll
        for (int kc = 0; kc < 4; kc++) {
            unsigned ph[4], pl[4], gh[4], gl[4];
            // attn fragments
            split2(s[2*kc][0],   s[2*kc][1],   ph[0], pl[0]);
            split2(s[2*kc][2],   s[2*kc][3],   ph[1], pl[1]);
            split2(s[2*kc+1][0], s[2*kc+1][1], ph[2], pl[2]);
            split2(s[2*kc+1][2], s[2*kc+1][3], ph[3], pl[3]);
            // geo fragments: ge(row, col) = exp(qp_row * kp_col), masked
            {
                int c0 = kc*16 + 2*tig;
                float k0v = kpst[c0],     k1v = kpst[c0 + 1];
                float k8v = kpst[c0 + 8], k9v = kpst[c0 + 9];
                float ge00 = (c0     - r0loc <= relq) ? __expf(qp0 * k0v) : 0.f;
                float ge01 = (c0 + 1 - r0loc <= relq) ? __expf(qp0 * k1v) : 0.f;
                float ge10 = (c0     - r1loc <= relq) ? __expf(qp1 * k0v) : 0.f;
                float ge11 = (c0 + 1 - r1loc <= relq) ? __expf(qp1 * k1v) : 0.f;
                float ge08 = (c0 + 8 - r0loc <= relq) ? __expf(qp0 * k8v) : 0.f;
                float ge09 = (c0 + 9 - r0loc <= relq) ? __expf(qp0 * k9v) : 0.f;
                float ge18 = (c0 + 8 - r1loc <= relq) ? __expf(qp1 * k8v) : 0.f;
                float ge19 = (c0 + 9 - r1loc <= relq) ? __expf(qp1 * k9v) : 0.f;
                lg0 += ge00 + ge01 + ge08 + ge09;
                lg1 += ge10 + ge11 + ge18 + ge19;
                split2(ge00, ge01, gh[0], gl[0]);
                split2(ge10, ge11, gh[1], gl[1]);
                split2(ge08, ge09, gh[2], gl[2]);
                split2(ge18, ge19, gh[3], gl[3]);
            }
            #pragma unroll
            for (int ndg = 0; ndg < 8; ndg++) {
                unsigned voff = (unsigned)(((st*256 + ndg*16 + lra)*VSTR + kc*16 + lca) * 2);
                unsigned vh4[4], vl4[4];
                ldsm_x4(vh4, uV + voff);
                ldsm_x4(vl4, uV + voff + (unsigned)(128*VSTR*2));
                #pragma unroll
                for (int hf = 0; hf < 2; hf++) {
                    int nd = ndg*2 + hf;
                    mma_bf16(O[nd],  ph, vh4[hf], vh4[2 + hf]);
                    mma_bf16(O[nd],  ph, vl4[hf], vl4[2 + hf]);
                    mma_bf16(O[nd],  pl, vh4[hf], vh4[2 + hf]);
                    mma_bf16(Og[nd], gh, vh4[hf], vh4[2 + hf]);
                    mma_bf16(Og[nd], gh, vl4[hf], vl4[2 + hf]);
                    mma_bf16(Og[nd], gl, vh4[hf], vh4[2 + hf]);
                }
            }
        }
        __syncthreads();
    }

    // reduce row sums across the 4 lanes of each row group
    #pragma unroll
    for (int o = 1; o <= 2; o <<= 1) {
        l0  += __shfl_xor_sync(0xffffffffu, l0,  o);
        l1  += __shfl_xor_sync(0xffffffffu, l1,  o);
        lg0 += __shfl_xor_sync(0xffffffffu, lg0, o);
        lg1 += __shfl_xor_sync(0xffffffffu, lg1, o);
    }
    float c1a = (1.f - hs) / l0, c2a = hs / lg0;
    float c1b = (1.f - hs) / l1, c2b = hs / lg1;

    // epilogue: normalize + blend, write bf16 hi/lo planes for the Wo GEMM
    size_t orow0 = (size_t)(b*TT + q0 + r0loc) * CC + h*DD;
    size_t orow1 = (size_t)(b*TT + q0 + r1loc) * CC + h*DD;
    #pragma unroll
    for (int nd = 0; nd < 16; nd++) {
        int d0 = nd*8 + 2*tig;
        unsigned hh, ll;
        float v0 = c1a*O[nd][0] + c2a*Og[nd][0];
        float v1 = c1a*O[nd][1] + c2a*Og[nd][1];
        split2(v0, v1, hh, ll);
        *(unsigned*)&aoh[orow0 + d0] = hh;
        *(unsigned*)&aol[orow0 + d0] = ll;
        v0 = c1b*O[nd][2] + c2b*Og[nd][2];
        v1 = c1b*O[nd][3] + c2b*Og[nd][3];
        split2(v0, v1, hh, ll);
        *(unsigned*)&aoh[orow1 + d0] = hh;
        *(unsigned*)&aol[orow1 + d0] = ll;
    }
}

// ---------------------------------------------------------------------------
// Launcher
// ---------------------------------------------------------------------------
extern "C" void kernel_launch(void* const* d_in, const int* in_sizes, int n_in,
                              void* d_out, int out_size)
{
    const float* x   = (const float*)d_in[0];
    const float* Wq  = (const float*)d_in[1];
    const float* Wk  = (const float*)d_in[2];
    const float* Wv  = (const float*)d_in[3];
    const float* Wo  = (const float*)d_in[4];
    const float* lng = (const float*)d_in[5];
    const float* lnb = (const float*)d_in[6];
    const float* hsc = (const float*)d_in[7];
    const float* hdr = (const float*)d_in[8];
    float* out = (float*)d_out;

    unsigned char* base = nullptr;
    cudaGetSymbolAddress((void**)&base, g_scratch);
    __nv_bfloat16* xnh = (__nv_bfloat16*)(base + OFF_XNH);
    __nv_bfloat16* xnl = (__nv_bfloat16*)(base + OFF_XNL);
    __nv_bfloat16* wh  = (__nv_bfloat16*)(base + OFF_WH);
    __nv_bfloat16* wl  = (__nv_bfloat16*)(base + OFF_WL);
    float* qf = (float*)(base + OFF_QF);
    float* kf = (float*)(base + OFF_KF);
    __nv_bfloat16* qhp = (__nv_bfloat16*)(base + OFF_QH);
    __nv_bfloat16* qlp = (__nv_bfloat16*)(base + OFF_QL);
    __nv_bfloat16* khp = (__nv_bfloat16*)(base + OFF_KH);
    __nv_bfloat16* klp = (__nv_bfloat16*)(base + OFF_KL);
    __nv_bfloat16* vth = (__nv_bfloat16*)(base + OFF_VTH);
    __nv_bfloat16* vtl = (__nv_bfloat16*)(base + OFF_VTL);
    __nv_bfloat16* aoh = (__nv_bfloat16*)(base + OFF_AOH);
    __nv_bfloat16* aol = (__nv_bfloat16*)(base + OFF_AOL);
    float* gqp = (float*)(base + OFF_QP);
    float* gkp = (float*)(base + OFF_KP);

    cudaFuncSetAttribute(gemm2<0>,
                         cudaFuncAttributeMaxDynamicSharedMemorySize, GEMM_SMEM);
    cudaFuncSetAttribute(gemm2<1>,
                         cudaFuncAttributeMaxDynamicSharedMemorySize, GEMM_SMEM);
    cudaFuncSetAttribute(attn_mma,
                         cudaFuncAttributeMaxDynamicSharedMemorySize, ATTN_SMEM);

    ln_split<<<NTOK, 256>>>(x, lng, lnb, xnh, xnl);
    wsplit<<<4096, 256>>>(Wq, Wk, Wv, Wo, wh, wl);

    gemm2<0><<<dim3(24, NTOK/128), 256, GEMM_SMEM>>>(
        xnh, xnl, wh, wl, nullptr, qf, kf, vth, vtl);

    rope_kernel<<<BH*TT, 128>>>(qf, kf, hdr, qhp, qlp, khp, klp, gqp, gkp);

    attn_mma<<<dim3(TT/128, BH), 256, ATTN_SMEM>>>(qhp, qlp, khp, klp, vth, vtl,
                                                   gqp, gkp, hsc, aoh, aol);

    gemm2<1><<<dim3(8, NTOK/128), 256, GEMM_SMEM>>>(
        aoh, aol, wh + 3*WPL, wl + 3*WPL, x, out, nullptr, nullptr, nullptr);
}